// round 1
// baseline (speedup 1.0000x reference)
#include <cuda_runtime.h>
#include <math.h>

// ---------------- problem constants ----------------
constexpr int BATCH = 4;
constexpr int C = 256;
constexpr int H = 64, W = 64;
constexpr int P = H * W;            // 4096 pixels
constexpr int NH = 8, HD = 32;      // heads
constexpr int P2 = (H / 2) * (W / 2); // 1024 pooled pixels
constexpr float SCALE = 0.1767766952966369f; // 32^-0.5
constexpr float EPS_GN = 1e-6f;
constexpr float EPS_LN = 1e-5f;

// ---------------- scratch (device globals; no allocation allowed) ----------
__device__ float g_stats[2 * BATCH];                 // per-batch sum, sumsq
__device__ float g_xn[BATCH * C * P];                // normalized x; later reused as global_x
__device__ float g_qkv[BATCH * 3 * C * P];           // qkv conv output
__device__ float g_gridx[BATCH * C * P];             // x + window-attn out, then grid_x (normed in place)
__device__ float g_m[BATCH * 4 * C * P2];            // patch-merge LN output, layout [b][k=1024][p2=1024]
__device__ float g_pm[BATCH * C * P2];               // pm reduction output
__device__ float g_ds[BATCH * C * P2];               // ds = GN(pm)
__device__ float g_qg[BATCH * C * P];                // global q
__device__ float g_kv[BATCH * 2 * C * P2];           // global k,v

// ---------------- small utils ----------------
__global__ void zero_stats_kernel() {
    if (threadIdx.x < 2 * BATCH) g_stats[threadIdx.x] = 0.f;
}

// Per-batch sum & sumsq reduction (atomic accumulate into g_stats).
__global__ void gn_stats_kernel(const float* __restrict__ x, int per_batch) {
    int b = blockIdx.y;
    const float* xb = x + (size_t)b * per_batch;
    float s = 0.f, ss = 0.f;
    for (int i = blockIdx.x * blockDim.x + threadIdx.x; i < per_batch;
         i += gridDim.x * blockDim.x) {
        float v = xb[i];
        s += v;
        ss = fmaf(v, v, ss);
    }
#pragma unroll
    for (int o = 16; o > 0; o >>= 1) {
        s += __shfl_xor_sync(~0u, s, o);
        ss += __shfl_xor_sync(~0u, ss, o);
    }
    __shared__ float red[2][8];
    int lane = threadIdx.x & 31, wp = threadIdx.x >> 5;
    if (lane == 0) { red[0][wp] = s; red[1][wp] = ss; }
    __syncthreads();
    if (threadIdx.x < 32) {
        float a = threadIdx.x < 8 ? red[0][threadIdx.x] : 0.f;
        float q = threadIdx.x < 8 ? red[1][threadIdx.x] : 0.f;
#pragma unroll
        for (int o = 4; o > 0; o >>= 1) {
            a += __shfl_xor_sync(~0u, a, o);
            q += __shfl_xor_sync(~0u, q, o);
        }
        if (threadIdx.x == 0) {
            atomicAdd(&g_stats[2 * b], a);
            atomicAdd(&g_stats[2 * b + 1], q);
        }
    }
}

// y = (x - mean) * rsqrt(var+eps) * w[c] + bias[c]   (per-sample stats from g_stats)
__global__ void gn_apply_kernel(const float* __restrict__ x,
                                const float* __restrict__ w,
                                const float* __restrict__ bias,
                                float* __restrict__ out,
                                int hw, int per_batch, float eps) {
    int b = blockIdx.y;
    float cnt = (float)per_batch;
    float mean = g_stats[2 * b] / cnt;
    float var = g_stats[2 * b + 1] / cnt - mean * mean;
    float inv = rsqrtf(var + eps);
    const float* xb = x + (size_t)b * per_batch;
    float* ob = out + (size_t)b * per_batch;
    for (int i = blockIdx.x * blockDim.x + threadIdx.x; i < per_batch;
         i += gridDim.x * blockDim.x) {
        int c = i / hw;
        ob[i] = (xb[i] - mean) * inv * w[c] + bias[c];
    }
}

// ---------------- tiled fp32 GEMM: C[b] = A[M,K] * B[b][K,N] (+bias[M]) ------
// Block tile 64x64, K tile 16, 256 threads, 4x4 per thread.
__global__ void gemm_kernel(const float* __restrict__ A,
                            const float* __restrict__ Bm,
                            const float* __restrict__ bias,
                            float* __restrict__ Cm,
                            int M, int N, int K) {
    const int b = blockIdx.z;
    Bm += (size_t)b * K * N;
    Cm += (size_t)b * M * N;
    __shared__ float As[16][64];
    __shared__ float Bs[16][64];
    const int tid = threadIdx.x;
    const int tx = tid & 15, ty = tid >> 4;
    const int m0 = blockIdx.y * 64, n0 = blockIdx.x * 64;
    float acc[4][4] = {};
    for (int k0 = 0; k0 < K; k0 += 16) {
#pragma unroll
        for (int i = 0; i < 4; ++i) {
            int idx = tid + i * 256;
            int mm = idx >> 4, kk = idx & 15;
            As[kk][mm] = A[(size_t)(m0 + mm) * K + k0 + kk];
        }
#pragma unroll
        for (int i = 0; i < 4; ++i) {
            int idx = tid + i * 256;
            int kk = idx >> 6, nn = idx & 63;
            Bs[kk][nn] = Bm[(size_t)(k0 + kk) * N + n0 + nn];
        }
        __syncthreads();
#pragma unroll
        for (int kk = 0; kk < 16; ++kk) {
            float4 av = *(const float4*)&As[kk][ty * 4];
            float4 bv = *(const float4*)&Bs[kk][tx * 4];
            float ar[4] = {av.x, av.y, av.z, av.w};
            float br[4] = {bv.x, bv.y, bv.z, bv.w};
#pragma unroll
            for (int i = 0; i < 4; ++i)
#pragma unroll
                for (int j = 0; j < 4; ++j)
                    acc[i][j] = fmaf(ar[i], br[j], acc[i][j]);
        }
        __syncthreads();
    }
#pragma unroll
    for (int i = 0; i < 4; ++i) {
        int m = m0 + ty * 4 + i;
        float bv = bias ? bias[m] : 0.f;
        float4 o;
        o.x = acc[i][0] + bv;
        o.y = acc[i][1] + bv;
        o.z = acc[i][2] + bv;
        o.w = acc[i][3] + bv;
        *(float4*)&Cm[(size_t)m * N + n0 + tx * 4] = o;
    }
}

// ---------------- windowed 8x8 attention ----------------
// One block per (b, head, gi, gj) window; 64 threads, one per query token.
// Writes out = x + attn_out  (pre-GN grid_x).
__global__ void win_attn_kernel(const float* __restrict__ qkv,
                                const float* __restrict__ x,
                                float* __restrict__ out) {
    int wid = blockIdx.x;
    int gj = wid & 7, gi = (wid >> 3) & 7, h = (wid >> 6) & 7, b = wid >> 9;
    int tid = threadIdx.x;            // 64 threads
    int si = tid >> 3, sj = tid & 7;
    int sp = (gi * 8 + si) * W + gj * 8 + sj;

    __shared__ float sq[64][33], sk[64][33], sv[64][33];
    __shared__ float sc[64][65];

    size_t baseq = ((size_t)b * 768 + h * 32) * (size_t)P + sp;
#pragma unroll
    for (int d = 0; d < 32; ++d) {
        sq[tid][d] = qkv[baseq + (size_t)d * P];
        sk[tid][d] = qkv[baseq + (size_t)(256 + d) * P];
        sv[tid][d] = qkv[baseq + (size_t)(512 + d) * P];
    }
    __syncthreads();

    float qr[32];
#pragma unroll
    for (int d = 0; d < 32; ++d) qr[d] = sq[tid][d] * SCALE;

    float mx = -1e30f;
    for (int j = 0; j < 64; ++j) {
        float s = 0.f;
#pragma unroll
        for (int d = 0; d < 32; ++d) s = fmaf(qr[d], sk[j][d], s);
        sc[tid][j] = s;
        mx = fmaxf(mx, s);
    }
    float l = 0.f;
    for (int j = 0; j < 64; ++j) {
        float p_ = __expf(sc[tid][j] - mx);
        sc[tid][j] = p_;
        l += p_;
    }
    float rl = 1.f / l;

    size_t baseo = ((size_t)b * 256 + h * 32) * (size_t)P + sp;
#pragma unroll
    for (int d = 0; d < 32; ++d) {
        float acc = 0.f;
        for (int j = 0; j < 64; ++j) acc = fmaf(sc[tid][j], sv[j][d], acc);
        out[baseo + (size_t)d * P] = x[baseo + (size_t)d * P] + acc * rl;
    }
}

// ---------------- patch merge + LayerNorm ----------------
// grid (p2=1024, b); 256 threads, one per channel; each owns 4 of the 1024 LN features.
__global__ void patch_merge_ln_kernel(const float* __restrict__ gx,
                                      const float* __restrict__ lnw,
                                      const float* __restrict__ lnb,
                                      float* __restrict__ m_out) {
    int b = blockIdx.y;
    int p2 = blockIdx.x;
    int i = p2 >> 5, j = p2 & 31;
    int c = threadIdx.x;
    size_t base = ((size_t)b * 256 + c) * (size_t)P;
    int sp00 = (2 * i) * W + 2 * j;
    float v0 = gx[base + sp00];        // (2i,   2j)
    float v1 = gx[base + sp00 + W];    // (2i+1, 2j)
    float v2 = gx[base + sp00 + 1];    // (2i,   2j+1)
    float v3 = gx[base + sp00 + W + 1];// (2i+1, 2j+1)

    float s = v0 + v1 + v2 + v3;
    float ss = v0 * v0 + v1 * v1 + v2 * v2 + v3 * v3;
#pragma unroll
    for (int o = 16; o > 0; o >>= 1) {
        s += __shfl_xor_sync(~0u, s, o);
        ss += __shfl_xor_sync(~0u, ss, o);
    }
    __shared__ float red[2][8];
    int lane = threadIdx.x & 31, wp = threadIdx.x >> 5;
    if (lane == 0) { red[0][wp] = s; red[1][wp] = ss; }
    __syncthreads();
    if (threadIdx.x < 32) {
        float a = threadIdx.x < 8 ? red[0][threadIdx.x] : 0.f;
        float q = threadIdx.x < 8 ? red[1][threadIdx.x] : 0.f;
#pragma unroll
        for (int o = 4; o > 0; o >>= 1) {
            a += __shfl_xor_sync(~0u, a, o);
            q += __shfl_xor_sync(~0u, q, o);
        }
        if (threadIdx.x == 0) { red[0][0] = a; red[1][0] = q; }
    }
    __syncthreads();
    float mean = red[0][0] * (1.f / 1024.f);
    float var = red[1][0] * (1.f / 1024.f) - mean * mean;
    float inv = rsqrtf(var + EPS_LN);

    size_t ob = (size_t)b * 1024 * (size_t)P2 + p2;
    m_out[ob + (size_t)(0 * 256 + c) * P2] = (v0 - mean) * inv * lnw[0 * 256 + c] + lnb[0 * 256 + c];
    m_out[ob + (size_t)(1 * 256 + c) * P2] = (v1 - mean) * inv * lnw[1 * 256 + c] + lnb[1 * 256 + c];
    m_out[ob + (size_t)(2 * 256 + c) * P2] = (v2 - mean) * inv * lnw[2 * 256 + c] + lnb[2 * 256 + c];
    m_out[ob + (size_t)(3 * 256 + c) * P2] = (v3 - mean) * inv * lnw[3 * 256 + c] + lnb[3 * 256 + c];
}

// ---------------- global attention (4096 q x 1024 kv, hd=32) ----------------
// grid (32 qtiles, 8 heads, 4 batch); 128 threads, one query per thread.
// Writes out = attn_out + gridx  (global_x).
__global__ void glob_attn_kernel(const float* __restrict__ qg,
                                 const float* __restrict__ kv,
                                 const float* __restrict__ gridx,
                                 float* __restrict__ out) {
    int b = blockIdx.z, h = blockIdx.y;
    int tid = threadIdx.x;
    int p = blockIdx.x * 128 + tid;

    __shared__ float sk[128][33], sv[128][33];

    float q[32];
    size_t qbase = ((size_t)b * 256 + h * 32) * (size_t)P + p;
#pragma unroll
    for (int d = 0; d < 32; ++d) q[d] = qg[qbase + (size_t)d * P] * SCALE;

    float m = -1e30f, l = 0.f;
    float acc[32];
#pragma unroll
    for (int d = 0; d < 32; ++d) acc[d] = 0.f;

    size_t kbase = ((size_t)b * 512 + h * 32) * (size_t)P2;
    size_t vbase = kbase + (size_t)256 * P2;

    for (int t = 0; t < P2; t += 128) {
        __syncthreads();
#pragma unroll
        for (int d = 0; d < 32; ++d) {
            sk[tid][d] = kv[kbase + (size_t)d * P2 + t + tid];
            sv[tid][d] = kv[vbase + (size_t)d * P2 + t + tid];
        }
        __syncthreads();
        for (int r = 0; r < 128; ++r) {
            float s = 0.f;
#pragma unroll
            for (int d = 0; d < 32; ++d) s = fmaf(q[d], sk[r][d], s);
            if (s <= m) {
                float ps = __expf(s - m);
                l += ps;
#pragma unroll
                for (int d = 0; d < 32; ++d) acc[d] = fmaf(ps, sv[r][d], acc[d]);
            } else {
                float corr = __expf(m - s);
                m = s;
                l = fmaf(l, corr, 1.f);
#pragma unroll
                for (int d = 0; d < 32; ++d) acc[d] = fmaf(acc[d], corr, sv[r][d]);
            }
        }
    }
    float rl = 1.f / l;
    size_t obase = ((size_t)b * 256 + h * 32) * (size_t)P + p;
#pragma unroll
    for (int d = 0; d < 32; ++d)
        out[obase + (size_t)d * P] = fmaf(acc[d], rl, gridx[obase + (size_t)d * P]);
}

// ---------------- host launcher ----------------
static float* sym_addr(const void* s) {
    void* p = nullptr;
    cudaGetSymbolAddress(&p, s);
    return (float*)p;
}

extern "C" void kernel_launch(void* const* d_in, const int* in_sizes, int n_in,
                              void* d_out, int out_size) {
    const float* x        = (const float*)d_in[0];
    const float* norm_w   = (const float*)d_in[1];
    const float* norm_b   = (const float*)d_in[2];
    const float* qkv_w    = (const float*)d_in[3];
    const float* qkv_b    = (const float*)d_in[4];
    const float* proj_w   = (const float*)d_in[5];
    const float* proj_b   = (const float*)d_in[6];
    const float* gridnw   = (const float*)d_in[7];
    const float* gridnb   = (const float*)d_in[8];
    const float* pm_ln_w  = (const float*)d_in[9];
    const float* pm_ln_b  = (const float*)d_in[10];
    const float* pm_red_w = (const float*)d_in[11];
    const float* ds_nw    = (const float*)d_in[12];
    const float* ds_nb    = (const float*)d_in[13];
    const float* q_w      = (const float*)d_in[14];
    const float* q_b      = (const float*)d_in[15];
    const float* kv_w     = (const float*)d_in[16];
    const float* kv_b     = (const float*)d_in[17];
    float* out = (float*)d_out;

    float* xn    = sym_addr(g_xn);
    float* qkv   = sym_addr(g_qkv);
    float* gridx = sym_addr(g_gridx);
    float* mbuf  = sym_addr(g_m);
    float* pm    = sym_addr(g_pm);
    float* ds    = sym_addr(g_ds);
    float* qg    = sym_addr(g_qg);
    float* kvb   = sym_addr(g_kv);

    dim3 gnGrid(64, BATCH);

    // ---- stage 1: GN(x) -> xn; qkv = conv1x1(xn) ----
    zero_stats_kernel<<<1, 32>>>();
    gn_stats_kernel<<<gnGrid, 256>>>(x, C * P);
    gn_apply_kernel<<<gnGrid, 256>>>(x, norm_w, norm_b, xn, P, C * P, EPS_GN);
    gemm_kernel<<<dim3(P / 64, 768 / 64, BATCH), 256>>>(qkv_w, xn, qkv_b, qkv, 768, P, C);

    // ---- stage 2: windowed attention + residual; GN -> grid_x (in place) ----
    win_attn_kernel<<<2048, 64>>>(qkv, x, gridx);
    zero_stats_kernel<<<1, 32>>>();
    gn_stats_kernel<<<gnGrid, 256>>>(gridx, C * P);
    gn_apply_kernel<<<gnGrid, 256>>>(gridx, gridnw, gridnb, gridx, P, C * P, EPS_GN);

    // ---- stage 3: patch merge + LN -> m; pm = m @ pm_red_w^T ----
    patch_merge_ln_kernel<<<dim3(P2, BATCH), 256>>>(gridx, pm_ln_w, pm_ln_b, mbuf);
    gemm_kernel<<<dim3(P2 / 64, C / 64, BATCH), 256>>>(pm_red_w, mbuf, nullptr, pm, C, P2, 4 * C);

    // ---- stage 4: GN(pm) -> ds; q/kv projections ----
    zero_stats_kernel<<<1, 32>>>();
    gn_stats_kernel<<<gnGrid, 256>>>(pm, C * P2);
    gn_apply_kernel<<<gnGrid, 256>>>(pm, ds_nw, ds_nb, ds, P2, C * P2, EPS_GN);
    gemm_kernel<<<dim3(P / 64, C / 64, BATCH), 256>>>(q_w, gridx, q_b, qg, C, P, C);
    gemm_kernel<<<dim3(P2 / 64, 512 / 64, BATCH), 256>>>(kv_w, ds, kv_b, kvb, 512, P2, C);

    // ---- stage 5: global attention + residual -> global_x (reuse xn buffer) ----
    glob_attn_kernel<<<dim3(P / 128, NH, BATCH), 128>>>(qg, kvb, gridx, xn);

    // ---- stage 6: proj ----
    gemm_kernel<<<dim3(P / 64, C / 64, BATCH), 256>>>(proj_w, xn, proj_b, out, C, P, C);
}

// round 2
// speedup vs baseline: 1.2721x; 1.2721x over previous
#include <cuda_runtime.h>
#include <math.h>

// ---------------- problem constants ----------------
constexpr int BATCH = 4;
constexpr int C = 256;
constexpr int H = 64, W = 64;
constexpr int P = H * W;              // 4096
constexpr int NH = 8, HD = 32;
constexpr int P2 = (H / 2) * (W / 2); // 1024
constexpr float SCALE = 0.1767766952966369f; // 32^-0.5
constexpr float EPS_GN = 1e-6f;
constexpr float EPS_LN = 1e-5f;

// ---------------- scratch (device globals) ----------
__device__ float g_stats[2 * BATCH];
__device__ float g_xn[BATCH * C * P];
__device__ float g_qkv[BATCH * 3 * C * P];
__device__ float g_gridx[BATCH * C * P];
__device__ float g_m[BATCH * 4 * C * P2];
__device__ float g_pm[BATCH * C * P2];
__device__ float g_ds[BATCH * C * P2];
__device__ float g_qg[BATCH * C * P];
__device__ float g_kv[BATCH * 2 * C * P2];

// ---------------- GroupNorm helpers ----------------
__global__ void zero_stats_kernel() {
    if (threadIdx.x < 2 * BATCH) g_stats[threadIdx.x] = 0.f;
}

__global__ void gn_stats_kernel(const float* __restrict__ x, int per_batch) {
    int b = blockIdx.y;
    const float* xb = x + (size_t)b * per_batch;
    float s = 0.f, ss = 0.f;
    for (int i = blockIdx.x * blockDim.x + threadIdx.x; i < per_batch;
         i += gridDim.x * blockDim.x) {
        float v = xb[i];
        s += v;
        ss = fmaf(v, v, ss);
    }
#pragma unroll
    for (int o = 16; o > 0; o >>= 1) {
        s += __shfl_xor_sync(~0u, s, o);
        ss += __shfl_xor_sync(~0u, ss, o);
    }
    __shared__ float red[2][8];
    int lane = threadIdx.x & 31, wp = threadIdx.x >> 5;
    if (lane == 0) { red[0][wp] = s; red[1][wp] = ss; }
    __syncthreads();
    if (threadIdx.x < 32) {
        float a = threadIdx.x < 8 ? red[0][threadIdx.x] : 0.f;
        float q = threadIdx.x < 8 ? red[1][threadIdx.x] : 0.f;
#pragma unroll
        for (int o = 4; o > 0; o >>= 1) {
            a += __shfl_xor_sync(~0u, a, o);
            q += __shfl_xor_sync(~0u, q, o);
        }
        if (threadIdx.x == 0) {
            atomicAdd(&g_stats[2 * b], a);
            atomicAdd(&g_stats[2 * b + 1], q);
        }
    }
}

__global__ void gn_apply_kernel(const float* __restrict__ x,
                                const float* __restrict__ w,
                                const float* __restrict__ bias,
                                float* __restrict__ out,
                                int hw, int per_batch, float eps) {
    int b = blockIdx.y;
    float cnt = (float)per_batch;
    float mean = g_stats[2 * b] / cnt;
    float var = g_stats[2 * b + 1] / cnt - mean * mean;
    float inv = rsqrtf(var + eps);
    const float* xb = x + (size_t)b * per_batch;
    float* ob = out + (size_t)b * per_batch;
    for (int i = blockIdx.x * blockDim.x + threadIdx.x; i < per_batch;
         i += gridDim.x * blockDim.x) {
        int c = i / hw;
        ob[i] = (xb[i] - mean) * inv * w[c] + bias[c];
    }
}

// ---------------- GEMM 128x128 tile, 8x8/thread ----------------
// C[b] = A[M,K] * B[b][K,N] (+bias[M]); 256 threads, K tile 16.
__global__ __launch_bounds__(256, 2)
void gemm_kernel(const float* __restrict__ A,
                 const float* __restrict__ Bm,
                 const float* __restrict__ bias,
                 float* __restrict__ Cm,
                 int M, int N, int K) {
    const int b = blockIdx.z;
    Bm += (size_t)b * K * N;
    Cm += (size_t)b * M * N;
    __shared__ float As[16][128];
    __shared__ float Bs[16][128];
    const int tid = threadIdx.x;
    const int tx = tid & 15, ty = tid >> 4;
    const int m0 = blockIdx.y * 128, n0 = blockIdx.x * 128;
    // A loader: 2x float4 (rows ar, ar+64)
    const int ar = tid >> 2;
    const int ac = (tid & 3) << 2;
    // B loader: 2x float4 (k-rows br, br+8)
    const int br = tid >> 5;
    const int bc = (tid & 31) << 2;

    float acc[8][8] = {};
    for (int k0 = 0; k0 < K; k0 += 16) {
        float4 a0 = *(const float4*)&A[(size_t)(m0 + ar) * K + k0 + ac];
        float4 a1 = *(const float4*)&A[(size_t)(m0 + ar + 64) * K + k0 + ac];
        As[ac + 0][ar] = a0.x; As[ac + 1][ar] = a0.y;
        As[ac + 2][ar] = a0.z; As[ac + 3][ar] = a0.w;
        As[ac + 0][ar + 64] = a1.x; As[ac + 1][ar + 64] = a1.y;
        As[ac + 2][ar + 64] = a1.z; As[ac + 3][ar + 64] = a1.w;
        *(float4*)&Bs[br][bc]     = *(const float4*)&Bm[(size_t)(k0 + br) * N + n0 + bc];
        *(float4*)&Bs[br + 8][bc] = *(const float4*)&Bm[(size_t)(k0 + br + 8) * N + n0 + bc];
        __syncthreads();
#pragma unroll
        for (int kk = 0; kk < 16; ++kk) {
            float4 a01 = *(const float4*)&As[kk][ty * 8];
            float4 a23 = *(const float4*)&As[kk][ty * 8 + 4];
            float4 b01 = *(const float4*)&Bs[kk][tx * 8];
            float4 b23 = *(const float4*)&Bs[kk][tx * 8 + 4];
            float ar8[8] = {a01.x, a01.y, a01.z, a01.w, a23.x, a23.y, a23.z, a23.w};
            float br8[8] = {b01.x, b01.y, b01.z, b01.w, b23.x, b23.y, b23.z, b23.w};
#pragma unroll
            for (int i = 0; i < 8; ++i)
#pragma unroll
                for (int j = 0; j < 8; ++j)
                    acc[i][j] = fmaf(ar8[i], br8[j], acc[i][j]);
        }
        __syncthreads();
    }
#pragma unroll
    for (int i = 0; i < 8; ++i) {
        int m = m0 + ty * 8 + i;
        float bv = bias ? bias[m] : 0.f;
        float4 o0, o1;
        o0.x = acc[i][0] + bv; o0.y = acc[i][1] + bv;
        o0.z = acc[i][2] + bv; o0.w = acc[i][3] + bv;
        o1.x = acc[i][4] + bv; o1.y = acc[i][5] + bv;
        o1.z = acc[i][6] + bv; o1.w = acc[i][7] + bv;
        *(float4*)&Cm[(size_t)m * N + n0 + tx * 8] = o0;
        *(float4*)&Cm[(size_t)m * N + n0 + tx * 8 + 4] = o1;
    }
}

// ---------------- windowed 8x8 attention ----------------
// 128 threads = 2 heads x 64 tokens; grid (64 windows, 4 head-pairs, batch).
// dyn smem: wk[2][32][64], wv[2][32][64], sc[128][65]
constexpr int WIN_SMEM = (2 * 32 * 64 * 2 + 128 * 65) * 4;
__global__ __launch_bounds__(128)
void win_attn_kernel(const float* __restrict__ qkv,
                     const float* __restrict__ x,
                     float* __restrict__ out) {
    extern __shared__ float sm[];
    float* wk = sm;                   // [2][32][64]
    float* wv = sm + 2 * 32 * 64;     // [2][32][64]
    float* sc = sm + 4 * 32 * 64;     // [128][65]

    const int win = blockIdx.x;            // gi*8+gj
    const int gi = win >> 3, gj = win & 7;
    const int hp = blockIdx.y;
    const int b = blockIdx.z;
    const int tid = threadIdx.x;
    const int hl = tid >> 6, t = tid & 63;
    const int h = hp * 2 + hl;

    // load K,V for both heads: 8192 elems
    for (int idx = tid; idx < 8192; idx += 128) {
        int token = idx & 63;
        int d = (idx >> 6) & 31;
        int tsel = (idx >> 11) & 1;   // 0=k, 1=v
        int hh = idx >> 12;           // head-local
        int ch = (tsel ? 512 : 256) + (hp * 2 + hh) * 32 + d;
        int si = token >> 3, sj = token & 7;
        int sp = (gi * 8 + si) * W + gj * 8 + sj;
        float val = qkv[((size_t)b * 768 + ch) * (size_t)P + sp];
        (tsel ? wv : wk)[hh * 2048 + d * 64 + token] = val;
    }
    __syncthreads();

    const int si = t >> 3, sj = t & 7;
    const int sp = (gi * 8 + si) * W + gj * 8 + sj;
    float q[32];
    size_t qb = ((size_t)b * 768 + h * 32) * (size_t)P + sp;
#pragma unroll
    for (int d = 0; d < 32; ++d) q[d] = qkv[qb + (size_t)d * P] * SCALE;

    const float* kh = wk + hl * 2048;
    const float* vh = wv + hl * 2048;
    float* myc = sc + tid * 65;

    float mx = -1e30f;
    for (int j = 0; j < 64; ++j) {
        float s = 0.f;
#pragma unroll
        for (int d = 0; d < 32; ++d) s = fmaf(q[d], kh[d * 64 + j], s);
        myc[j] = s;
        mx = fmaxf(mx, s);
    }
    float l = 0.f;
    for (int j = 0; j < 64; ++j) {
        float p_ = __expf(myc[j] - mx);
        myc[j] = p_;
        l += p_;
    }
    float rl = 1.f / l;

    float acc[32];
#pragma unroll
    for (int d = 0; d < 32; ++d) acc[d] = 0.f;
    for (int j = 0; j < 64; ++j) {
        float p_ = myc[j];
#pragma unroll
        for (int d = 0; d < 32; ++d) acc[d] = fmaf(p_, vh[d * 64 + j], acc[d]);
    }

    size_t ob = ((size_t)b * 256 + h * 32) * (size_t)P + sp;
#pragma unroll
    for (int d = 0; d < 32; ++d)
        out[ob + (size_t)d * P] = x[ob + (size_t)d * P] + acc[d] * rl;
}

// ---------------- patch merge + LayerNorm ----------------
__global__ void patch_merge_ln_kernel(const float* __restrict__ gx,
                                      const float* __restrict__ lnw,
                                      const float* __restrict__ lnb,
                                      float* __restrict__ m_out) {
    int b = blockIdx.y;
    int p2 = blockIdx.x;
    int i = p2 >> 5, j = p2 & 31;
    int c = threadIdx.x;
    size_t base = ((size_t)b * 256 + c) * (size_t)P;
    int sp00 = (2 * i) * W + 2 * j;
    float v0 = gx[base + sp00];
    float v1 = gx[base + sp00 + W];
    float v2 = gx[base + sp00 + 1];
    float v3 = gx[base + sp00 + W + 1];

    float s = v0 + v1 + v2 + v3;
    float ss = v0 * v0 + v1 * v1 + v2 * v2 + v3 * v3;
#pragma unroll
    for (int o = 16; o > 0; o >>= 1) {
        s += __shfl_xor_sync(~0u, s, o);
        ss += __shfl_xor_sync(~0u, ss, o);
    }
    __shared__ float red[2][8];
    int lane = threadIdx.x & 31, wp = threadIdx.x >> 5;
    if (lane == 0) { red[0][wp] = s; red[1][wp] = ss; }
    __syncthreads();
    if (threadIdx.x < 32) {
        float a = threadIdx.x < 8 ? red[0][threadIdx.x] : 0.f;
        float q = threadIdx.x < 8 ? red[1][threadIdx.x] : 0.f;
#pragma unroll
        for (int o = 4; o > 0; o >>= 1) {
            a += __shfl_xor_sync(~0u, a, o);
            q += __shfl_xor_sync(~0u, q, o);
        }
        if (threadIdx.x == 0) { red[0][0] = a; red[1][0] = q; }
    }
    __syncthreads();
    float mean = red[0][0] * (1.f / 1024.f);
    float var = red[1][0] * (1.f / 1024.f) - mean * mean;
    float inv = rsqrtf(var + EPS_LN);

    size_t ob = (size_t)b * 1024 * (size_t)P2 + p2;
    m_out[ob + (size_t)(0 * 256 + c) * P2] = (v0 - mean) * inv * lnw[0 * 256 + c] + lnb[0 * 256 + c];
    m_out[ob + (size_t)(1 * 256 + c) * P2] = (v1 - mean) * inv * lnw[1 * 256 + c] + lnb[1 * 256 + c];
    m_out[ob + (size_t)(2 * 256 + c) * P2] = (v2 - mean) * inv * lnw[2 * 256 + c] + lnb[2 * 256 + c];
    m_out[ob + (size_t)(3 * 256 + c) * P2] = (v3 - mean) * inv * lnw[3 * 256 + c] + lnb[3 * 256 + c];
}

// ---------------- global attention ----------------
// 128 threads (1 query each), 128-key tiles, two-pass softmax per tile.
// dyn smem: sk[128][36], sv[128][36], sc[128][129]
constexpr int GLOB_SMEM = (2 * 128 * 36 + 128 * 129) * 4;
__global__ __launch_bounds__(128)
void glob_attn_kernel(const float* __restrict__ qg,
                      const float* __restrict__ kv,
                      const float* __restrict__ gridx,
                      float* __restrict__ out) {
    extern __shared__ float sm[];
    float* sk = sm;                 // [128][36]
    float* sv = sm + 128 * 36;      // [128][36]
    float* sc = sm + 2 * 128 * 36;  // [128][129]

    const int b = blockIdx.z, h = blockIdx.y;
    const int tid = threadIdx.x;
    const int p = blockIdx.x * 128 + tid;

    float q[32];
    size_t qbase = ((size_t)b * 256 + h * 32) * (size_t)P + p;
#pragma unroll
    for (int d = 0; d < 32; ++d) q[d] = qg[qbase + (size_t)d * P] * SCALE;

    float m = -1e30f, l = 0.f;
    float acc[32];
#pragma unroll
    for (int d = 0; d < 32; ++d) acc[d] = 0.f;

    size_t kbase = ((size_t)b * 512 + h * 32) * (size_t)P2;
    size_t vbase = kbase + (size_t)256 * P2;
    float* myc = sc + tid * 129;

    for (int t = 0; t < P2; t += 128) {
        __syncthreads();
#pragma unroll
        for (int d = 0; d < 32; ++d) {
            sk[tid * 36 + d] = kv[kbase + (size_t)d * P2 + t + tid];
            sv[tid * 36 + d] = kv[vbase + (size_t)d * P2 + t + tid];
        }
        __syncthreads();

        // pass 1: scores + tile max
        float tm = -1e30f;
        for (int r = 0; r < 128; ++r) {
            const float4* kr = (const float4*)&sk[r * 36];
            float s = 0.f;
#pragma unroll
            for (int d4 = 0; d4 < 8; ++d4) {
                float4 kvv = kr[d4];
                s = fmaf(q[d4 * 4 + 0], kvv.x, s);
                s = fmaf(q[d4 * 4 + 1], kvv.y, s);
                s = fmaf(q[d4 * 4 + 2], kvv.z, s);
                s = fmaf(q[d4 * 4 + 3], kvv.w, s);
            }
            myc[r] = s;
            tm = fmaxf(tm, s);
        }
        // rescale running state once per tile
        float nm = fmaxf(m, tm);
        float corr = __expf(m - nm);
        m = nm;
        l *= corr;
#pragma unroll
        for (int d = 0; d < 32; ++d) acc[d] *= corr;

        // pass 2: exp + accumulate
        for (int r = 0; r < 128; ++r) {
            float p_ = __expf(myc[r] - nm);
            l += p_;
            const float4* vr = (const float4*)&sv[r * 36];
#pragma unroll
            for (int d4 = 0; d4 < 8; ++d4) {
                float4 vv = vr[d4];
                acc[d4 * 4 + 0] = fmaf(p_, vv.x, acc[d4 * 4 + 0]);
                acc[d4 * 4 + 1] = fmaf(p_, vv.y, acc[d4 * 4 + 1]);
                acc[d4 * 4 + 2] = fmaf(p_, vv.z, acc[d4 * 4 + 2]);
                acc[d4 * 4 + 3] = fmaf(p_, vv.w, acc[d4 * 4 + 3]);
            }
        }
    }
    float rl = 1.f / l;
    size_t obase = ((size_t)b * 256 + h * 32) * (size_t)P + p;
#pragma unroll
    for (int d = 0; d < 32; ++d)
        out[obase + (size_t)d * P] = fmaf(acc[d], rl, gridx[obase + (size_t)d * P]);
}

// ---------------- host launcher ----------------
static float* sym_addr(const void* s) {
    void* p = nullptr;
    cudaGetSymbolAddress(&p, s);
    return (float*)p;
}

extern "C" void kernel_launch(void* const* d_in, const int* in_sizes, int n_in,
                              void* d_out, int out_size) {
    const float* x        = (const float*)d_in[0];
    const float* norm_w   = (const float*)d_in[1];
    const float* norm_b   = (const float*)d_in[2];
    const float* qkv_w    = (const float*)d_in[3];
    const float* qkv_b    = (const float*)d_in[4];
    const float* proj_w   = (const float*)d_in[5];
    const float* proj_b   = (const float*)d_in[6];
    const float* gridnw   = (const float*)d_in[7];
    const float* gridnb   = (const float*)d_in[8];
    const float* pm_ln_w  = (const float*)d_in[9];
    const float* pm_ln_b  = (const float*)d_in[10];
    const float* pm_red_w = (const float*)d_in[11];
    const float* ds_nw    = (const float*)d_in[12];
    const float* ds_nb    = (const float*)d_in[13];
    const float* q_w      = (const float*)d_in[14];
    const float* q_b      = (const float*)d_in[15];
    const float* kv_w     = (const float*)d_in[16];
    const float* kv_b     = (const float*)d_in[17];
    float* out = (float*)d_out;

    float* xn    = sym_addr(g_xn);
    float* qkv   = sym_addr(g_qkv);
    float* gridx = sym_addr(g_gridx);
    float* mbuf  = sym_addr(g_m);
    float* pm    = sym_addr(g_pm);
    float* ds    = sym_addr(g_ds);
    float* qg    = sym_addr(g_qg);
    float* kvb   = sym_addr(g_kv);

    cudaFuncSetAttribute(win_attn_kernel,
                         cudaFuncAttributeMaxDynamicSharedMemorySize, WIN_SMEM);
    cudaFuncSetAttribute(glob_attn_kernel,
                         cudaFuncAttributeMaxDynamicSharedMemorySize, GLOB_SMEM);

    dim3 gnGrid(64, BATCH);

    // ---- stage 1: GN(x) -> xn; qkv = conv1x1(xn) ----
    zero_stats_kernel<<<1, 32>>>();
    gn_stats_kernel<<<gnGrid, 256>>>(x, C * P);
    gn_apply_kernel<<<gnGrid, 256>>>(x, norm_w, norm_b, xn, P, C * P, EPS_GN);
    gemm_kernel<<<dim3(P / 128, 768 / 128, BATCH), 256>>>(qkv_w, xn, qkv_b, qkv, 768, P, C);

    // ---- stage 2: windowed attention + residual; GN -> grid_x ----
    win_attn_kernel<<<dim3(64, 4, BATCH), 128, WIN_SMEM>>>(qkv, x, gridx);
    zero_stats_kernel<<<1, 32>>>();
    gn_stats_kernel<<<gnGrid, 256>>>(gridx, C * P);
    gn_apply_kernel<<<gnGrid, 256>>>(gridx, gridnw, gridnb, gridx, P, C * P, EPS_GN);

    // ---- stage 3: patch merge + LN; pm reduction GEMM ----
    patch_merge_ln_kernel<<<dim3(P2, BATCH), 256>>>(gridx, pm_ln_w, pm_ln_b, mbuf);
    gemm_kernel<<<dim3(P2 / 128, C / 128, BATCH), 256>>>(pm_red_w, mbuf, nullptr, pm, C, P2, 4 * C);

    // ---- stage 4: GN(pm) -> ds; q/kv projections ----
    zero_stats_kernel<<<1, 32>>>();
    gn_stats_kernel<<<gnGrid, 256>>>(pm, C * P2);
    gn_apply_kernel<<<gnGrid, 256>>>(pm, ds_nw, ds_nb, ds, P2, C * P2, EPS_GN);
    gemm_kernel<<<dim3(P / 128, C / 128, BATCH), 256>>>(q_w, gridx, q_b, qg, C, P, C);
    gemm_kernel<<<dim3(P2 / 128, 512 / 128, BATCH), 256>>>(kv_w, ds, kv_b, kvb, 512, P2, C);

    // ---- stage 5: global attention + residual ----
    glob_attn_kernel<<<dim3(P / 128, NH, BATCH), 128, GLOB_SMEM>>>(qg, kvb, gridx, xn);

    // ---- stage 6: proj ----
    gemm_kernel<<<dim3(P / 128, C / 128, BATCH), 256>>>(proj_w, xn, proj_b, out, C, P, C);
}

// round 3
// speedup vs baseline: 2.8249x; 2.2207x over previous
#include <cuda_runtime.h>
#include <math.h>
#include <stdint.h>

// ---------------- problem constants ----------------
constexpr int BATCH = 4;
constexpr int C = 256;
constexpr int H = 64, W = 64;
constexpr int P = H * W;              // 4096
constexpr int NH = 8, HD = 32;
constexpr int P2 = (H / 2) * (W / 2); // 1024
constexpr float SCALE = 0.1767766952966369f; // 32^-0.5
constexpr float EPS_GN = 1e-6f;
constexpr float EPS_LN = 1e-5f;

// ---------------- scratch (device globals) ----------
__device__ float g_stats[2 * BATCH];
__device__ float g_xn[BATCH * C * P];
__device__ float g_qkv[BATCH * 3 * C * P];
__device__ float g_gridx[BATCH * C * P];
__device__ float g_m[BATCH * 4 * C * P2];
__device__ float g_pm[BATCH * C * P2];
__device__ float g_ds[BATCH * C * P2];
__device__ float g_qg[BATCH * C * P];
__device__ float g_kv[BATCH * 2 * C * P2];

// ---------------- mma helpers ----------------
__device__ __forceinline__ uint32_t f2tf(float f) {
    uint32_t u;
    asm("cvt.rna.tf32.f32 %0, %1;" : "=r"(u) : "f"(f));
    return u;
}
__device__ __forceinline__ void mma_tf32(float* c, const uint32_t* a,
                                         uint32_t b0, uint32_t b1) {
    asm volatile(
        "mma.sync.aligned.m16n8k8.row.col.f32.tf32.tf32.f32 "
        "{%0,%1,%2,%3}, {%4,%5,%6,%7}, {%8,%9}, {%0,%1,%2,%3};"
        : "+f"(c[0]), "+f"(c[1]), "+f"(c[2]), "+f"(c[3])
        : "r"(a[0]), "r"(a[1]), "r"(a[2]), "r"(a[3]), "r"(b0), "r"(b1));
}

// ---------------- GroupNorm helpers ----------------
__global__ void zero_stats_kernel() {
    if (threadIdx.x < 2 * BATCH) g_stats[threadIdx.x] = 0.f;
}

__global__ void gn_stats_kernel(const float* __restrict__ x, int per_batch) {
    int b = blockIdx.y;
    const float* xb = x + (size_t)b * per_batch;
    float s = 0.f, ss = 0.f;
    for (int i = blockIdx.x * blockDim.x + threadIdx.x; i < per_batch;
         i += gridDim.x * blockDim.x) {
        float v = xb[i];
        s += v;
        ss = fmaf(v, v, ss);
    }
#pragma unroll
    for (int o = 16; o > 0; o >>= 1) {
        s += __shfl_xor_sync(~0u, s, o);
        ss += __shfl_xor_sync(~0u, ss, o);
    }
    __shared__ float red[2][8];
    int lane = threadIdx.x & 31, wp = threadIdx.x >> 5;
    if (lane == 0) { red[0][wp] = s; red[1][wp] = ss; }
    __syncthreads();
    if (threadIdx.x < 32) {
        float a = threadIdx.x < 8 ? red[0][threadIdx.x] : 0.f;
        float q = threadIdx.x < 8 ? red[1][threadIdx.x] : 0.f;
#pragma unroll
        for (int o = 4; o > 0; o >>= 1) {
            a += __shfl_xor_sync(~0u, a, o);
            q += __shfl_xor_sync(~0u, q, o);
        }
        if (threadIdx.x == 0) {
            atomicAdd(&g_stats[2 * b], a);
            atomicAdd(&g_stats[2 * b + 1], q);
        }
    }
}

__global__ void gn_apply_kernel(const float* __restrict__ x,
                                const float* __restrict__ w,
                                const float* __restrict__ bias,
                                float* __restrict__ out,
                                int hw, int per_batch, float eps) {
    int b = blockIdx.y;
    float cnt = (float)per_batch;
    float mean = g_stats[2 * b] / cnt;
    float var = g_stats[2 * b + 1] / cnt - mean * mean;
    float inv = rsqrtf(var + eps);
    const float* xb = x + (size_t)b * per_batch;
    float* ob = out + (size_t)b * per_batch;
    for (int i = blockIdx.x * blockDim.x + threadIdx.x; i < per_batch;
         i += gridDim.x * blockDim.x) {
        int c = i / hw;
        ob[i] = (xb[i] - mean) * inv * w[c] + bias[c];
    }
}

// ---------------- TF32 GEMM: C[b] = A[M,K] * B[b][K,N] (+bias[M]) --------
// 128x128 tile, 8 warps (2x4), warp tile 64x32, mma m16n8k8.
constexpr int GEMM_LDS = 136;  // smem row stride (floats), conflict-free frag loads
__global__ __launch_bounds__(256)
void gemm_tf32_kernel(const float* __restrict__ A,
                      const float* __restrict__ Bm,
                      const float* __restrict__ bias,
                      float* __restrict__ Cm,
                      int M, int N, int K) {
    const int b = blockIdx.z;
    Bm += (size_t)b * K * N;
    Cm += (size_t)b * M * N;
    __shared__ float As[16 * GEMM_LDS];
    __shared__ float Bs[16 * GEMM_LDS];
    const int tid = threadIdx.x;
    const int warp = tid >> 5, lane = tid & 31;
    const int wm = warp >> 2, wn = warp & 3;     // 2 x 4 warps
    const int g = lane >> 2, tq = lane & 3;
    const int m0 = blockIdx.y * 128, n0 = blockIdx.x * 128;
    // A loader: 2 float4 rows (ar, ar+64), k cols ac..ac+3
    const int ar = tid >> 2;
    const int ac = (tid & 3) << 2;
    // B loader: rows br, br+8; 128 cols via float4
    const int br = tid >> 5;
    const int bc = lane << 2;

    float acc[4][4][4] = {};
    for (int k0 = 0; k0 < K; k0 += 16) {
        float4 a0v = *(const float4*)&A[(size_t)(m0 + ar) * K + k0 + ac];
        float4 a1v = *(const float4*)&A[(size_t)(m0 + ar + 64) * K + k0 + ac];
        As[(ac + 0) * GEMM_LDS + ar] = a0v.x;
        As[(ac + 1) * GEMM_LDS + ar] = a0v.y;
        As[(ac + 2) * GEMM_LDS + ar] = a0v.z;
        As[(ac + 3) * GEMM_LDS + ar] = a0v.w;
        As[(ac + 0) * GEMM_LDS + ar + 64] = a1v.x;
        As[(ac + 1) * GEMM_LDS + ar + 64] = a1v.y;
        As[(ac + 2) * GEMM_LDS + ar + 64] = a1v.z;
        As[(ac + 3) * GEMM_LDS + ar + 64] = a1v.w;
        *(float4*)&Bs[br * GEMM_LDS + bc] =
            *(const float4*)&Bm[(size_t)(k0 + br) * N + n0 + bc];
        *(float4*)&Bs[(br + 8) * GEMM_LDS + bc] =
            *(const float4*)&Bm[(size_t)(k0 + br + 8) * N + n0 + bc];
        __syncthreads();
#pragma unroll
        for (int ks = 0; ks < 2; ++ks) {
            const int kb = ks * 8;
            uint32_t af[4][4];
            uint32_t bf[4][2];
#pragma unroll
            for (int mt = 0; mt < 4; ++mt) {
                const int mb = wm * 64 + mt * 16;
                af[mt][0] = f2tf(As[(kb + tq) * GEMM_LDS + mb + g]);
                af[mt][1] = f2tf(As[(kb + tq) * GEMM_LDS + mb + 8 + g]);
                af[mt][2] = f2tf(As[(kb + tq + 4) * GEMM_LDS + mb + g]);
                af[mt][3] = f2tf(As[(kb + tq + 4) * GEMM_LDS + mb + 8 + g]);
            }
#pragma unroll
            for (int nt = 0; nt < 4; ++nt) {
                const int nb = wn * 32 + nt * 8;
                bf[nt][0] = f2tf(Bs[(kb + tq) * GEMM_LDS + nb + g]);
                bf[nt][1] = f2tf(Bs[(kb + tq + 4) * GEMM_LDS + nb + g]);
            }
#pragma unroll
            for (int mt = 0; mt < 4; ++mt)
#pragma unroll
                for (int nt = 0; nt < 4; ++nt)
                    mma_tf32(acc[mt][nt], af[mt], bf[nt][0], bf[nt][1]);
        }
        __syncthreads();
    }
#pragma unroll
    for (int mt = 0; mt < 4; ++mt) {
#pragma unroll
        for (int nt = 0; nt < 4; ++nt) {
            int row = m0 + wm * 64 + mt * 16 + g;
            int col = n0 + wn * 32 + nt * 8 + tq * 2;
            float bv0 = bias ? bias[row] : 0.f;
            float bv1 = bias ? bias[row + 8] : 0.f;
            float2 o0 = {acc[mt][nt][0] + bv0, acc[mt][nt][1] + bv0};
            float2 o1 = {acc[mt][nt][2] + bv1, acc[mt][nt][3] + bv1};
            *(float2*)&Cm[(size_t)row * N + col] = o0;
            *(float2*)&Cm[(size_t)(row + 8) * N + col] = o1;
        }
    }
}

// ---------------- windowed 8x8 attention (unchanged) ----------------
constexpr int WIN_SMEM = (2 * 32 * 64 * 2 + 128 * 65) * 4;
__global__ __launch_bounds__(128)
void win_attn_kernel(const float* __restrict__ qkv,
                     const float* __restrict__ x,
                     float* __restrict__ out) {
    extern __shared__ float sm[];
    float* wk = sm;
    float* wv = sm + 2 * 32 * 64;
    float* sc = sm + 4 * 32 * 64;

    const int win = blockIdx.x;
    const int gi = win >> 3, gj = win & 7;
    const int hp = blockIdx.y;
    const int b = blockIdx.z;
    const int tid = threadIdx.x;
    const int hl = tid >> 6, t = tid & 63;
    const int h = hp * 2 + hl;

    for (int idx = tid; idx < 8192; idx += 128) {
        int token = idx & 63;
        int d = (idx >> 6) & 31;
        int tsel = (idx >> 11) & 1;
        int hh = idx >> 12;
        int ch = (tsel ? 512 : 256) + (hp * 2 + hh) * 32 + d;
        int si = token >> 3, sj = token & 7;
        int sp = (gi * 8 + si) * W + gj * 8 + sj;
        float val = qkv[((size_t)b * 768 + ch) * (size_t)P + sp];
        (tsel ? wv : wk)[hh * 2048 + d * 64 + token] = val;
    }
    __syncthreads();

    const int si = t >> 3, sj = t & 7;
    const int sp = (gi * 8 + si) * W + gj * 8 + sj;
    float q[32];
    size_t qb = ((size_t)b * 768 + h * 32) * (size_t)P + sp;
#pragma unroll
    for (int d = 0; d < 32; ++d) q[d] = qkv[qb + (size_t)d * P] * SCALE;

    const float* kh = wk + hl * 2048;
    const float* vh = wv + hl * 2048;
    float* myc = sc + tid * 65;

    float mx = -1e30f;
    for (int j = 0; j < 64; ++j) {
        float s = 0.f;
#pragma unroll
        for (int d = 0; d < 32; ++d) s = fmaf(q[d], kh[d * 64 + j], s);
        myc[j] = s;
        mx = fmaxf(mx, s);
    }
    float l = 0.f;
    for (int j = 0; j < 64; ++j) {
        float p_ = __expf(myc[j] - mx);
        myc[j] = p_;
        l += p_;
    }
    float rl = 1.f / l;

    float acc[32];
#pragma unroll
    for (int d = 0; d < 32; ++d) acc[d] = 0.f;
    for (int j = 0; j < 64; ++j) {
        float p_ = myc[j];
#pragma unroll
        for (int d = 0; d < 32; ++d) acc[d] = fmaf(p_, vh[d * 64 + j], acc[d]);
    }

    size_t ob = ((size_t)b * 256 + h * 32) * (size_t)P + sp;
#pragma unroll
    for (int d = 0; d < 32; ++d)
        out[ob + (size_t)d * P] = x[ob + (size_t)d * P] + acc[d] * rl;
}

// ---------------- patch merge + LayerNorm (unchanged) ----------------
__global__ void patch_merge_ln_kernel(const float* __restrict__ gx,
                                      const float* __restrict__ lnw,
                                      const float* __restrict__ lnb,
                                      float* __restrict__ m_out) {
    int b = blockIdx.y;
    int p2 = blockIdx.x;
    int i = p2 >> 5, j = p2 & 31;
    int c = threadIdx.x;
    size_t base = ((size_t)b * 256 + c) * (size_t)P;
    int sp00 = (2 * i) * W + 2 * j;
    float v0 = gx[base + sp00];
    float v1 = gx[base + sp00 + W];
    float v2 = gx[base + sp00 + 1];
    float v3 = gx[base + sp00 + W + 1];

    float s = v0 + v1 + v2 + v3;
    float ss = v0 * v0 + v1 * v1 + v2 * v2 + v3 * v3;
#pragma unroll
    for (int o = 16; o > 0; o >>= 1) {
        s += __shfl_xor_sync(~0u, s, o);
        ss += __shfl_xor_sync(~0u, ss, o);
    }
    __shared__ float red[2][8];
    int lane = threadIdx.x & 31, wp = threadIdx.x >> 5;
    if (lane == 0) { red[0][wp] = s; red[1][wp] = ss; }
    __syncthreads();
    if (threadIdx.x < 32) {
        float a = threadIdx.x < 8 ? red[0][threadIdx.x] : 0.f;
        float q = threadIdx.x < 8 ? red[1][threadIdx.x] : 0.f;
#pragma unroll
        for (int o = 4; o > 0; o >>= 1) {
            a += __shfl_xor_sync(~0u, a, o);
            q += __shfl_xor_sync(~0u, q, o);
        }
        if (threadIdx.x == 0) { red[0][0] = a; red[1][0] = q; }
    }
    __syncthreads();
    float mean = red[0][0] * (1.f / 1024.f);
    float var = red[1][0] * (1.f / 1024.f) - mean * mean;
    float inv = rsqrtf(var + EPS_LN);

    size_t ob = (size_t)b * 1024 * (size_t)P2 + p2;
    m_out[ob + (size_t)(0 * 256 + c) * P2] = (v0 - mean) * inv * lnw[0 * 256 + c] + lnb[0 * 256 + c];
    m_out[ob + (size_t)(1 * 256 + c) * P2] = (v1 - mean) * inv * lnw[1 * 256 + c] + lnb[1 * 256 + c];
    m_out[ob + (size_t)(2 * 256 + c) * P2] = (v2 - mean) * inv * lnw[2 * 256 + c] + lnb[2 * 256 + c];
    m_out[ob + (size_t)(3 * 256 + c) * P2] = (v3 - mean) * inv * lnw[3 * 256 + c] + lnb[3 * 256 + c];
}

// ---------------- global attention: flash-style TF32 mma ----------------
// Block: 128 queries, 4 warps (32 q-rows each); K-tiles of 64 keys.
// smem: sQ[32][136] (also output staging), sK[32][72], sV[32][72], sP[128][72]
constexpr int SQ_LD = 136;
constexpr int SK_LD = 72;
constexpr int GLOB_SMEM = (32 * SQ_LD + 2 * 32 * SK_LD + 128 * SK_LD) * 4;
__global__ __launch_bounds__(128, 2)
void glob_attn_mma_kernel(const float* __restrict__ qg,
                          const float* __restrict__ kv,
                          const float* __restrict__ gridx,
                          float* __restrict__ out) {
    extern __shared__ float sm[];
    float* sQ = sm;                       // [32][136]
    float* sK = sm + 32 * SQ_LD;          // [32][72]
    float* sV = sK + 32 * SK_LD;          // [32][72]
    float* sP = sV + 32 * SK_LD;          // [128][72]

    const int b = blockIdx.z, h = blockIdx.y;
    const int q0 = blockIdx.x * 128;
    const int tid = threadIdx.x, warp = tid >> 5, lane = tid & 31;
    const int g = lane >> 2, tq = lane & 3;

    // ---- load Q tile (scaled) into sQ[d][q] ----
    const size_t qbase = ((size_t)b * 256 + h * 32) * (size_t)P + q0;
    for (int i = tid; i < 32 * 32; i += 128) {
        int d = i >> 5, q4 = (i & 31) << 2;
        float4 v = *(const float4*)&qg[qbase + (size_t)d * P + q4];
        v.x *= SCALE; v.y *= SCALE; v.z *= SCALE; v.w *= SCALE;
        *(float4*)&sQ[d * SQ_LD + q4] = v;
    }
    __syncthreads();

    // ---- extract Q fragments (resident in regs) ----
    uint32_t qf[2][4][4];
#pragma unroll
    for (int mt = 0; mt < 2; ++mt) {
        const int qb = warp * 32 + mt * 16;
#pragma unroll
        for (int ks = 0; ks < 4; ++ks) {
            const int kb = ks * 8;
            qf[mt][ks][0] = f2tf(sQ[(kb + tq) * SQ_LD + qb + g]);
            qf[mt][ks][1] = f2tf(sQ[(kb + tq) * SQ_LD + qb + 8 + g]);
            qf[mt][ks][2] = f2tf(sQ[(kb + tq + 4) * SQ_LD + qb + g]);
            qf[mt][ks][3] = f2tf(sQ[(kb + tq + 4) * SQ_LD + qb + 8 + g]);
        }
    }

    float O[2][4][4] = {};
    float mrow[2][2], lrow[2][2];
#pragma unroll
    for (int mt = 0; mt < 2; ++mt) {
        mrow[mt][0] = mrow[mt][1] = -1e30f;
        lrow[mt][0] = lrow[mt][1] = 0.f;
    }

    const size_t kbase = ((size_t)b * 512 + h * 32) * (size_t)P2;
    const size_t vbase = kbase + (size_t)256 * P2;

    for (int t = 0; t < P2; t += 64) {
        __syncthreads();  // all warps done with previous sK/sV
        for (int i = tid; i < 32 * 16; i += 128) {
            int d = i >> 4, c4 = (i & 15) << 2;
            *(float4*)&sK[d * SK_LD + c4] = *(const float4*)&kv[kbase + (size_t)d * P2 + t + c4];
            *(float4*)&sV[d * SK_LD + c4] = *(const float4*)&kv[vbase + (size_t)d * P2 + t + c4];
        }
        __syncthreads();

        // ---- S = Q K^T (64 keys) ----
        float S[2][8][4];
#pragma unroll
        for (int nt = 0; nt < 8; ++nt) {
            const int nb = nt * 8;
            uint32_t b0[4], b1[4];
#pragma unroll
            for (int ks = 0; ks < 4; ++ks) {
                const int kb = ks * 8;
                b0[ks] = f2tf(sK[(kb + tq) * SK_LD + nb + g]);
                b1[ks] = f2tf(sK[(kb + tq + 4) * SK_LD + nb + g]);
            }
#pragma unroll
            for (int mt = 0; mt < 2; ++mt) {
                S[mt][nt][0] = S[mt][nt][1] = S[mt][nt][2] = S[mt][nt][3] = 0.f;
#pragma unroll
                for (int ks = 0; ks < 4; ++ks)
                    mma_tf32(S[mt][nt], qf[mt][ks], b0[ks], b1[ks]);
            }
        }

        // ---- online softmax + stage probs to sP ----
#pragma unroll
        for (int mt = 0; mt < 2; ++mt) {
            const int qb = warp * 32 + mt * 16;
            float tm0 = -1e30f, tm1 = -1e30f;
#pragma unroll
            for (int nt = 0; nt < 8; ++nt) {
                tm0 = fmaxf(tm0, fmaxf(S[mt][nt][0], S[mt][nt][1]));
                tm1 = fmaxf(tm1, fmaxf(S[mt][nt][2], S[mt][nt][3]));
            }
            tm0 = fmaxf(tm0, __shfl_xor_sync(~0u, tm0, 1));
            tm0 = fmaxf(tm0, __shfl_xor_sync(~0u, tm0, 2));
            tm1 = fmaxf(tm1, __shfl_xor_sync(~0u, tm1, 1));
            tm1 = fmaxf(tm1, __shfl_xor_sync(~0u, tm1, 2));
            float m0n = fmaxf(mrow[mt][0], tm0);
            float m1n = fmaxf(mrow[mt][1], tm1);
            float c0 = __expf(mrow[mt][0] - m0n);
            float c1 = __expf(mrow[mt][1] - m1n);
            mrow[mt][0] = m0n; mrow[mt][1] = m1n;
            float s0 = 0.f, s1 = 0.f;
#pragma unroll
            for (int nt = 0; nt < 8; ++nt) {
                float p0 = __expf(S[mt][nt][0] - m0n);
                float p1 = __expf(S[mt][nt][1] - m0n);
                float p2 = __expf(S[mt][nt][2] - m1n);
                float p3 = __expf(S[mt][nt][3] - m1n);
                s0 += p0 + p1; s1 += p2 + p3;
                const int col = nt * 8 + tq * 2;
                sP[(qb + g) * SK_LD + col] = p0;
                sP[(qb + g) * SK_LD + col + 1] = p1;
                sP[(qb + 8 + g) * SK_LD + col] = p2;
                sP[(qb + 8 + g) * SK_LD + col + 1] = p3;
            }
            s0 += __shfl_xor_sync(~0u, s0, 1);
            s0 += __shfl_xor_sync(~0u, s0, 2);
            s1 += __shfl_xor_sync(~0u, s1, 1);
            s1 += __shfl_xor_sync(~0u, s1, 2);
            lrow[mt][0] = lrow[mt][0] * c0 + s0;
            lrow[mt][1] = lrow[mt][1] * c1 + s1;
#pragma unroll
            for (int ntd = 0; ntd < 4; ++ntd) {
                O[mt][ntd][0] *= c0; O[mt][ntd][1] *= c0;
                O[mt][ntd][2] *= c1; O[mt][ntd][3] *= c1;
            }
        }
        __syncwarp();  // sP regions are per-warp

        // ---- O += P V ----
#pragma unroll
        for (int ks = 0; ks < 8; ++ks) {
            const int kb = ks * 8;
            uint32_t af[2][4];
#pragma unroll
            for (int mt = 0; mt < 2; ++mt) {
                const int qb = warp * 32 + mt * 16;
                af[mt][0] = f2tf(sP[(qb + g) * SK_LD + kb + tq]);
                af[mt][1] = f2tf(sP[(qb + 8 + g) * SK_LD + kb + tq]);
                af[mt][2] = f2tf(sP[(qb + g) * SK_LD + kb + tq + 4]);
                af[mt][3] = f2tf(sP[(qb + 8 + g) * SK_LD + kb + tq + 4]);
            }
#pragma unroll
            for (int ntd = 0; ntd < 4; ++ntd) {
                const int nb = ntd * 8;
                uint32_t b0 = f2tf(sV[(nb + g) * SK_LD + kb + tq]);
                uint32_t b1 = f2tf(sV[(nb + g) * SK_LD + kb + tq + 4]);
#pragma unroll
                for (int mt = 0; mt < 2; ++mt)
                    mma_tf32(O[mt][ntd], af[mt], b0, b1);
            }
        }
    }

    // ---- epilogue: normalize, stage O^T into sQ, coalesced write ----
    __syncthreads();
#pragma unroll
    for (int mt = 0; mt < 2; ++mt) {
        const int qb = warp * 32 + mt * 16;
        float rl0 = 1.f / lrow[mt][0];
        float rl1 = 1.f / lrow[mt][1];
#pragma unroll
        for (int ntd = 0; ntd < 4; ++ntd) {
            const int d0 = ntd * 8 + tq * 2;
            sQ[(d0) * SQ_LD + qb + g] = O[mt][ntd][0] * rl0;
            sQ[(d0 + 1) * SQ_LD + qb + g] = O[mt][ntd][1] * rl0;
            sQ[(d0) * SQ_LD + qb + 8 + g] = O[mt][ntd][2] * rl1;
            sQ[(d0 + 1) * SQ_LD + qb + 8 + g] = O[mt][ntd][3] * rl1;
        }
    }
    __syncthreads();
    for (int i = tid; i < 32 * 32; i += 128) {
        int d = i >> 5, q4 = (i & 31) << 2;
        float4 o = *(float4*)&sQ[d * SQ_LD + q4];
        float4 r = *(const float4*)&gridx[qbase + (size_t)d * P + q4];
        o.x += r.x; o.y += r.y; o.z += r.z; o.w += r.w;
        *(float4*)&out[qbase + (size_t)d * P + q4] = o;
    }
}

// ---------------- host launcher ----------------
static float* sym_addr(const void* s) {
    void* p = nullptr;
    cudaGetSymbolAddress(&p, s);
    return (float*)p;
}

extern "C" void kernel_launch(void* const* d_in, const int* in_sizes, int n_in,
                              void* d_out, int out_size) {
    const float* x        = (const float*)d_in[0];
    const float* norm_w   = (const float*)d_in[1];
    const float* norm_b   = (const float*)d_in[2];
    const float* qkv_w    = (const float*)d_in[3];
    const float* qkv_b    = (const float*)d_in[4];
    const float* proj_w   = (const float*)d_in[5];
    const float* proj_b   = (const float*)d_in[6];
    const float* gridnw   = (const float*)d_in[7];
    const float* gridnb   = (const float*)d_in[8];
    const float* pm_ln_w  = (const float*)d_in[9];
    const float* pm_ln_b  = (const float*)d_in[10];
    const float* pm_red_w = (const float*)d_in[11];
    const float* ds_nw    = (const float*)d_in[12];
    const float* ds_nb    = (const float*)d_in[13];
    const float* q_w      = (const float*)d_in[14];
    const float* q_b      = (const float*)d_in[15];
    const float* kv_w     = (const float*)d_in[16];
    const float* kv_b     = (const float*)d_in[17];
    float* out = (float*)d_out;

    float* xn    = sym_addr(g_xn);
    float* qkv   = sym_addr(g_qkv);
    float* gridx = sym_addr(g_gridx);
    float* mbuf  = sym_addr(g_m);
    float* pm    = sym_addr(g_pm);
    float* ds    = sym_addr(g_ds);
    float* qg    = sym_addr(g_qg);
    float* kvb   = sym_addr(g_kv);

    cudaFuncSetAttribute(win_attn_kernel,
                         cudaFuncAttributeMaxDynamicSharedMemorySize, WIN_SMEM);
    cudaFuncSetAttribute(glob_attn_mma_kernel,
                         cudaFuncAttributeMaxDynamicSharedMemorySize, GLOB_SMEM);

    dim3 gnGrid(64, BATCH);

    // ---- stage 1: GN(x) -> xn; qkv = conv1x1(xn) ----
    zero_stats_kernel<<<1, 32>>>();
    gn_stats_kernel<<<gnGrid, 256>>>(x, C * P);
    gn_apply_kernel<<<gnGrid, 256>>>(x, norm_w, norm_b, xn, P, C * P, EPS_GN);
    gemm_tf32_kernel<<<dim3(P / 128, 768 / 128, BATCH), 256>>>(qkv_w, xn, qkv_b, qkv, 768, P, C);

    // ---- stage 2: windowed attention + residual; GN -> grid_x ----
    win_attn_kernel<<<dim3(64, 4, BATCH), 128, WIN_SMEM>>>(qkv, x, gridx);
    zero_stats_kernel<<<1, 32>>>();
    gn_stats_kernel<<<gnGrid, 256>>>(gridx, C * P);
    gn_apply_kernel<<<gnGrid, 256>>>(gridx, gridnw, gridnb, gridx, P, C * P, EPS_GN);

    // ---- stage 3: patch merge + LN; pm reduction GEMM ----
    patch_merge_ln_kernel<<<dim3(P2, BATCH), 256>>>(gridx, pm_ln_w, pm_ln_b, mbuf);
    gemm_tf32_kernel<<<dim3(P2 / 128, C / 128, BATCH), 256>>>(pm_red_w, mbuf, nullptr, pm, C, P2, 4 * C);

    // ---- stage 4: GN(pm) -> ds; q/kv projections ----
    zero_stats_kernel<<<1, 32>>>();
    gn_stats_kernel<<<gnGrid, 256>>>(pm, C * P2);
    gn_apply_kernel<<<gnGrid, 256>>>(pm, ds_nw, ds_nb, ds, P2, C * P2, EPS_GN);
    gemm_tf32_kernel<<<dim3(P / 128, C / 128, BATCH), 256>>>(q_w, gridx, q_b, qg, C, P, C);
    gemm_tf32_kernel<<<dim3(P2 / 128, 512 / 128, BATCH), 256>>>(kv_w, ds, kv_b, kvb, 512, P2, C);

    // ---- stage 5: global attention + residual ----
    glob_attn_mma_kernel<<<dim3(P / 128, NH, BATCH), 128, GLOB_SMEM>>>(qg, kvb, gridx, xn);

    // ---- stage 6: proj ----
    gemm_tf32_kernel<<<dim3(P / 128, C / 128, BATCH), 256>>>(proj_w, xn, proj_b, out, C, P, C);
}

// round 4
// speedup vs baseline: 2.9112x; 1.0305x over previous
#include <cuda_runtime.h>
#include <math.h>
#include <stdint.h>

// ---------------- problem constants ----------------
constexpr int BATCH = 4;
constexpr int C = 256;
constexpr int H = 64, W = 64;
constexpr int P = H * W;              // 4096
constexpr int NH = 8, HD = 32;
constexpr int P2 = (H / 2) * (W / 2); // 1024
constexpr float SCALE = 0.1767766952966369f; // 32^-0.5
constexpr float EPS_GN = 1e-6f;
constexpr float EPS_LN = 1e-5f;

// ---------------- scratch (device globals) ----------
// stats slots: 0 = x (stage1), 1 = gridx (stage2), 2 = pm (stage4)
__device__ float g_stats[3][2 * BATCH];
__device__ float g_xn[BATCH * C * P];
__device__ float g_qkv[BATCH * 3 * C * P];
__device__ float g_gridx[BATCH * C * P];
__device__ float g_m[BATCH * 4 * C * P2];
__device__ float g_pm[BATCH * C * P2];
__device__ float g_ds[BATCH * C * P2];
__device__ float g_qg[BATCH * C * P];
__device__ float g_kv[BATCH * 2 * C * P2];

// ---------------- mma helpers ----------------
__device__ __forceinline__ uint32_t f2tf(float f) {
    uint32_t u;
    asm("cvt.rna.tf32.f32 %0, %1;" : "=r"(u) : "f"(f));
    return u;
}
__device__ __forceinline__ void mma_tf32(float* c, const uint32_t* a,
                                         uint32_t b0, uint32_t b1) {
    asm volatile(
        "mma.sync.aligned.m16n8k8.row.col.f32.tf32.tf32.f32 "
        "{%0,%1,%2,%3}, {%4,%5,%6,%7}, {%8,%9}, {%0,%1,%2,%3};"
        : "+f"(c[0]), "+f"(c[1]), "+f"(c[2]), "+f"(c[3])
        : "r"(a[0]), "r"(a[1]), "r"(a[2]), "r"(a[3]), "r"(b0), "r"(b1));
}

// ---------------- GroupNorm helpers ----------------
__global__ void zero_stats_kernel() {
    if (threadIdx.x < 3 * 2 * BATCH) ((float*)g_stats)[threadIdx.x] = 0.f;
}

__global__ void gn_stats_kernel(const float* __restrict__ x, int per_batch, int slot) {
    int b = blockIdx.y;
    const float* xb = x + (size_t)b * per_batch;
    float s = 0.f, ss = 0.f;
    for (int i = blockIdx.x * blockDim.x + threadIdx.x; i < per_batch;
         i += gridDim.x * blockDim.x) {
        float v = xb[i];
        s += v;
        ss = fmaf(v, v, ss);
    }
#pragma unroll
    for (int o = 16; o > 0; o >>= 1) {
        s += __shfl_xor_sync(~0u, s, o);
        ss += __shfl_xor_sync(~0u, ss, o);
    }
    __shared__ float red[2][8];
    int lane = threadIdx.x & 31, wp = threadIdx.x >> 5;
    if (lane == 0) { red[0][wp] = s; red[1][wp] = ss; }
    __syncthreads();
    if (threadIdx.x < 32) {
        float a = threadIdx.x < 8 ? red[0][threadIdx.x] : 0.f;
        float q = threadIdx.x < 8 ? red[1][threadIdx.x] : 0.f;
#pragma unroll
        for (int o = 4; o > 0; o >>= 1) {
            a += __shfl_xor_sync(~0u, a, o);
            q += __shfl_xor_sync(~0u, q, o);
        }
        if (threadIdx.x == 0) {
            atomicAdd(&g_stats[slot][2 * b], a);
            atomicAdd(&g_stats[slot][2 * b + 1], q);
        }
    }
}

__global__ void gn_apply_kernel(const float* __restrict__ x,
                                const float* __restrict__ w,
                                const float* __restrict__ bias,
                                float* __restrict__ out,
                                int hw, int per_batch, float eps, int slot) {
    int b = blockIdx.y;
    float cnt = (float)per_batch;
    float mean = g_stats[slot][2 * b] / cnt;
    float var = g_stats[slot][2 * b + 1] / cnt - mean * mean;
    float inv = rsqrtf(var + eps);
    const float* xb = x + (size_t)b * per_batch;
    float* ob = out + (size_t)b * per_batch;
    for (int i = blockIdx.x * blockDim.x + threadIdx.x; i < per_batch;
         i += gridDim.x * blockDim.x) {
        int c = i / hw;
        ob[i] = (xb[i] - mean) * inv * w[c] + bias[c];
    }
}

// ---------------- TF32 GEMM, pipelined ----------------
// C[b] = A[M,K] * B[b][K,N] (+bias[M]); 128x128 tile, 8 warps (2x4),
// warp tile 64x32, K-tile 16, register-prefetch double buffering,
// tf32 conversion once at smem-store time.
constexpr int GEMM_LDS = 136;
__global__ __launch_bounds__(256)
void gemm_tf32_kernel(const float* __restrict__ A,
                      const float* __restrict__ Bm,
                      const float* __restrict__ bias,
                      float* __restrict__ Cm,
                      int M, int N, int K) {
    const int b = blockIdx.z;
    Bm += (size_t)b * K * N;
    Cm += (size_t)b * M * N;
    __shared__ uint32_t As[2][16 * GEMM_LDS];
    __shared__ uint32_t Bs[2][16 * GEMM_LDS];
    const int tid = threadIdx.x;
    const int warp = tid >> 5, lane = tid & 31;
    const int wm = warp >> 2, wn = warp & 3;
    const int g = lane >> 2, tq = lane & 3;
    const int m0 = blockIdx.y * 128, n0 = blockIdx.x * 128;
    const int ar = tid >> 2;
    const int ac = (tid & 3) << 2;
    const int br = tid >> 5;
    const int bc = lane << 2;

    const float* Aplo = &A[(size_t)(m0 + ar) * K + ac];
    const float* Aphi = &A[(size_t)(m0 + ar + 64) * K + ac];
    const float* Bplo = &Bm[(size_t)br * N + n0 + bc];
    const float* Bphi = &Bm[(size_t)(br + 8) * N + n0 + bc];

    float4 a0v, a1v, b0v, b1v;
    a0v = *(const float4*)Aplo;
    a1v = *(const float4*)Aphi;
    b0v = *(const float4*)Bplo;
    b1v = *(const float4*)Bphi;

    float acc[4][4][4] = {};
    const int ntile = K >> 4;
#pragma unroll 1
    for (int i = 0; i < ntile; ++i) {
        const int cur = i & 1;
        // store prefetched regs (tile i) into smem[cur], converting to tf32
        uint32_t* as = As[cur];
        uint32_t* bs = Bs[cur];
        as[(ac + 0) * GEMM_LDS + ar] = f2tf(a0v.x);
        as[(ac + 1) * GEMM_LDS + ar] = f2tf(a0v.y);
        as[(ac + 2) * GEMM_LDS + ar] = f2tf(a0v.z);
        as[(ac + 3) * GEMM_LDS + ar] = f2tf(a0v.w);
        as[(ac + 0) * GEMM_LDS + ar + 64] = f2tf(a1v.x);
        as[(ac + 1) * GEMM_LDS + ar + 64] = f2tf(a1v.y);
        as[(ac + 2) * GEMM_LDS + ar + 64] = f2tf(a1v.z);
        as[(ac + 3) * GEMM_LDS + ar + 64] = f2tf(a1v.w);
        uint4 bu0 = {f2tf(b0v.x), f2tf(b0v.y), f2tf(b0v.z), f2tf(b0v.w)};
        uint4 bu1 = {f2tf(b1v.x), f2tf(b1v.y), f2tf(b1v.z), f2tf(b1v.w)};
        *(uint4*)&bs[br * GEMM_LDS + bc] = bu0;
        *(uint4*)&bs[(br + 8) * GEMM_LDS + bc] = bu1;
        __syncthreads();
        // prefetch tile i+1 (global loads in flight during compute)
        if (i + 1 < ntile) {
            const int k1 = (i + 1) << 4;
            a0v = *(const float4*)(Aplo + k1);
            a1v = *(const float4*)(Aphi + k1);
            b0v = *(const float4*)(Bplo + (size_t)k1 * N);
            b1v = *(const float4*)(Bphi + (size_t)k1 * N);
        }
#pragma unroll
        for (int ks = 0; ks < 2; ++ks) {
            const int kb = ks * 8;
            uint32_t af[4][4];
            uint32_t bf[4][2];
#pragma unroll
            for (int mt = 0; mt < 4; ++mt) {
                const int mb = wm * 64 + mt * 16;
                af[mt][0] = as[(kb + tq) * GEMM_LDS + mb + g];
                af[mt][1] = as[(kb + tq) * GEMM_LDS + mb + 8 + g];
                af[mt][2] = as[(kb + tq + 4) * GEMM_LDS + mb + g];
                af[mt][3] = as[(kb + tq + 4) * GEMM_LDS + mb + 8 + g];
            }
#pragma unroll
            for (int nt = 0; nt < 4; ++nt) {
                const int nb = wn * 32 + nt * 8;
                bf[nt][0] = bs[(kb + tq) * GEMM_LDS + nb + g];
                bf[nt][1] = bs[(kb + tq + 4) * GEMM_LDS + nb + g];
            }
#pragma unroll
            for (int mt = 0; mt < 4; ++mt)
#pragma unroll
                for (int nt = 0; nt < 4; ++nt)
                    mma_tf32(acc[mt][nt], af[mt], bf[nt][0], bf[nt][1]);
        }
        __syncthreads();
    }
#pragma unroll
    for (int mt = 0; mt < 4; ++mt) {
#pragma unroll
        for (int nt = 0; nt < 4; ++nt) {
            int row = m0 + wm * 64 + mt * 16 + g;
            int col = n0 + wn * 32 + nt * 8 + tq * 2;
            float bv0 = bias ? bias[row] : 0.f;
            float bv1 = bias ? bias[row + 8] : 0.f;
            float2 o0 = {acc[mt][nt][0] + bv0, acc[mt][nt][1] + bv0};
            float2 o1 = {acc[mt][nt][2] + bv1, acc[mt][nt][3] + bv1};
            *(float2*)&Cm[(size_t)row * N + col] = o0;
            *(float2*)&Cm[(size_t)(row + 8) * N + col] = o1;
        }
    }
}

// ---------------- windowed 8x8 attention + fused GN stats ----------------
constexpr int WIN_SMEM = (2 * 32 * 64 * 2 + 128 * 65) * 4;
__global__ __launch_bounds__(128)
void win_attn_kernel(const float* __restrict__ qkv,
                     const float* __restrict__ x,
                     float* __restrict__ out) {
    extern __shared__ float sm[];
    float* wk = sm;
    float* wv = sm + 2 * 32 * 64;
    float* sc = sm + 4 * 32 * 64;

    const int win = blockIdx.x;
    const int gi = win >> 3, gj = win & 7;
    const int hp = blockIdx.y;
    const int b = blockIdx.z;
    const int tid = threadIdx.x;
    const int hl = tid >> 6, t = tid & 63;
    const int h = hp * 2 + hl;

    for (int idx = tid; idx < 8192; idx += 128) {
        int token = idx & 63;
        int d = (idx >> 6) & 31;
        int tsel = (idx >> 11) & 1;
        int hh = idx >> 12;
        int ch = (tsel ? 512 : 256) + (hp * 2 + hh) * 32 + d;
        int si = token >> 3, sj = token & 7;
        int sp = (gi * 8 + si) * W + gj * 8 + sj;
        float val = qkv[((size_t)b * 768 + ch) * (size_t)P + sp];
        (tsel ? wv : wk)[hh * 2048 + d * 64 + token] = val;
    }
    __syncthreads();

    const int si = t >> 3, sj = t & 7;
    const int sp = (gi * 8 + si) * W + gj * 8 + sj;
    float q[32];
    size_t qb = ((size_t)b * 768 + h * 32) * (size_t)P + sp;
#pragma unroll
    for (int d = 0; d < 32; ++d) q[d] = qkv[qb + (size_t)d * P] * SCALE;

    const float* kh = wk + hl * 2048;
    const float* vh = wv + hl * 2048;
    float* myc = sc + tid * 65;

    float mx = -1e30f;
    for (int j = 0; j < 64; ++j) {
        float s = 0.f;
#pragma unroll
        for (int d = 0; d < 32; ++d) s = fmaf(q[d], kh[d * 64 + j], s);
        myc[j] = s;
        mx = fmaxf(mx, s);
    }
    float l = 0.f;
    for (int j = 0; j < 64; ++j) {
        float p_ = __expf(myc[j] - mx);
        myc[j] = p_;
        l += p_;
    }
    float rl = 1.f / l;

    float acc[32];
#pragma unroll
    for (int d = 0; d < 32; ++d) acc[d] = 0.f;
    for (int j = 0; j < 64; ++j) {
        float p_ = myc[j];
#pragma unroll
        for (int d = 0; d < 32; ++d) acc[d] = fmaf(p_, vh[d * 64 + j], acc[d]);
    }

    size_t ob = ((size_t)b * 256 + h * 32) * (size_t)P + sp;
    float s = 0.f, ss = 0.f;
#pragma unroll
    for (int d = 0; d < 32; ++d) {
        float v = x[ob + (size_t)d * P] + acc[d] * rl;
        out[ob + (size_t)d * P] = v;
        s += v;
        ss = fmaf(v, v, ss);
    }
    // fused GN stats (slot 1) for gridx
#pragma unroll
    for (int o = 16; o > 0; o >>= 1) {
        s += __shfl_xor_sync(~0u, s, o);
        ss += __shfl_xor_sync(~0u, ss, o);
    }
    __shared__ float red[2][4];
    int lane = tid & 31, wp = tid >> 5;
    if (lane == 0) { red[0][wp] = s; red[1][wp] = ss; }
    __syncthreads();
    if (tid == 0) {
        float a = red[0][0] + red[0][1] + red[0][2] + red[0][3];
        float qq = red[1][0] + red[1][1] + red[1][2] + red[1][3];
        atomicAdd(&g_stats[1][2 * b], a);
        atomicAdd(&g_stats[1][2 * b + 1], qq);
    }
}

// ---------------- patch merge + LayerNorm ----------------
__global__ void patch_merge_ln_kernel(const float* __restrict__ gx,
                                      const float* __restrict__ lnw,
                                      const float* __restrict__ lnb,
                                      float* __restrict__ m_out) {
    int b = blockIdx.y;
    int p2 = blockIdx.x;
    int i = p2 >> 5, j = p2 & 31;
    int c = threadIdx.x;
    size_t base = ((size_t)b * 256 + c) * (size_t)P;
    int sp00 = (2 * i) * W + 2 * j;
    float v0 = gx[base + sp00];
    float v1 = gx[base + sp00 + W];
    float v2 = gx[base + sp00 + 1];
    float v3 = gx[base + sp00 + W + 1];

    float s = v0 + v1 + v2 + v3;
    float ss = v0 * v0 + v1 * v1 + v2 * v2 + v3 * v3;
#pragma unroll
    for (int o = 16; o > 0; o >>= 1) {
        s += __shfl_xor_sync(~0u, s, o);
        ss += __shfl_xor_sync(~0u, ss, o);
    }
    __shared__ float red[2][8];
    int lane = threadIdx.x & 31, wp = threadIdx.x >> 5;
    if (lane == 0) { red[0][wp] = s; red[1][wp] = ss; }
    __syncthreads();
    if (threadIdx.x < 32) {
        float a = threadIdx.x < 8 ? red[0][threadIdx.x] : 0.f;
        float q = threadIdx.x < 8 ? red[1][threadIdx.x] : 0.f;
#pragma unroll
        for (int o = 4; o > 0; o >>= 1) {
            a += __shfl_xor_sync(~0u, a, o);
            q += __shfl_xor_sync(~0u, q, o);
        }
        if (threadIdx.x == 0) { red[0][0] = a; red[1][0] = q; }
    }
    __syncthreads();
    float mean = red[0][0] * (1.f / 1024.f);
    float var = red[1][0] * (1.f / 1024.f) - mean * mean;
    float inv = rsqrtf(var + EPS_LN);

    size_t ob = (size_t)b * 1024 * (size_t)P2 + p2;
    m_out[ob + (size_t)(0 * 256 + c) * P2] = (v0 - mean) * inv * lnw[0 * 256 + c] + lnb[0 * 256 + c];
    m_out[ob + (size_t)(1 * 256 + c) * P2] = (v1 - mean) * inv * lnw[1 * 256 + c] + lnb[1 * 256 + c];
    m_out[ob + (size_t)(2 * 256 + c) * P2] = (v2 - mean) * inv * lnw[2 * 256 + c] + lnb[2 * 256 + c];
    m_out[ob + (size_t)(3 * 256 + c) * P2] = (v3 - mean) * inv * lnw[3 * 256 + c] + lnb[3 * 256 + c];
}

// ---------------- global attention: flash-style TF32 mma ----------------
// tf32 bits stored in smem for K/V/P (convert once at store).
constexpr int SQ_LD = 136;
constexpr int SK_LD = 72;
constexpr int GLOB_SMEM = (32 * SQ_LD + 2 * 32 * SK_LD + 128 * SK_LD) * 4;
__global__ __launch_bounds__(128, 2)
void glob_attn_mma_kernel(const float* __restrict__ qg,
                          const float* __restrict__ kv,
                          const float* __restrict__ gridx,
                          float* __restrict__ out) {
    extern __shared__ float sm[];
    float* sQ = sm;                                    // [32][136] floats
    uint32_t* sK = (uint32_t*)(sm + 32 * SQ_LD);       // [32][72] tf32
    uint32_t* sV = sK + 32 * SK_LD;                    // [32][72] tf32
    uint32_t* sP = sV + 32 * SK_LD;                    // [128][72] tf32

    const int b = blockIdx.z, h = blockIdx.y;
    const int q0 = blockIdx.x * 128;
    const int tid = threadIdx.x, warp = tid >> 5, lane = tid & 31;
    const int g = lane >> 2, tq = lane & 3;

    const size_t qbase = ((size_t)b * 256 + h * 32) * (size_t)P + q0;
    for (int i = tid; i < 32 * 32; i += 128) {
        int d = i >> 5, q4 = (i & 31) << 2;
        float4 v = *(const float4*)&qg[qbase + (size_t)d * P + q4];
        v.x *= SCALE; v.y *= SCALE; v.z *= SCALE; v.w *= SCALE;
        *(float4*)&sQ[d * SQ_LD + q4] = v;
    }
    __syncthreads();

    uint32_t qf[2][4][4];
#pragma unroll
    for (int mt = 0; mt < 2; ++mt) {
        const int qb = warp * 32 + mt * 16;
#pragma unroll
        for (int ks = 0; ks < 4; ++ks) {
            const int kb = ks * 8;
            qf[mt][ks][0] = f2tf(sQ[(kb + tq) * SQ_LD + qb + g]);
            qf[mt][ks][1] = f2tf(sQ[(kb + tq) * SQ_LD + qb + 8 + g]);
            qf[mt][ks][2] = f2tf(sQ[(kb + tq + 4) * SQ_LD + qb + g]);
            qf[mt][ks][3] = f2tf(sQ[(kb + tq + 4) * SQ_LD + qb + 8 + g]);
        }
    }

    float O[2][4][4] = {};
    float mrow[2][2], lrow[2][2];
#pragma unroll
    for (int mt = 0; mt < 2; ++mt) {
        mrow[mt][0] = mrow[mt][1] = -1e30f;
        lrow[mt][0] = lrow[mt][1] = 0.f;
    }

    const size_t kbase = ((size_t)b * 512 + h * 32) * (size_t)P2;
    const size_t vbase = kbase + (size_t)256 * P2;

    for (int t = 0; t < P2; t += 64) {
        __syncthreads();
        for (int i = tid; i < 32 * 16; i += 128) {
            int d = i >> 4, c4 = (i & 15) << 2;
            float4 kk = *(const float4*)&kv[kbase + (size_t)d * P2 + t + c4];
            float4 vv = *(const float4*)&kv[vbase + (size_t)d * P2 + t + c4];
            uint4 ku = {f2tf(kk.x), f2tf(kk.y), f2tf(kk.z), f2tf(kk.w)};
            uint4 vu = {f2tf(vv.x), f2tf(vv.y), f2tf(vv.z), f2tf(vv.w)};
            *(uint4*)&sK[d * SK_LD + c4] = ku;
            *(uint4*)&sV[d * SK_LD + c4] = vu;
        }
        __syncthreads();

        float S[2][8][4];
#pragma unroll
        for (int nt = 0; nt < 8; ++nt) {
            const int nb = nt * 8;
            uint32_t b0[4], b1[4];
#pragma unroll
            for (int ks = 0; ks < 4; ++ks) {
                const int kb = ks * 8;
                b0[ks] = sK[(kb + tq) * SK_LD + nb + g];
                b1[ks] = sK[(kb + tq + 4) * SK_LD + nb + g];
            }
#pragma unroll
            for (int mt = 0; mt < 2; ++mt) {
                S[mt][nt][0] = S[mt][nt][1] = S[mt][nt][2] = S[mt][nt][3] = 0.f;
#pragma unroll
                for (int ks = 0; ks < 4; ++ks)
                    mma_tf32(S[mt][nt], qf[mt][ks], b0[ks], b1[ks]);
            }
        }

#pragma unroll
        for (int mt = 0; mt < 2; ++mt) {
            const int qb = warp * 32 + mt * 16;
            float tm0 = -1e30f, tm1 = -1e30f;
#pragma unroll
            for (int nt = 0; nt < 8; ++nt) {
                tm0 = fmaxf(tm0, fmaxf(S[mt][nt][0], S[mt][nt][1]));
                tm1 = fmaxf(tm1, fmaxf(S[mt][nt][2], S[mt][nt][3]));
            }
            tm0 = fmaxf(tm0, __shfl_xor_sync(~0u, tm0, 1));
            tm0 = fmaxf(tm0, __shfl_xor_sync(~0u, tm0, 2));
            tm1 = fmaxf(tm1, __shfl_xor_sync(~0u, tm1, 1));
            tm1 = fmaxf(tm1, __shfl_xor_sync(~0u, tm1, 2));
            float m0n = fmaxf(mrow[mt][0], tm0);
            float m1n = fmaxf(mrow[mt][1], tm1);
            float c0 = __expf(mrow[mt][0] - m0n);
            float c1 = __expf(mrow[mt][1] - m1n);
            mrow[mt][0] = m0n; mrow[mt][1] = m1n;
            float s0 = 0.f, s1 = 0.f;
#pragma unroll
            for (int nt = 0; nt < 8; ++nt) {
                float p0 = __expf(S[mt][nt][0] - m0n);
                float p1 = __expf(S[mt][nt][1] - m0n);
                float p2 = __expf(S[mt][nt][2] - m1n);
                float p3 = __expf(S[mt][nt][3] - m1n);
                s0 += p0 + p1; s1 += p2 + p3;
                const int col = nt * 8 + tq * 2;
                sP[(qb + g) * SK_LD + col] = f2tf(p0);
                sP[(qb + g) * SK_LD + col + 1] = f2tf(p1);
                sP[(qb + 8 + g) * SK_LD + col] = f2tf(p2);
                sP[(qb + 8 + g) * SK_LD + col + 1] = f2tf(p3);
            }
            s0 += __shfl_xor_sync(~0u, s0, 1);
            s0 += __shfl_xor_sync(~0u, s0, 2);
            s1 += __shfl_xor_sync(~0u, s1, 1);
            s1 += __shfl_xor_sync(~0u, s1, 2);
            lrow[mt][0] = lrow[mt][0] * c0 + s0;
            lrow[mt][1] = lrow[mt][1] * c1 + s1;
#pragma unroll
            for (int ntd = 0; ntd < 4; ++ntd) {
                O[mt][ntd][0] *= c0; O[mt][ntd][1] *= c0;
                O[mt][ntd][2] *= c1; O[mt][ntd][3] *= c1;
            }
        }
        __syncwarp();

#pragma unroll
        for (int ks = 0; ks < 8; ++ks) {
            const int kb = ks * 8;
            uint32_t af[2][4];
#pragma unroll
            for (int mt = 0; mt < 2; ++mt) {
                const int qb = warp * 32 + mt * 16;
                af[mt][0] = sP[(qb + g) * SK_LD + kb + tq];
                af[mt][1] = sP[(qb + 8 + g) * SK_LD + kb + tq];
                af[mt][2] = sP[(qb + g) * SK_LD + kb + tq + 4];
                af[mt][3] = sP[(qb + 8 + g) * SK_LD + kb + tq + 4];
            }
#pragma unroll
            for (int ntd = 0; ntd < 4; ++ntd) {
                const int nb = ntd * 8;
                uint32_t b0 = sV[(nb + g) * SK_LD + kb + tq];
                uint32_t b1 = sV[(nb + g) * SK_LD + kb + tq + 4];
#pragma unroll
                for (int mt = 0; mt < 2; ++mt)
                    mma_tf32(O[mt][ntd], af[mt], b0, b1);
            }
        }
    }

    __syncthreads();
#pragma unroll
    for (int mt = 0; mt < 2; ++mt) {
        const int qb = warp * 32 + mt * 16;
        float rl0 = 1.f / lrow[mt][0];
        float rl1 = 1.f / lrow[mt][1];
#pragma unroll
        for (int ntd = 0; ntd < 4; ++ntd) {
            const int d0 = ntd * 8 + tq * 2;
            sQ[(d0) * SQ_LD + qb + g] = O[mt][ntd][0] * rl0;
            sQ[(d0 + 1) * SQ_LD + qb + g] = O[mt][ntd][1] * rl0;
            sQ[(d0) * SQ_LD + qb + 8 + g] = O[mt][ntd][2] * rl1;
            sQ[(d0 + 1) * SQ_LD + qb + 8 + g] = O[mt][ntd][3] * rl1;
        }
    }
    __syncthreads();
    for (int i = tid; i < 32 * 32; i += 128) {
        int d = i >> 5, q4 = (i & 31) << 2;
        float4 o = *(float4*)&sQ[d * SQ_LD + q4];
        float4 r = *(const float4*)&gridx[qbase + (size_t)d * P + q4];
        o.x += r.x; o.y += r.y; o.z += r.z; o.w += r.w;
        *(float4*)&out[qbase + (size_t)d * P + q4] = o;
    }
}

// ---------------- host launcher ----------------
static float* sym_addr(const void* s) {
    void* p = nullptr;
    cudaGetSymbolAddress(&p, s);
    return (float*)p;
}

extern "C" void kernel_launch(void* const* d_in, const int* in_sizes, int n_in,
                              void* d_out, int out_size) {
    const float* x        = (const float*)d_in[0];
    const float* norm_w   = (const float*)d_in[1];
    const float* norm_b   = (const float*)d_in[2];
    const float* qkv_w    = (const float*)d_in[3];
    const float* qkv_b    = (const float*)d_in[4];
    const float* proj_w   = (const float*)d_in[5];
    const float* proj_b   = (const float*)d_in[6];
    const float* gridnw   = (const float*)d_in[7];
    const float* gridnb   = (const float*)d_in[8];
    const float* pm_ln_w  = (const float*)d_in[9];
    const float* pm_ln_b  = (const float*)d_in[10];
    const float* pm_red_w = (const float*)d_in[11];
    const float* ds_nw    = (const float*)d_in[12];
    const float* ds_nb    = (const float*)d_in[13];
    const float* q_w      = (const float*)d_in[14];
    const float* q_b      = (const float*)d_in[15];
    const float* kv_w     = (const float*)d_in[16];
    const float* kv_b     = (const float*)d_in[17];
    float* out = (float*)d_out;

    float* xn    = sym_addr(g_xn);
    float* qkv   = sym_addr(g_qkv);
    float* gridx = sym_addr(g_gridx);
    float* mbuf  = sym_addr(g_m);
    float* pm    = sym_addr(g_pm);
    float* ds    = sym_addr(g_ds);
    float* qg    = sym_addr(g_qg);
    float* kvb   = sym_addr(g_kv);

    cudaFuncSetAttribute(win_attn_kernel,
                         cudaFuncAttributeMaxDynamicSharedMemorySize, WIN_SMEM);
    cudaFuncSetAttribute(glob_attn_mma_kernel,
                         cudaFuncAttributeMaxDynamicSharedMemorySize, GLOB_SMEM);

    dim3 gnGrid(64, BATCH);

    // ---- zero all stat slots once ----
    zero_stats_kernel<<<1, 32>>>();

    // ---- stage 1: GN(x) -> xn; qkv = conv1x1(xn) ----
    gn_stats_kernel<<<gnGrid, 256>>>(x, C * P, 0);
    gn_apply_kernel<<<gnGrid, 256>>>(x, norm_w, norm_b, xn, P, C * P, EPS_GN, 0);
    gemm_tf32_kernel<<<dim3(P / 128, 768 / 128, BATCH), 256>>>(qkv_w, xn, qkv_b, qkv, 768, P, C);

    // ---- stage 2: windowed attention + residual (stats fused); GN -> grid_x ----
    win_attn_kernel<<<dim3(64, 4, BATCH), 128, WIN_SMEM>>>(qkv, x, gridx);
    gn_apply_kernel<<<gnGrid, 256>>>(gridx, gridnw, gridnb, gridx, P, C * P, EPS_GN, 1);

    // ---- stage 3: patch merge + LN; pm reduction GEMM ----
    patch_merge_ln_kernel<<<dim3(P2, BATCH), 256>>>(gridx, pm_ln_w, pm_ln_b, mbuf);
    gemm_tf32_kernel<<<dim3(P2 / 128, C / 128, BATCH), 256>>>(pm_red_w, mbuf, nullptr, pm, C, P2, 4 * C);

    // ---- stage 4: GN(pm) -> ds; q/kv projections ----
    gn_stats_kernel<<<gnGrid, 256>>>(pm, C * P2, 2);
    gn_apply_kernel<<<gnGrid, 256>>>(pm, ds_nw, ds_nb, ds, P2, C * P2, EPS_GN, 2);
    gemm_tf32_kernel<<<dim3(P / 128, C / 128, BATCH), 256>>>(q_w, gridx, q_b, qg, C, P, C);
    gemm_tf32_kernel<<<dim3(P2 / 128, 512 / 128, BATCH), 256>>>(kv_w, ds, kv_b, kvb, 512, P2, C);

    // ---- stage 5: global attention + residual ----
    glob_attn_mma_kernel<<<dim3(P / 128, NH, BATCH), 128, GLOB_SMEM>>>(qg, kvb, gridx, xn);

    // ---- stage 6: proj ----
    gemm_tf32_kernel<<<dim3(P / 128, C / 128, BATCH), 256>>>(proj_w, xn, proj_b, out, C, P, C);
}

// round 5
// speedup vs baseline: 3.3289x; 1.1435x over previous
#include <cuda_runtime.h>
#include <math.h>
#include <stdint.h>

// ---------------- problem constants ----------------
constexpr int BATCH = 4;
constexpr int C = 256;
constexpr int H = 64, W = 64;
constexpr int P = H * W;              // 4096
constexpr int NH = 8, HD = 32;
constexpr int P2 = (H / 2) * (W / 2); // 1024
constexpr float SCALE = 0.1767766952966369f; // 32^-0.5
constexpr float EPS_GN = 1e-6f;
constexpr float EPS_LN = 1e-5f;

// ---------------- scratch (device globals) ----------
// stats slots: 0 = x (stage1), 1 = gridx (stage2), 2 = pm (stage4)
__device__ float g_stats[3][2 * BATCH];
__device__ float g_xn[BATCH * C * P];     // global_x scratch
__device__ float g_qkv[BATCH * 3 * C * P];
__device__ float g_gridx[BATCH * C * P];
__device__ float g_m[BATCH * 4 * C * P2];
__device__ float g_pm[BATCH * C * P2];
__device__ float g_qg[BATCH * C * P];
__device__ float g_kv[BATCH * 2 * C * P2];

// ---------------- mma helpers ----------------
__device__ __forceinline__ uint32_t f2tf(float f) {
    uint32_t u;
    asm("cvt.rna.tf32.f32 %0, %1;" : "=r"(u) : "f"(f));
    return u;
}
__device__ __forceinline__ void mma_tf32(float* c, const uint32_t* a,
                                         uint32_t b0, uint32_t b1) {
    asm volatile(
        "mma.sync.aligned.m16n8k8.row.col.f32.tf32.tf32.f32 "
        "{%0,%1,%2,%3}, {%4,%5,%6,%7}, {%8,%9}, {%0,%1,%2,%3};"
        : "+f"(c[0]), "+f"(c[1]), "+f"(c[2]), "+f"(c[3])
        : "r"(a[0]), "r"(a[1]), "r"(a[2]), "r"(a[3]), "r"(b0), "r"(b1));
}

// ---------------- GroupNorm helpers ----------------
__global__ void zero_stats_kernel() {
    if (threadIdx.x < 3 * 2 * BATCH) ((float*)g_stats)[threadIdx.x] = 0.f;
}

__global__ void gn_stats_kernel(const float* __restrict__ x, int per_batch, int slot) {
    int b = blockIdx.y;
    const float* xb = x + (size_t)b * per_batch;
    float s = 0.f, ss = 0.f;
    for (int i = blockIdx.x * blockDim.x + threadIdx.x; i < per_batch;
         i += gridDim.x * blockDim.x) {
        float v = xb[i];
        s += v;
        ss = fmaf(v, v, ss);
    }
#pragma unroll
    for (int o = 16; o > 0; o >>= 1) {
        s += __shfl_xor_sync(~0u, s, o);
        ss += __shfl_xor_sync(~0u, ss, o);
    }
    __shared__ float red[2][8];
    int lane = threadIdx.x & 31, wp = threadIdx.x >> 5;
    if (lane == 0) { red[0][wp] = s; red[1][wp] = ss; }
    __syncthreads();
    if (threadIdx.x < 32) {
        float a = threadIdx.x < 8 ? red[0][threadIdx.x] : 0.f;
        float q = threadIdx.x < 8 ? red[1][threadIdx.x] : 0.f;
#pragma unroll
        for (int o = 4; o > 0; o >>= 1) {
            a += __shfl_xor_sync(~0u, a, o);
            q += __shfl_xor_sync(~0u, q, o);
        }
        if (threadIdx.x == 0) {
            atomicAdd(&g_stats[slot][2 * b], a);
            atomicAdd(&g_stats[slot][2 * b + 1], q);
        }
    }
}

__global__ void gn_apply_kernel(const float* __restrict__ x,
                                const float* __restrict__ w,
                                const float* __restrict__ bias,
                                float* __restrict__ out,
                                int hw, int per_batch, float eps, int slot) {
    int b = blockIdx.y;
    float cnt = (float)per_batch;
    float mean = g_stats[slot][2 * b] / cnt;
    float var = g_stats[slot][2 * b + 1] / cnt - mean * mean;
    float inv = rsqrtf(var + eps);
    const float* xb = x + (size_t)b * per_batch;
    float* ob = out + (size_t)b * per_batch;
    for (int i = blockIdx.x * blockDim.x + threadIdx.x; i < per_batch;
         i += gridDim.x * blockDim.x) {
        int c = i / hw;
        ob[i] = (xb[i] - mean) * inv * w[c] + bias[c];
    }
}

// ---------------- TF32 GEMM (single buffer, reg prefetch, fused GN on B) ----
// C[b] = A[M,K] * GN(B[b])[K,N] (+bias[M]); 128x128 tile, 8 warps, K-tile 16.
// If gnw != nullptr, B rows get y = x*alpha[k] + beta[k] from stats slot.
constexpr int GEMM_LDS = 136;
__global__ __launch_bounds__(256, 2)
void gemm_tf32_kernel(const float* __restrict__ A,
                      const float* __restrict__ Bm,
                      const float* __restrict__ bias,
                      float* __restrict__ Cm,
                      int M, int N, int K,
                      const float* __restrict__ gnw,
                      const float* __restrict__ gnb,
                      int slot) {
    const int b = blockIdx.z;
    Bm += (size_t)b * K * N;
    Cm += (size_t)b * M * N;
    __shared__ uint32_t As[16 * GEMM_LDS];
    __shared__ uint32_t Bs[16 * GEMM_LDS];
    const int tid = threadIdx.x;
    const int warp = tid >> 5, lane = tid & 31;
    const int wm = warp >> 2, wn = warp & 3;
    const int g = lane >> 2, tq = lane & 3;
    const int m0 = blockIdx.y * 128, n0 = blockIdx.x * 128;
    const int ar = tid >> 2;
    const int ac = (tid & 3) << 2;
    const int br = tid >> 5;
    const int bc = lane << 2;

    float mean = 0.f, inv = 0.f;
    if (gnw) {
        float cnt = (float)K * (float)N;
        mean = g_stats[slot][2 * b] / cnt;
        float var = g_stats[slot][2 * b + 1] / cnt - mean * mean;
        inv = rsqrtf(var + EPS_GN);
    }

    const float* Aplo = &A[(size_t)(m0 + ar) * K + ac];
    const float* Aphi = &A[(size_t)(m0 + ar + 64) * K + ac];
    const float* Bplo = &Bm[(size_t)br * N + n0 + bc];
    const float* Bphi = &Bm[(size_t)(br + 8) * N + n0 + bc];

    float4 a0v = *(const float4*)Aplo;
    float4 a1v = *(const float4*)Aphi;
    float4 b0v = *(const float4*)Bplo;
    float4 b1v = *(const float4*)Bphi;

    float acc[4][4][4] = {};
    const int ntile = K >> 4;
#pragma unroll 1
    for (int i = 0; i < ntile; ++i) {
        __syncthreads();  // consumers of previous tile done
        As[(ac + 0) * GEMM_LDS + ar] = f2tf(a0v.x);
        As[(ac + 1) * GEMM_LDS + ar] = f2tf(a0v.y);
        As[(ac + 2) * GEMM_LDS + ar] = f2tf(a0v.z);
        As[(ac + 3) * GEMM_LDS + ar] = f2tf(a0v.w);
        As[(ac + 0) * GEMM_LDS + ar + 64] = f2tf(a1v.x);
        As[(ac + 1) * GEMM_LDS + ar + 64] = f2tf(a1v.y);
        As[(ac + 2) * GEMM_LDS + ar + 64] = f2tf(a1v.z);
        As[(ac + 3) * GEMM_LDS + ar + 64] = f2tf(a1v.w);
        if (gnw) {
            int k0r = i * 16 + br;
            float al0 = inv * gnw[k0r], be0 = gnb[k0r] - mean * al0;
            float al1 = inv * gnw[k0r + 8], be1 = gnb[k0r + 8] - mean * al1;
            uint4 bu0 = {f2tf(fmaf(b0v.x, al0, be0)), f2tf(fmaf(b0v.y, al0, be0)),
                         f2tf(fmaf(b0v.z, al0, be0)), f2tf(fmaf(b0v.w, al0, be0))};
            uint4 bu1 = {f2tf(fmaf(b1v.x, al1, be1)), f2tf(fmaf(b1v.y, al1, be1)),
                         f2tf(fmaf(b1v.z, al1, be1)), f2tf(fmaf(b1v.w, al1, be1))};
            *(uint4*)&Bs[br * GEMM_LDS + bc] = bu0;
            *(uint4*)&Bs[(br + 8) * GEMM_LDS + bc] = bu1;
        } else {
            uint4 bu0 = {f2tf(b0v.x), f2tf(b0v.y), f2tf(b0v.z), f2tf(b0v.w)};
            uint4 bu1 = {f2tf(b1v.x), f2tf(b1v.y), f2tf(b1v.z), f2tf(b1v.w)};
            *(uint4*)&Bs[br * GEMM_LDS + bc] = bu0;
            *(uint4*)&Bs[(br + 8) * GEMM_LDS + bc] = bu1;
        }
        __syncthreads();
        if (i + 1 < ntile) {
            const int k1 = (i + 1) << 4;
            a0v = *(const float4*)(Aplo + k1);
            a1v = *(const float4*)(Aphi + k1);
            b0v = *(const float4*)(Bplo + (size_t)k1 * N);
            b1v = *(const float4*)(Bphi + (size_t)k1 * N);
        }
#pragma unroll
        for (int ks = 0; ks < 2; ++ks) {
            const int kb = ks * 8;
            uint32_t af[4][4];
            uint32_t bf[4][2];
#pragma unroll
            for (int mt = 0; mt < 4; ++mt) {
                const int mb = wm * 64 + mt * 16;
                af[mt][0] = As[(kb + tq) * GEMM_LDS + mb + g];
                af[mt][1] = As[(kb + tq) * GEMM_LDS + mb + 8 + g];
                af[mt][2] = As[(kb + tq + 4) * GEMM_LDS + mb + g];
                af[mt][3] = As[(kb + tq + 4) * GEMM_LDS + mb + 8 + g];
            }
#pragma unroll
            for (int nt = 0; nt < 4; ++nt) {
                const int nb = wn * 32 + nt * 8;
                bf[nt][0] = Bs[(kb + tq) * GEMM_LDS + nb + g];
                bf[nt][1] = Bs[(kb + tq + 4) * GEMM_LDS + nb + g];
            }
#pragma unroll
            for (int mt = 0; mt < 4; ++mt)
#pragma unroll
                for (int nt = 0; nt < 4; ++nt)
                    mma_tf32(acc[mt][nt], af[mt], bf[nt][0], bf[nt][1]);
        }
    }
#pragma unroll
    for (int mt = 0; mt < 4; ++mt) {
#pragma unroll
        for (int nt = 0; nt < 4; ++nt) {
            int row = m0 + wm * 64 + mt * 16 + g;
            int col = n0 + wn * 32 + nt * 8 + tq * 2;
            float bv0 = bias ? bias[row] : 0.f;
            float bv1 = bias ? bias[row + 8] : 0.f;
            float2 o0 = {acc[mt][nt][0] + bv0, acc[mt][nt][1] + bv0};
            float2 o1 = {acc[mt][nt][2] + bv1, acc[mt][nt][3] + bv1};
            *(float2*)&Cm[(size_t)row * N + col] = o0;
            *(float2*)&Cm[(size_t)(row + 8) * N + col] = o1;
        }
    }
}

// ---------------- windowed 8x8 attention via TF32 mma ----------------
// One block per (window, head, batch); 4 warps, warp owns 16 queries.
// S = Q(64x32) K^T, softmax, O = P(64x64) V(64x32). Fused residual + GN stats.
constexpr int WK_LD = 72;
constexpr int WIN_SMEM = (3 * 32 * WK_LD + 64 * WK_LD) * 4;
__global__ __launch_bounds__(128)
void win_attn_mma_kernel(const float* __restrict__ qkv,
                         const float* __restrict__ x,
                         float* __restrict__ out) {
    extern __shared__ uint32_t smu[];
    uint32_t* sQ = smu;                  // [32][72] tf32, [d][token]
    uint32_t* sK = smu + 32 * WK_LD;     // [32][72]
    uint32_t* sV = sK + 32 * WK_LD;      // [32][72]
    uint32_t* sP = sV + 32 * WK_LD;      // [64][72]

    const int win = blockIdx.x;
    const int gi = win >> 3, gj = win & 7;
    const int h = blockIdx.y;
    const int b = blockIdx.z;
    const int tid = threadIdx.x, warp = tid >> 5, lane = tid & 31;
    const int g = lane >> 2, tq = lane & 3;

    // load Q(scaled), K, V for this (b,h,window)
    for (int idx = tid; idx < 2048; idx += 128) {
        int t = idx & 63, d = idx >> 6;
        int si = t >> 3, sj = t & 7;
        int sp = (gi * 8 + si) * W + gj * 8 + sj;
        size_t base = ((size_t)b * 768 + h * 32 + d) * (size_t)P + sp;
        sQ[d * WK_LD + t] = f2tf(qkv[base] * SCALE);
        sK[d * WK_LD + t] = f2tf(qkv[base + (size_t)256 * P]);
        sV[d * WK_LD + t] = f2tf(qkv[base + (size_t)512 * P]);
    }
    __syncthreads();

    const int qb = warp * 16;
    uint32_t qf[4][4];
#pragma unroll
    for (int ks = 0; ks < 4; ++ks) {
        const int kb = ks * 8;
        qf[ks][0] = sQ[(kb + tq) * WK_LD + qb + g];
        qf[ks][1] = sQ[(kb + tq) * WK_LD + qb + 8 + g];
        qf[ks][2] = sQ[(kb + tq + 4) * WK_LD + qb + g];
        qf[ks][3] = sQ[(kb + tq + 4) * WK_LD + qb + 8 + g];
    }

    // S = Q K^T
    float S[8][4];
#pragma unroll
    for (int nt = 0; nt < 8; ++nt) {
        const int nb = nt * 8;
        S[nt][0] = S[nt][1] = S[nt][2] = S[nt][3] = 0.f;
#pragma unroll
        for (int ks = 0; ks < 4; ++ks) {
            const int kb = ks * 8;
            uint32_t b0 = sK[(kb + tq) * WK_LD + nb + g];
            uint32_t b1 = sK[(kb + tq + 4) * WK_LD + nb + g];
            mma_tf32(S[nt], qf[ks], b0, b1);
        }
    }

    // softmax (full row, 64 keys)
    float m0 = -1e30f, m1 = -1e30f;
#pragma unroll
    for (int nt = 0; nt < 8; ++nt) {
        m0 = fmaxf(m0, fmaxf(S[nt][0], S[nt][1]));
        m1 = fmaxf(m1, fmaxf(S[nt][2], S[nt][3]));
    }
    m0 = fmaxf(m0, __shfl_xor_sync(~0u, m0, 1));
    m0 = fmaxf(m0, __shfl_xor_sync(~0u, m0, 2));
    m1 = fmaxf(m1, __shfl_xor_sync(~0u, m1, 1));
    m1 = fmaxf(m1, __shfl_xor_sync(~0u, m1, 2));
    float l0 = 0.f, l1 = 0.f;
#pragma unroll
    for (int nt = 0; nt < 8; ++nt) {
        float p0 = __expf(S[nt][0] - m0);
        float p1 = __expf(S[nt][1] - m0);
        float p2 = __expf(S[nt][2] - m1);
        float p3 = __expf(S[nt][3] - m1);
        l0 += p0 + p1; l1 += p2 + p3;
        const int col = nt * 8 + tq * 2;
        sP[(qb + g) * WK_LD + col] = f2tf(p0);
        sP[(qb + g) * WK_LD + col + 1] = f2tf(p1);
        sP[(qb + 8 + g) * WK_LD + col] = f2tf(p2);
        sP[(qb + 8 + g) * WK_LD + col + 1] = f2tf(p3);
    }
    l0 += __shfl_xor_sync(~0u, l0, 1);
    l0 += __shfl_xor_sync(~0u, l0, 2);
    l1 += __shfl_xor_sync(~0u, l1, 1);
    l1 += __shfl_xor_sync(~0u, l1, 2);
    __syncwarp();

    // O = P V
    float O[4][4] = {};
#pragma unroll
    for (int ks = 0; ks < 8; ++ks) {
        const int kb = ks * 8;
        uint32_t af[4];
        af[0] = sP[(qb + g) * WK_LD + kb + tq];
        af[1] = sP[(qb + 8 + g) * WK_LD + kb + tq];
        af[2] = sP[(qb + g) * WK_LD + kb + tq + 4];
        af[3] = sP[(qb + 8 + g) * WK_LD + kb + tq + 4];
#pragma unroll
        for (int ntd = 0; ntd < 4; ++ntd) {
            const int nb = ntd * 8;
            uint32_t b0 = sV[(nb + g) * WK_LD + kb + tq];
            uint32_t b1 = sV[(nb + g) * WK_LD + kb + tq + 4];
            mma_tf32(O[ntd], af, b0, b1);
        }
    }

    // epilogue: normalize, residual, store, fused GN stats (slot 1)
    float rl0 = 1.f / l0, rl1 = 1.f / l1;
    const int q0 = qb + g, q1 = qb + 8 + g;
    const int sp0 = (gi * 8 + (q0 >> 3)) * W + gj * 8 + (q0 & 7);
    const int sp1 = (gi * 8 + (q1 >> 3)) * W + gj * 8 + (q1 & 7);
    const size_t ob = ((size_t)b * 256 + h * 32) * (size_t)P;
    float s = 0.f, ss = 0.f;
#pragma unroll
    for (int ntd = 0; ntd < 4; ++ntd) {
        const int d0 = ntd * 8 + tq * 2;
        size_t a00 = ob + (size_t)d0 * P + sp0;
        size_t a01 = ob + (size_t)(d0 + 1) * P + sp0;
        size_t a10 = ob + (size_t)d0 * P + sp1;
        size_t a11 = ob + (size_t)(d0 + 1) * P + sp1;
        float v00 = x[a00] + O[ntd][0] * rl0;
        float v01 = x[a01] + O[ntd][1] * rl0;
        float v10 = x[a10] + O[ntd][2] * rl1;
        float v11 = x[a11] + O[ntd][3] * rl1;
        out[a00] = v00; out[a01] = v01; out[a10] = v10; out[a11] = v11;
        s += v00 + v01 + v10 + v11;
        ss = fmaf(v00, v00, ss);
        ss = fmaf(v01, v01, ss);
        ss = fmaf(v10, v10, ss);
        ss = fmaf(v11, v11, ss);
    }
#pragma unroll
    for (int o = 16; o > 0; o >>= 1) {
        s += __shfl_xor_sync(~0u, s, o);
        ss += __shfl_xor_sync(~0u, ss, o);
    }
    __shared__ float red[2][4];
    if (lane == 0) { red[0][warp] = s; red[1][warp] = ss; }
    __syncthreads();
    if (tid == 0) {
        float a = red[0][0] + red[0][1] + red[0][2] + red[0][3];
        float qq = red[1][0] + red[1][1] + red[1][2] + red[1][3];
        atomicAdd(&g_stats[1][2 * b], a);
        atomicAdd(&g_stats[1][2 * b + 1], qq);
    }
}

// ---------------- patch merge + LayerNorm ----------------
__global__ void patch_merge_ln_kernel(const float* __restrict__ gx,
                                      const float* __restrict__ lnw,
                                      const float* __restrict__ lnb,
                                      float* __restrict__ m_out) {
    int b = blockIdx.y;
    int p2 = blockIdx.x;
    int i = p2 >> 5, j = p2 & 31;
    int c = threadIdx.x;
    size_t base = ((size_t)b * 256 + c) * (size_t)P;
    int sp00 = (2 * i) * W + 2 * j;
    float v0 = gx[base + sp00];
    float v1 = gx[base + sp00 + W];
    float v2 = gx[base + sp00 + 1];
    float v3 = gx[base + sp00 + W + 1];

    float s = v0 + v1 + v2 + v3;
    float ss = v0 * v0 + v1 * v1 + v2 * v2 + v3 * v3;
#pragma unroll
    for (int o = 16; o > 0; o >>= 1) {
        s += __shfl_xor_sync(~0u, s, o);
        ss += __shfl_xor_sync(~0u, ss, o);
    }
    __shared__ float red[2][8];
    int lane = threadIdx.x & 31, wp = threadIdx.x >> 5;
    if (lane == 0) { red[0][wp] = s; red[1][wp] = ss; }
    __syncthreads();
    if (threadIdx.x < 32) {
        float a = threadIdx.x < 8 ? red[0][threadIdx.x] : 0.f;
        float q = threadIdx.x < 8 ? red[1][threadIdx.x] : 0.f;
#pragma unroll
        for (int o = 4; o > 0; o >>= 1) {
            a += __shfl_xor_sync(~0u, a, o);
            q += __shfl_xor_sync(~0u, q, o);
        }
        if (threadIdx.x == 0) { red[0][0] = a; red[1][0] = q; }
    }
    __syncthreads();
    float mean = red[0][0] * (1.f / 1024.f);
    float var = red[1][0] * (1.f / 1024.f) - mean * mean;
    float inv = rsqrtf(var + EPS_LN);

    size_t ob = (size_t)b * 1024 * (size_t)P2 + p2;
    m_out[ob + (size_t)(0 * 256 + c) * P2] = (v0 - mean) * inv * lnw[0 * 256 + c] + lnb[0 * 256 + c];
    m_out[ob + (size_t)(1 * 256 + c) * P2] = (v1 - mean) * inv * lnw[1 * 256 + c] + lnb[1 * 256 + c];
    m_out[ob + (size_t)(2 * 256 + c) * P2] = (v2 - mean) * inv * lnw[2 * 256 + c] + lnb[2 * 256 + c];
    m_out[ob + (size_t)(3 * 256 + c) * P2] = (v3 - mean) * inv * lnw[3 * 256 + c] + lnb[3 * 256 + c];
}

// ---------------- global attention: flash-style TF32 mma ----------------
constexpr int SQ_LD = 136;
constexpr int SK_LD = 72;
constexpr int GLOB_SMEM = (32 * SQ_LD + 2 * 32 * SK_LD + 128 * SK_LD) * 4;
__global__ __launch_bounds__(128, 2)
void glob_attn_mma_kernel(const float* __restrict__ qg,
                          const float* __restrict__ kv,
                          const float* __restrict__ gridx,
                          float* __restrict__ out) {
    extern __shared__ float sm[];
    float* sQ = sm;                                    // [32][136] floats
    uint32_t* sK = (uint32_t*)(sm + 32 * SQ_LD);       // [32][72] tf32
    uint32_t* sV = sK + 32 * SK_LD;                    // [32][72] tf32
    uint32_t* sP = sV + 32 * SK_LD;                    // [128][72] tf32

    const int b = blockIdx.z, h = blockIdx.y;
    const int q0 = blockIdx.x * 128;
    const int tid = threadIdx.x, warp = tid >> 5, lane = tid & 31;
    const int g = lane >> 2, tq = lane & 3;

    const size_t qbase = ((size_t)b * 256 + h * 32) * (size_t)P + q0;
    for (int i = tid; i < 32 * 32; i += 128) {
        int d = i >> 5, q4 = (i & 31) << 2;
        float4 v = *(const float4*)&qg[qbase + (size_t)d * P + q4];
        v.x *= SCALE; v.y *= SCALE; v.z *= SCALE; v.w *= SCALE;
        *(float4*)&sQ[d * SQ_LD + q4] = v;
    }
    __syncthreads();

    uint32_t qf[2][4][4];
#pragma unroll
    for (int mt = 0; mt < 2; ++mt) {
        const int qb = warp * 32 + mt * 16;
#pragma unroll
        for (int ks = 0; ks < 4; ++ks) {
            const int kb = ks * 8;
            qf[mt][ks][0] = f2tf(sQ[(kb + tq) * SQ_LD + qb + g]);
            qf[mt][ks][1] = f2tf(sQ[(kb + tq) * SQ_LD + qb + 8 + g]);
            qf[mt][ks][2] = f2tf(sQ[(kb + tq + 4) * SQ_LD + qb + g]);
            qf[mt][ks][3] = f2tf(sQ[(kb + tq + 4) * SQ_LD + qb + 8 + g]);
        }
    }

    float O[2][4][4] = {};
    float mrow[2][2], lrow[2][2];
#pragma unroll
    for (int mt = 0; mt < 2; ++mt) {
        mrow[mt][0] = mrow[mt][1] = -1e30f;
        lrow[mt][0] = lrow[mt][1] = 0.f;
    }

    const size_t kbase = ((size_t)b * 512 + h * 32) * (size_t)P2;
    const size_t vbase = kbase + (size_t)256 * P2;

    for (int t = 0; t < P2; t += 64) {
        __syncthreads();
        for (int i = tid; i < 32 * 16; i += 128) {
            int d = i >> 4, c4 = (i & 15) << 2;
            float4 kk = *(const float4*)&kv[kbase + (size_t)d * P2 + t + c4];
            float4 vv = *(const float4*)&kv[vbase + (size_t)d * P2 + t + c4];
            uint4 ku = {f2tf(kk.x), f2tf(kk.y), f2tf(kk.z), f2tf(kk.w)};
            uint4 vu = {f2tf(vv.x), f2tf(vv.y), f2tf(vv.z), f2tf(vv.w)};
            *(uint4*)&sK[d * SK_LD + c4] = ku;
            *(uint4*)&sV[d * SK_LD + c4] = vu;
        }
        __syncthreads();

        float S[2][8][4];
#pragma unroll
        for (int nt = 0; nt < 8; ++nt) {
            const int nb = nt * 8;
            uint32_t b0[4], b1[4];
#pragma unroll
            for (int ks = 0; ks < 4; ++ks) {
                const int kb = ks * 8;
                b0[ks] = sK[(kb + tq) * SK_LD + nb + g];
                b1[ks] = sK[(kb + tq + 4) * SK_LD + nb + g];
            }
#pragma unroll
            for (int mt = 0; mt < 2; ++mt) {
                S[mt][nt][0] = S[mt][nt][1] = S[mt][nt][2] = S[mt][nt][3] = 0.f;
#pragma unroll
                for (int ks = 0; ks < 4; ++ks)
                    mma_tf32(S[mt][nt], qf[mt][ks], b0[ks], b1[ks]);
            }
        }

#pragma unroll
        for (int mt = 0; mt < 2; ++mt) {
            const int qb = warp * 32 + mt * 16;
            float tm0 = -1e30f, tm1 = -1e30f;
#pragma unroll
            for (int nt = 0; nt < 8; ++nt) {
                tm0 = fmaxf(tm0, fmaxf(S[mt][nt][0], S[mt][nt][1]));
                tm1 = fmaxf(tm1, fmaxf(S[mt][nt][2], S[mt][nt][3]));
            }
            tm0 = fmaxf(tm0, __shfl_xor_sync(~0u, tm0, 1));
            tm0 = fmaxf(tm0, __shfl_xor_sync(~0u, tm0, 2));
            tm1 = fmaxf(tm1, __shfl_xor_sync(~0u, tm1, 1));
            tm1 = fmaxf(tm1, __shfl_xor_sync(~0u, tm1, 2));
            float m0n = fmaxf(mrow[mt][0], tm0);
            float m1n = fmaxf(mrow[mt][1], tm1);
            float c0 = __expf(mrow[mt][0] - m0n);
            float c1 = __expf(mrow[mt][1] - m1n);
            mrow[mt][0] = m0n; mrow[mt][1] = m1n;
            float s0 = 0.f, s1 = 0.f;
#pragma unroll
            for (int nt = 0; nt < 8; ++nt) {
                float p0 = __expf(S[mt][nt][0] - m0n);
                float p1 = __expf(S[mt][nt][1] - m0n);
                float p2 = __expf(S[mt][nt][2] - m1n);
                float p3 = __expf(S[mt][nt][3] - m1n);
                s0 += p0 + p1; s1 += p2 + p3;
                const int col = nt * 8 + tq * 2;
                sP[(qb + g) * SK_LD + col] = f2tf(p0);
                sP[(qb + g) * SK_LD + col + 1] = f2tf(p1);
                sP[(qb + 8 + g) * SK_LD + col] = f2tf(p2);
                sP[(qb + 8 + g) * SK_LD + col + 1] = f2tf(p3);
            }
            s0 += __shfl_xor_sync(~0u, s0, 1);
            s0 += __shfl_xor_sync(~0u, s0, 2);
            s1 += __shfl_xor_sync(~0u, s1, 1);
            s1 += __shfl_xor_sync(~0u, s1, 2);
            lrow[mt][0] = lrow[mt][0] * c0 + s0;
            lrow[mt][1] = lrow[mt][1] * c1 + s1;
#pragma unroll
            for (int ntd = 0; ntd < 4; ++ntd) {
                O[mt][ntd][0] *= c0; O[mt][ntd][1] *= c0;
                O[mt][ntd][2] *= c1; O[mt][ntd][3] *= c1;
            }
        }
        __syncwarp();

#pragma unroll
        for (int ks = 0; ks < 8; ++ks) {
            const int kb = ks * 8;
            uint32_t af[2][4];
#pragma unroll
            for (int mt = 0; mt < 2; ++mt) {
                const int qb = warp * 32 + mt * 16;
                af[mt][0] = sP[(qb + g) * SK_LD + kb + tq];
                af[mt][1] = sP[(qb + 8 + g) * SK_LD + kb + tq];
                af[mt][2] = sP[(qb + g) * SK_LD + kb + tq + 4];
                af[mt][3] = sP[(qb + 8 + g) * SK_LD + kb + tq + 4];
            }
#pragma unroll
            for (int ntd = 0; ntd < 4; ++ntd) {
                const int nb = ntd * 8;
                uint32_t b0 = sV[(nb + g) * SK_LD + kb + tq];
                uint32_t b1 = sV[(nb + g) * SK_LD + kb + tq + 4];
#pragma unroll
                for (int mt = 0; mt < 2; ++mt)
                    mma_tf32(O[mt][ntd], af[mt], b0, b1);
            }
        }
    }

    __syncthreads();
#pragma unroll
    for (int mt = 0; mt < 2; ++mt) {
        const int qb = warp * 32 + mt * 16;
        float rl0 = 1.f / lrow[mt][0];
        float rl1 = 1.f / lrow[mt][1];
#pragma unroll
        for (int ntd = 0; ntd < 4; ++ntd) {
            const int d0 = ntd * 8 + tq * 2;
            sQ[(d0) * SQ_LD + qb + g] = O[mt][ntd][0] * rl0;
            sQ[(d0 + 1) * SQ_LD + qb + g] = O[mt][ntd][1] * rl0;
            sQ[(d0) * SQ_LD + qb + 8 + g] = O[mt][ntd][2] * rl1;
            sQ[(d0 + 1) * SQ_LD + qb + 8 + g] = O[mt][ntd][3] * rl1;
        }
    }
    __syncthreads();
    for (int i = tid; i < 32 * 32; i += 128) {
        int d = i >> 5, q4 = (i & 31) << 2;
        float4 o = *(float4*)&sQ[d * SQ_LD + q4];
        float4 r = *(const float4*)&gridx[qbase + (size_t)d * P + q4];
        o.x += r.x; o.y += r.y; o.z += r.z; o.w += r.w;
        *(float4*)&out[qbase + (size_t)d * P + q4] = o;
    }
}

// ---------------- host launcher ----------------
static float* sym_addr(const void* s) {
    void* p = nullptr;
    cudaGetSymbolAddress(&p, s);
    return (float*)p;
}

extern "C" void kernel_launch(void* const* d_in, const int* in_sizes, int n_in,
                              void* d_out, int out_size) {
    const float* x        = (const float*)d_in[0];
    const float* norm_w   = (const float*)d_in[1];
    const float* norm_b   = (const float*)d_in[2];
    const float* qkv_w    = (const float*)d_in[3];
    const float* qkv_b    = (const float*)d_in[4];
    const float* proj_w   = (const float*)d_in[5];
    const float* proj_b   = (const float*)d_in[6];
    const float* gridnw   = (const float*)d_in[7];
    const float* gridnb   = (const float*)d_in[8];
    const float* pm_ln_w  = (const float*)d_in[9];
    const float* pm_ln_b  = (const float*)d_in[10];
    const float* pm_red_w = (const float*)d_in[11];
    const float* ds_nw    = (const float*)d_in[12];
    const float* ds_nb    = (const float*)d_in[13];
    const float* q_w      = (const float*)d_in[14];
    const float* q_b      = (const float*)d_in[15];
    const float* kv_w     = (const float*)d_in[16];
    const float* kv_b     = (const float*)d_in[17];
    float* out = (float*)d_out;

    float* xn    = sym_addr(g_xn);
    float* qkv   = sym_addr(g_qkv);
    float* gridx = sym_addr(g_gridx);
    float* mbuf  = sym_addr(g_m);
    float* pm    = sym_addr(g_pm);
    float* qg    = sym_addr(g_qg);
    float* kvb   = sym_addr(g_kv);

    cudaFuncSetAttribute(win_attn_mma_kernel,
                         cudaFuncAttributeMaxDynamicSharedMemorySize, WIN_SMEM);
    cudaFuncSetAttribute(glob_attn_mma_kernel,
                         cudaFuncAttributeMaxDynamicSharedMemorySize, GLOB_SMEM);

    dim3 gnGrid(64, BATCH);

    zero_stats_kernel<<<1, 32>>>();

    // ---- stage 1: stats(x); qkv = conv1x1(GN(x)) with GN fused in GEMM ----
    gn_stats_kernel<<<gnGrid, 256>>>(x, C * P, 0);
    gemm_tf32_kernel<<<dim3(P / 128, 768 / 128, BATCH), 256>>>(
        qkv_w, x, qkv_b, qkv, 768, P, C, norm_w, norm_b, 0);

    // ---- stage 2: windowed attention (mma) + residual + fused stats; GN apply ----
    win_attn_mma_kernel<<<dim3(64, NH, BATCH), 128, WIN_SMEM>>>(qkv, x, gridx);
    gn_apply_kernel<<<gnGrid, 256>>>(gridx, gridnw, gridnb, gridx, P, C * P, EPS_GN, 1);

    // ---- stage 3: patch merge + LN; pm reduction GEMM ----
    patch_merge_ln_kernel<<<dim3(P2, BATCH), 256>>>(gridx, pm_ln_w, pm_ln_b, mbuf);
    gemm_tf32_kernel<<<dim3(P2 / 128, C / 128, BATCH), 256>>>(
        pm_red_w, mbuf, nullptr, pm, C, P2, 4 * C, nullptr, nullptr, -1);

    // ---- stage 4: stats(pm); q/kv projections (kv GEMM fuses GN(pm)) ----
    gn_stats_kernel<<<gnGrid, 256>>>(pm, C * P2, 2);
    gemm_tf32_kernel<<<dim3(P / 128, C / 128, BATCH), 256>>>(
        q_w, gridx, q_b, qg, C, P, C, nullptr, nullptr, -1);
    gemm_tf32_kernel<<<dim3(P2 / 128, 512 / 128, BATCH), 256>>>(
        kv_w, pm, kv_b, kvb, 512, P2, C, ds_nw, ds_nb, 2);

    // ---- stage 5: global attention + residual ----
    glob_attn_mma_kernel<<<dim3(P / 128, NH, BATCH), 128, GLOB_SMEM>>>(qg, kvb, gridx, xn);

    // ---- stage 6: proj ----
    gemm_tf32_kernel<<<dim3(P / 128, C / 128, BATCH), 256>>>(
        proj_w, xn, proj_b, out, C, P, C, nullptr, nullptr, -1);
}

// round 6
// speedup vs baseline: 3.7190x; 1.1172x over previous
#include <cuda_runtime.h>
#include <math.h>
#include <stdint.h>

// ---------------- problem constants ----------------
constexpr int BATCH = 4;
constexpr int C = 256;
constexpr int H = 64, W = 64;
constexpr int P = H * W;              // 4096
constexpr int NH = 8, HD = 32;
constexpr int P2 = (H / 2) * (W / 2); // 1024
constexpr float SCALE = 0.1767766952966369f; // 32^-0.5
constexpr float EPS_GN = 1e-6f;
constexpr float EPS_LN = 1e-5f;

// ---------------- scratch (device globals) ----------
// stats slots: 0 = x (stage1), 1 = gridx (stage2), 2 = pm (stage4)
__device__ float g_stats[3][2 * BATCH];
__device__ float g_xn[BATCH * C * P];     // global_x scratch
__device__ float g_qkv[BATCH * 3 * C * P];
__device__ float g_gridx[BATCH * C * P];
__device__ float g_m[BATCH * 4 * C * P2];
__device__ float g_pm[BATCH * C * P2];
__device__ float g_qg[BATCH * C * P];
__device__ float g_kv[BATCH * 2 * C * P2];

// ---------------- mma helpers ----------------
__device__ __forceinline__ uint32_t f2tf(float f) {
    uint32_t u;
    asm("cvt.rna.tf32.f32 %0, %1;" : "=r"(u) : "f"(f));
    return u;
}
__device__ __forceinline__ void mma_tf32(float* c, const uint32_t* a,
                                         uint32_t b0, uint32_t b1) {
    asm volatile(
        "mma.sync.aligned.m16n8k8.row.col.f32.tf32.tf32.f32 "
        "{%0,%1,%2,%3}, {%4,%5,%6,%7}, {%8,%9}, {%0,%1,%2,%3};"
        : "+f"(c[0]), "+f"(c[1]), "+f"(c[2]), "+f"(c[3])
        : "r"(a[0]), "r"(a[1]), "r"(a[2]), "r"(a[3]), "r"(b0), "r"(b1));
}

// ---------------- GroupNorm helpers ----------------
__global__ void zero_stats_kernel() {
    if (threadIdx.x < 3 * 2 * BATCH) ((float*)g_stats)[threadIdx.x] = 0.f;
}

__global__ void gn_stats_kernel(const float* __restrict__ x, int per_batch, int slot) {
    int b = blockIdx.y;
    const float* xb = x + (size_t)b * per_batch;
    float s = 0.f, ss = 0.f;
    for (int i = blockIdx.x * blockDim.x + threadIdx.x; i < per_batch;
         i += gridDim.x * blockDim.x) {
        float v = xb[i];
        s += v;
        ss = fmaf(v, v, ss);
    }
#pragma unroll
    for (int o = 16; o > 0; o >>= 1) {
        s += __shfl_xor_sync(~0u, s, o);
        ss += __shfl_xor_sync(~0u, ss, o);
    }
    __shared__ float red[2][8];
    int lane = threadIdx.x & 31, wp = threadIdx.x >> 5;
    if (lane == 0) { red[0][wp] = s; red[1][wp] = ss; }
    __syncthreads();
    if (threadIdx.x < 32) {
        float a = threadIdx.x < 8 ? red[0][threadIdx.x] : 0.f;
        float q = threadIdx.x < 8 ? red[1][threadIdx.x] : 0.f;
#pragma unroll
        for (int o = 4; o > 0; o >>= 1) {
            a += __shfl_xor_sync(~0u, a, o);
            q += __shfl_xor_sync(~0u, q, o);
        }
        if (threadIdx.x == 0) {
            atomicAdd(&g_stats[slot][2 * b], a);
            atomicAdd(&g_stats[slot][2 * b + 1], q);
        }
    }
}

__global__ void gn_apply_kernel(const float* __restrict__ x,
                                const float* __restrict__ w,
                                const float* __restrict__ bias,
                                float* __restrict__ out,
                                int hw, int per_batch, float eps, int slot) {
    int b = blockIdx.y;
    float cnt = (float)per_batch;
    float mean = g_stats[slot][2 * b] / cnt;
    float var = g_stats[slot][2 * b + 1] / cnt - mean * mean;
    float inv = rsqrtf(var + eps);
    const float* xb = x + (size_t)b * per_batch;
    float* ob = out + (size_t)b * per_batch;
    for (int i = blockIdx.x * blockDim.x + threadIdx.x; i < per_batch;
         i += gridDim.x * blockDim.x) {
        int c = i / hw;
        ob[i] = (xb[i] - mean) * inv * w[c] + bias[c];
    }
}

// ---------------- TF32 GEMM (single buffer, reg prefetch, fused GN on B) ----
constexpr int GEMM_LDS = 136;
__global__ __launch_bounds__(256, 2)
void gemm_tf32_kernel(const float* __restrict__ A,
                      const float* __restrict__ Bm,
                      const float* __restrict__ bias,
                      float* __restrict__ Cm,
                      int M, int N, int K,
                      const float* __restrict__ gnw,
                      const float* __restrict__ gnb,
                      int slot) {
    const int b = blockIdx.z;
    Bm += (size_t)b * K * N;
    Cm += (size_t)b * M * N;
    __shared__ uint32_t As[16 * GEMM_LDS];
    __shared__ uint32_t Bs[16 * GEMM_LDS];
    const int tid = threadIdx.x;
    const int warp = tid >> 5, lane = tid & 31;
    const int wm = warp >> 2, wn = warp & 3;
    const int g = lane >> 2, tq = lane & 3;
    const int m0 = blockIdx.y * 128, n0 = blockIdx.x * 128;
    const int ar = tid >> 2;
    const int ac = (tid & 3) << 2;
    const int br = tid >> 5;
    const int bc = lane << 2;

    float mean = 0.f, inv = 0.f;
    if (gnw) {
        float cnt = (float)K * (float)N;
        mean = g_stats[slot][2 * b] / cnt;
        float var = g_stats[slot][2 * b + 1] / cnt - mean * mean;
        inv = rsqrtf(var + EPS_GN);
    }

    const float* Aplo = &A[(size_t)(m0 + ar) * K + ac];
    const float* Aphi = &A[(size_t)(m0 + ar + 64) * K + ac];
    const float* Bplo = &Bm[(size_t)br * N + n0 + bc];
    const float* Bphi = &Bm[(size_t)(br + 8) * N + n0 + bc];

    float4 a0v = *(const float4*)Aplo;
    float4 a1v = *(const float4*)Aphi;
    float4 b0v = *(const float4*)Bplo;
    float4 b1v = *(const float4*)Bphi;

    float acc[4][4][4] = {};
    const int ntile = K >> 4;
#pragma unroll 1
    for (int i = 0; i < ntile; ++i) {
        __syncthreads();
        As[(ac + 0) * GEMM_LDS + ar] = f2tf(a0v.x);
        As[(ac + 1) * GEMM_LDS + ar] = f2tf(a0v.y);
        As[(ac + 2) * GEMM_LDS + ar] = f2tf(a0v.z);
        As[(ac + 3) * GEMM_LDS + ar] = f2tf(a0v.w);
        As[(ac + 0) * GEMM_LDS + ar + 64] = f2tf(a1v.x);
        As[(ac + 1) * GEMM_LDS + ar + 64] = f2tf(a1v.y);
        As[(ac + 2) * GEMM_LDS + ar + 64] = f2tf(a1v.z);
        As[(ac + 3) * GEMM_LDS + ar + 64] = f2tf(a1v.w);
        if (gnw) {
            int k0r = i * 16 + br;
            float al0 = inv * gnw[k0r], be0 = gnb[k0r] - mean * al0;
            float al1 = inv * gnw[k0r + 8], be1 = gnb[k0r + 8] - mean * al1;
            uint4 bu0 = {f2tf(fmaf(b0v.x, al0, be0)), f2tf(fmaf(b0v.y, al0, be0)),
                         f2tf(fmaf(b0v.z, al0, be0)), f2tf(fmaf(b0v.w, al0, be0))};
            uint4 bu1 = {f2tf(fmaf(b1v.x, al1, be1)), f2tf(fmaf(b1v.y, al1, be1)),
                         f2tf(fmaf(b1v.z, al1, be1)), f2tf(fmaf(b1v.w, al1, be1))};
            *(uint4*)&Bs[br * GEMM_LDS + bc] = bu0;
            *(uint4*)&Bs[(br + 8) * GEMM_LDS + bc] = bu1;
        } else {
            uint4 bu0 = {f2tf(b0v.x), f2tf(b0v.y), f2tf(b0v.z), f2tf(b0v.w)};
            uint4 bu1 = {f2tf(b1v.x), f2tf(b1v.y), f2tf(b1v.z), f2tf(b1v.w)};
            *(uint4*)&Bs[br * GEMM_LDS + bc] = bu0;
            *(uint4*)&Bs[(br + 8) * GEMM_LDS + bc] = bu1;
        }
        __syncthreads();
        if (i + 1 < ntile) {
            const int k1 = (i + 1) << 4;
            a0v = *(const float4*)(Aplo + k1);
            a1v = *(const float4*)(Aphi + k1);
            b0v = *(const float4*)(Bplo + (size_t)k1 * N);
            b1v = *(const float4*)(Bphi + (size_t)k1 * N);
        }
#pragma unroll
        for (int ks = 0; ks < 2; ++ks) {
            const int kb = ks * 8;
            uint32_t af[4][4];
            uint32_t bf[4][2];
#pragma unroll
            for (int mt = 0; mt < 4; ++mt) {
                const int mb = wm * 64 + mt * 16;
                af[mt][0] = As[(kb + tq) * GEMM_LDS + mb + g];
                af[mt][1] = As[(kb + tq) * GEMM_LDS + mb + 8 + g];
                af[mt][2] = As[(kb + tq + 4) * GEMM_LDS + mb + g];
                af[mt][3] = As[(kb + tq + 4) * GEMM_LDS + mb + 8 + g];
            }
#pragma unroll
            for (int nt = 0; nt < 4; ++nt) {
                const int nb = wn * 32 + nt * 8;
                bf[nt][0] = Bs[(kb + tq) * GEMM_LDS + nb + g];
                bf[nt][1] = Bs[(kb + tq + 4) * GEMM_LDS + nb + g];
            }
#pragma unroll
            for (int mt = 0; mt < 4; ++mt)
#pragma unroll
                for (int nt = 0; nt < 4; ++nt)
                    mma_tf32(acc[mt][nt], af[mt], bf[nt][0], bf[nt][1]);
        }
    }
#pragma unroll
    for (int mt = 0; mt < 4; ++mt) {
#pragma unroll
        for (int nt = 0; nt < 4; ++nt) {
            int row = m0 + wm * 64 + mt * 16 + g;
            int col = n0 + wn * 32 + nt * 8 + tq * 2;
            float bv0 = bias ? bias[row] : 0.f;
            float bv1 = bias ? bias[row + 8] : 0.f;
            float2 o0 = {acc[mt][nt][0] + bv0, acc[mt][nt][1] + bv0};
            float2 o1 = {acc[mt][nt][2] + bv1, acc[mt][nt][3] + bv1};
            *(float2*)&Cm[(size_t)row * N + col] = o0;
            *(float2*)&Cm[(size_t)(row + 8) * N + col] = o1;
        }
    }
}

// ---------------- windowed 8x8 attention via TF32 mma (vectorized I/O) ------
// One block per (window, head, batch); 4 warps, warp owns 16 queries.
constexpr int WK_LD = 72;
constexpr int WIN_SMEM = (3 * 32 * WK_LD + 64 * WK_LD) * 4;
__global__ __launch_bounds__(128, 4)
void win_attn_mma_kernel(const float* __restrict__ qkv,
                         const float* __restrict__ x,
                         float* __restrict__ out) {
    extern __shared__ uint32_t smu[];
    uint32_t* sQ = smu;                  // [32][72] tf32, [d][token]
    uint32_t* sK = smu + 32 * WK_LD;     // [32][72]
    uint32_t* sV = sK + 32 * WK_LD;      // [32][72]
    uint32_t* sP = sV + 32 * WK_LD;      // [64][72] probs; later O staging
    float* sO = (float*)sP;              // epilogue alias

    const int win = blockIdx.x;
    const int gi = win >> 3, gj = win & 7;
    const int h = blockIdx.y;
    const int b = blockIdx.z;
    const int tid = threadIdx.x, warp = tid >> 5, lane = tid & 31;
    const int g = lane >> 2, tq = lane & 3;

    const int row0 = gi * 8;            // window top row
    const int col0 = gj * 8;            // window left col
    const size_t qkb = ((size_t)b * 768 + h * 32) * (size_t)P;

    // vectorized load: 512 float4 per tensor; 4 per thread.
#pragma unroll
    for (int ch = 0; ch < 4; ++ch) {
        int idx = tid + ch * 128;        // [0,512)
        int d = idx >> 4;
        int si = (idx >> 1) & 7;
        int sj4 = (idx & 1) << 2;
        int tok = si * 8 + sj4;
        size_t ga = qkb + (size_t)d * P + (row0 + si) * W + col0 + sj4;
        float4 qv = *(const float4*)&qkv[ga];
        float4 kv4 = *(const float4*)&qkv[ga + (size_t)256 * P];
        float4 vv = *(const float4*)&qkv[ga + (size_t)512 * P];
        uint4 qu = {f2tf(qv.x * SCALE), f2tf(qv.y * SCALE),
                    f2tf(qv.z * SCALE), f2tf(qv.w * SCALE)};
        uint4 ku = {f2tf(kv4.x), f2tf(kv4.y), f2tf(kv4.z), f2tf(kv4.w)};
        uint4 vu = {f2tf(vv.x), f2tf(vv.y), f2tf(vv.z), f2tf(vv.w)};
        *(uint4*)&sQ[d * WK_LD + tok] = qu;
        *(uint4*)&sK[d * WK_LD + tok] = ku;
        *(uint4*)&sV[d * WK_LD + tok] = vu;
    }
    __syncthreads();

    const int qb = warp * 16;
    uint32_t qf[4][4];
#pragma unroll
    for (int ks = 0; ks < 4; ++ks) {
        const int kb = ks * 8;
        qf[ks][0] = sQ[(kb + tq) * WK_LD + qb + g];
        qf[ks][1] = sQ[(kb + tq) * WK_LD + qb + 8 + g];
        qf[ks][2] = sQ[(kb + tq + 4) * WK_LD + qb + g];
        qf[ks][3] = sQ[(kb + tq + 4) * WK_LD + qb + 8 + g];
    }

    // S = Q K^T
    float S[8][4];
#pragma unroll
    for (int nt = 0; nt < 8; ++nt) {
        const int nb = nt * 8;
        S[nt][0] = S[nt][1] = S[nt][2] = S[nt][3] = 0.f;
#pragma unroll
        for (int ks = 0; ks < 4; ++ks) {
            const int kb = ks * 8;
            uint32_t b0 = sK[(kb + tq) * WK_LD + nb + g];
            uint32_t b1 = sK[(kb + tq + 4) * WK_LD + nb + g];
            mma_tf32(S[nt], qf[ks], b0, b1);
        }
    }

    // softmax (full 64-key row)
    float m0 = -1e30f, m1 = -1e30f;
#pragma unroll
    for (int nt = 0; nt < 8; ++nt) {
        m0 = fmaxf(m0, fmaxf(S[nt][0], S[nt][1]));
        m1 = fmaxf(m1, fmaxf(S[nt][2], S[nt][3]));
    }
    m0 = fmaxf(m0, __shfl_xor_sync(~0u, m0, 1));
    m0 = fmaxf(m0, __shfl_xor_sync(~0u, m0, 2));
    m1 = fmaxf(m1, __shfl_xor_sync(~0u, m1, 1));
    m1 = fmaxf(m1, __shfl_xor_sync(~0u, m1, 2));
    float l0 = 0.f, l1 = 0.f;
#pragma unroll
    for (int nt = 0; nt < 8; ++nt) {
        float p0 = __expf(S[nt][0] - m0);
        float p1 = __expf(S[nt][1] - m0);
        float p2 = __expf(S[nt][2] - m1);
        float p3 = __expf(S[nt][3] - m1);
        l0 += p0 + p1; l1 += p2 + p3;
        const int col = nt * 8 + tq * 2;
        sP[(qb + g) * WK_LD + col] = f2tf(p0);
        sP[(qb + g) * WK_LD + col + 1] = f2tf(p1);
        sP[(qb + 8 + g) * WK_LD + col] = f2tf(p2);
        sP[(qb + 8 + g) * WK_LD + col + 1] = f2tf(p3);
    }
    l0 += __shfl_xor_sync(~0u, l0, 1);
    l0 += __shfl_xor_sync(~0u, l0, 2);
    l1 += __shfl_xor_sync(~0u, l1, 1);
    l1 += __shfl_xor_sync(~0u, l1, 2);
    __syncwarp();

    // O = P V
    float O[4][4] = {};
#pragma unroll
    for (int ks = 0; ks < 8; ++ks) {
        const int kb = ks * 8;
        uint32_t af[4];
        af[0] = sP[(qb + g) * WK_LD + kb + tq];
        af[1] = sP[(qb + 8 + g) * WK_LD + kb + tq];
        af[2] = sP[(qb + g) * WK_LD + kb + tq + 4];
        af[3] = sP[(qb + 8 + g) * WK_LD + kb + tq + 4];
#pragma unroll
        for (int ntd = 0; ntd < 4; ++ntd) {
            const int nb = ntd * 8;
            uint32_t b0 = sV[(nb + g) * WK_LD + kb + tq];
            uint32_t b1 = sV[(nb + g) * WK_LD + kb + tq + 4];
            mma_tf32(O[ntd], af, b0, b1);
        }
    }

    // stage normalized O into smem as [d][token] (alias over sP)
    __syncthreads();
    float rl0 = 1.f / l0, rl1 = 1.f / l1;
    const int t0 = qb + g, t1 = qb + 8 + g;
#pragma unroll
    for (int ntd = 0; ntd < 4; ++ntd) {
        const int d0 = ntd * 8 + tq * 2;
        sO[d0 * WK_LD + t0] = O[ntd][0] * rl0;
        sO[(d0 + 1) * WK_LD + t0] = O[ntd][1] * rl0;
        sO[d0 * WK_LD + t1] = O[ntd][2] * rl1;
        sO[(d0 + 1) * WK_LD + t1] = O[ntd][3] * rl1;
    }
    __syncthreads();

    // vectorized epilogue: out = x + O, fused GN stats (slot 1)
    float s = 0.f, ss = 0.f;
#pragma unroll
    for (int ch = 0; ch < 4; ++ch) {
        int idx = tid + ch * 128;
        int d = idx >> 4;
        int si = (idx >> 1) & 7;
        int sj4 = (idx & 1) << 2;
        int tok = si * 8 + sj4;
        size_t ga = ((size_t)b * 256 + h * 32 + d) * (size_t)P
                    + (row0 + si) * W + col0 + sj4;
        float4 xv = *(const float4*)&x[ga];
        float4 ov = *(float4*)&sO[d * WK_LD + tok];
        float4 r;
        r.x = xv.x + ov.x; r.y = xv.y + ov.y;
        r.z = xv.z + ov.z; r.w = xv.w + ov.w;
        *(float4*)&out[ga] = r;
        s += r.x + r.y + r.z + r.w;
        ss = fmaf(r.x, r.x, ss);
        ss = fmaf(r.y, r.y, ss);
        ss = fmaf(r.z, r.z, ss);
        ss = fmaf(r.w, r.w, ss);
    }
#pragma unroll
    for (int o = 16; o > 0; o >>= 1) {
        s += __shfl_xor_sync(~0u, s, o);
        ss += __shfl_xor_sync(~0u, ss, o);
    }
    __shared__ float red[2][4];
    if (lane == 0) { red[0][warp] = s; red[1][warp] = ss; }
    __syncthreads();
    if (tid == 0) {
        float a = red[0][0] + red[0][1] + red[0][2] + red[0][3];
        float qq = red[1][0] + red[1][1] + red[1][2] + red[1][3];
        atomicAdd(&g_stats[1][2 * b], a);
        atomicAdd(&g_stats[1][2 * b + 1], qq);
    }
}

// ---------------- patch merge + LayerNorm ----------------
__global__ void patch_merge_ln_kernel(const float* __restrict__ gx,
                                      const float* __restrict__ lnw,
                                      const float* __restrict__ lnb,
                                      float* __restrict__ m_out) {
    int b = blockIdx.y;
    int p2 = blockIdx.x;
    int i = p2 >> 5, j = p2 & 31;
    int c = threadIdx.x;
    size_t base = ((size_t)b * 256 + c) * (size_t)P;
    int sp00 = (2 * i) * W + 2 * j;
    float v0 = gx[base + sp00];
    float v1 = gx[base + sp00 + W];
    float v2 = gx[base + sp00 + 1];
    float v3 = gx[base + sp00 + W + 1];

    float s = v0 + v1 + v2 + v3;
    float ss = v0 * v0 + v1 * v1 + v2 * v2 + v3 * v3;
#pragma unroll
    for (int o = 16; o > 0; o >>= 1) {
        s += __shfl_xor_sync(~0u, s, o);
        ss += __shfl_xor_sync(~0u, ss, o);
    }
    __shared__ float red[2][8];
    int lane = threadIdx.x & 31, wp = threadIdx.x >> 5;
    if (lane == 0) { red[0][wp] = s; red[1][wp] = ss; }
    __syncthreads();
    if (threadIdx.x < 32) {
        float a = threadIdx.x < 8 ? red[0][threadIdx.x] : 0.f;
        float q = threadIdx.x < 8 ? red[1][threadIdx.x] : 0.f;
#pragma unroll
        for (int o = 4; o > 0; o >>= 1) {
            a += __shfl_xor_sync(~0u, a, o);
            q += __shfl_xor_sync(~0u, q, o);
        }
        if (threadIdx.x == 0) { red[0][0] = a; red[1][0] = q; }
    }
    __syncthreads();
    float mean = red[0][0] * (1.f / 1024.f);
    float var = red[1][0] * (1.f / 1024.f) - mean * mean;
    float inv = rsqrtf(var + EPS_LN);

    size_t ob = (size_t)b * 1024 * (size_t)P2 + p2;
    m_out[ob + (size_t)(0 * 256 + c) * P2] = (v0 - mean) * inv * lnw[0 * 256 + c] + lnb[0 * 256 + c];
    m_out[ob + (size_t)(1 * 256 + c) * P2] = (v1 - mean) * inv * lnw[1 * 256 + c] + lnb[1 * 256 + c];
    m_out[ob + (size_t)(2 * 256 + c) * P2] = (v2 - mean) * inv * lnw[2 * 256 + c] + lnb[2 * 256 + c];
    m_out[ob + (size_t)(3 * 256 + c) * P2] = (v3 - mean) * inv * lnw[3 * 256 + c] + lnb[3 * 256 + c];
}

// ---------------- global attention: flash-style TF32 mma (lean smem) -------
// sQ staging and epilogue staging alias the sP region (Q frags live in regs
// before sP is first written; sP is dead by the epilogue).
constexpr int SQ_LD = 136;
constexpr int SK_LD = 72;
constexpr int GLOB_SMEM = (2 * 32 * SK_LD + 128 * SK_LD) * 4;  // 55.3 KB
__global__ __launch_bounds__(128, 3)
void glob_attn_mma_kernel(const float* __restrict__ qg,
                          const float* __restrict__ kv,
                          const float* __restrict__ gridx,
                          float* __restrict__ out) {
    extern __shared__ uint32_t smg[];
    uint32_t* sK = smg;                    // [32][72] tf32
    uint32_t* sV = sK + 32 * SK_LD;        // [32][72] tf32
    uint32_t* sP = sV + 32 * SK_LD;        // [128][72] tf32
    float* sQ = (float*)sP;                // alias: Q stage + epilogue stage

    const int b = blockIdx.z, h = blockIdx.y;
    const int q0 = blockIdx.x * 128;
    const int tid = threadIdx.x, warp = tid >> 5, lane = tid & 31;
    const int g = lane >> 2, tq = lane & 3;

    const size_t qbase = ((size_t)b * 256 + h * 32) * (size_t)P + q0;
    for (int i = tid; i < 32 * 32; i += 128) {
        int d = i >> 5, q4 = (i & 31) << 2;
        float4 v = *(const float4*)&qg[qbase + (size_t)d * P + q4];
        v.x *= SCALE; v.y *= SCALE; v.z *= SCALE; v.w *= SCALE;
        *(float4*)&sQ[d * SQ_LD + q4] = v;
    }
    __syncthreads();

    uint32_t qf[2][4][4];
#pragma unroll
    for (int mt = 0; mt < 2; ++mt) {
        const int qb = warp * 32 + mt * 16;
#pragma unroll
        for (int ks = 0; ks < 4; ++ks) {
            const int kb = ks * 8;
            qf[mt][ks][0] = f2tf(sQ[(kb + tq) * SQ_LD + qb + g]);
            qf[mt][ks][1] = f2tf(sQ[(kb + tq) * SQ_LD + qb + 8 + g]);
            qf[mt][ks][2] = f2tf(sQ[(kb + tq + 4) * SQ_LD + qb + g]);
            qf[mt][ks][3] = f2tf(sQ[(kb + tq + 4) * SQ_LD + qb + 8 + g]);
        }
    }

    float O[2][4][4] = {};
    float mrow[2][2], lrow[2][2];
#pragma unroll
    for (int mt = 0; mt < 2; ++mt) {
        mrow[mt][0] = mrow[mt][1] = -1e30f;
        lrow[mt][0] = lrow[mt][1] = 0.f;
    }

    const size_t kbase = ((size_t)b * 512 + h * 32) * (size_t)P2;
    const size_t vbase = kbase + (size_t)256 * P2;

    for (int t = 0; t < P2; t += 64) {
        __syncthreads();   // prev tile consumed; Q frags extracted (iter 0)
        for (int i = tid; i < 32 * 16; i += 128) {
            int d = i >> 4, c4 = (i & 15) << 2;
            float4 kk = *(const float4*)&kv[kbase + (size_t)d * P2 + t + c4];
            float4 vv = *(const float4*)&kv[vbase + (size_t)d * P2 + t + c4];
            uint4 ku = {f2tf(kk.x), f2tf(kk.y), f2tf(kk.z), f2tf(kk.w)};
            uint4 vu = {f2tf(vv.x), f2tf(vv.y), f2tf(vv.z), f2tf(vv.w)};
            *(uint4*)&sK[d * SK_LD + c4] = ku;
            *(uint4*)&sV[d * SK_LD + c4] = vu;
        }
        __syncthreads();

        float S[2][8][4];
#pragma unroll
        for (int nt = 0; nt < 8; ++nt) {
            const int nb = nt * 8;
            uint32_t b0[4], b1[4];
#pragma unroll
            for (int ks = 0; ks < 4; ++ks) {
                const int kb = ks * 8;
                b0[ks] = sK[(kb + tq) * SK_LD + nb + g];
                b1[ks] = sK[(kb + tq + 4) * SK_LD + nb + g];
            }
#pragma unroll
            for (int mt = 0; mt < 2; ++mt) {
                S[mt][nt][0] = S[mt][nt][1] = S[mt][nt][2] = S[mt][nt][3] = 0.f;
#pragma unroll
                for (int ks = 0; ks < 4; ++ks)
                    mma_tf32(S[mt][nt], qf[mt][ks], b0[ks], b1[ks]);
            }
        }

#pragma unroll
        for (int mt = 0; mt < 2; ++mt) {
            const int qb = warp * 32 + mt * 16;
            float tm0 = -1e30f, tm1 = -1e30f;
#pragma unroll
            for (int nt = 0; nt < 8; ++nt) {
                tm0 = fmaxf(tm0, fmaxf(S[mt][nt][0], S[mt][nt][1]));
                tm1 = fmaxf(tm1, fmaxf(S[mt][nt][2], S[mt][nt][3]));
            }
            tm0 = fmaxf(tm0, __shfl_xor_sync(~0u, tm0, 1));
            tm0 = fmaxf(tm0, __shfl_xor_sync(~0u, tm0, 2));
            tm1 = fmaxf(tm1, __shfl_xor_sync(~0u, tm1, 1));
            tm1 = fmaxf(tm1, __shfl_xor_sync(~0u, tm1, 2));
            float m0n = fmaxf(mrow[mt][0], tm0);
            float m1n = fmaxf(mrow[mt][1], tm1);
            float c0 = __expf(mrow[mt][0] - m0n);
            float c1 = __expf(mrow[mt][1] - m1n);
            mrow[mt][0] = m0n; mrow[mt][1] = m1n;
            float s0 = 0.f, s1 = 0.f;
#pragma unroll
            for (int nt = 0; nt < 8; ++nt) {
                float p0 = __expf(S[mt][nt][0] - m0n);
                float p1 = __expf(S[mt][nt][1] - m0n);
                float p2 = __expf(S[mt][nt][2] - m1n);
                float p3 = __expf(S[mt][nt][3] - m1n);
                s0 += p0 + p1; s1 += p2 + p3;
                const int col = nt * 8 + tq * 2;
                sP[(qb + g) * SK_LD + col] = f2tf(p0);
                sP[(qb + g) * SK_LD + col + 1] = f2tf(p1);
                sP[(qb + 8 + g) * SK_LD + col] = f2tf(p2);
                sP[(qb + 8 + g) * SK_LD + col + 1] = f2tf(p3);
            }
            s0 += __shfl_xor_sync(~0u, s0, 1);
            s0 += __shfl_xor_sync(~0u, s0, 2);
            s1 += __shfl_xor_sync(~0u, s1, 1);
            s1 += __shfl_xor_sync(~0u, s1, 2);
            lrow[mt][0] = lrow[mt][0] * c0 + s0;
            lrow[mt][1] = lrow[mt][1] * c1 + s1;
#pragma unroll
            for (int ntd = 0; ntd < 4; ++ntd) {
                O[mt][ntd][0] *= c0; O[mt][ntd][1] *= c0;
                O[mt][ntd][2] *= c1; O[mt][ntd][3] *= c1;
            }
        }
        __syncwarp();

#pragma unroll
        for (int ks = 0; ks < 8; ++ks) {
            const int kb = ks * 8;
            uint32_t af[2][4];
#pragma unroll
            for (int mt = 0; mt < 2; ++mt) {
                const int qb = warp * 32 + mt * 16;
                af[mt][0] = sP[(qb + g) * SK_LD + kb + tq];
                af[mt][1] = sP[(qb + 8 + g) * SK_LD + kb + tq];
                af[mt][2] = sP[(qb + g) * SK_LD + kb + tq + 4];
                af[mt][3] = sP[(qb + 8 + g) * SK_LD + kb + tq + 4];
            }
#pragma unroll
            for (int ntd = 0; ntd < 4; ++ntd) {
                const int nb = ntd * 8;
                uint32_t b0 = sV[(nb + g) * SK_LD + kb + tq];
                uint32_t b1 = sV[(nb + g) * SK_LD + kb + tq + 4];
#pragma unroll
                for (int mt = 0; mt < 2; ++mt)
                    mma_tf32(O[mt][ntd], af[mt], b0, b1);
            }
        }
    }

    __syncthreads();
#pragma unroll
    for (int mt = 0; mt < 2; ++mt) {
        const int qb = warp * 32 + mt * 16;
        float rl0 = 1.f / lrow[mt][0];
        float rl1 = 1.f / lrow[mt][1];
#pragma unroll
        for (int ntd = 0; ntd < 4; ++ntd) {
            const int d0 = ntd * 8 + tq * 2;
            sQ[(d0) * SQ_LD + qb + g] = O[mt][ntd][0] * rl0;
            sQ[(d0 + 1) * SQ_LD + qb + g] = O[mt][ntd][1] * rl0;
            sQ[(d0) * SQ_LD + qb + 8 + g] = O[mt][ntd][2] * rl1;
            sQ[(d0 + 1) * SQ_LD + qb + 8 + g] = O[mt][ntd][3] * rl1;
        }
    }
    __syncthreads();
    for (int i = tid; i < 32 * 32; i += 128) {
        int d = i >> 5, q4 = (i & 31) << 2;
        float4 o = *(float4*)&sQ[d * SQ_LD + q4];
        float4 r = *(const float4*)&gridx[qbase + (size_t)d * P + q4];
        o.x += r.x; o.y += r.y; o.z += r.z; o.w += r.w;
        *(float4*)&out[qbase + (size_t)d * P + q4] = o;
    }
}

// ---------------- host launcher ----------------
static float* sym_addr(const void* s) {
    void* p = nullptr;
    cudaGetSymbolAddress(&p, s);
    return (float*)p;
}

extern "C" void kernel_launch(void* const* d_in, const int* in_sizes, int n_in,
                              void* d_out, int out_size) {
    const float* x        = (const float*)d_in[0];
    const float* norm_w   = (const float*)d_in[1];
    const float* norm_b   = (const float*)d_in[2];
    const float* qkv_w    = (const float*)d_in[3];
    const float* qkv_b    = (const float*)d_in[4];
    const float* proj_w   = (const float*)d_in[5];
    const float* proj_b   = (const float*)d_in[6];
    const float* gridnw   = (const float*)d_in[7];
    const float* gridnb   = (const float*)d_in[8];
    const float* pm_ln_w  = (const float*)d_in[9];
    const float* pm_ln_b  = (const float*)d_in[10];
    const float* pm_red_w = (const float*)d_in[11];
    const float* ds_nw    = (const float*)d_in[12];
    const float* ds_nb    = (const float*)d_in[13];
    const float* q_w      = (const float*)d_in[14];
    const float* q_b      = (const float*)d_in[15];
    const float* kv_w     = (const float*)d_in[16];
    const float* kv_b     = (const float*)d_in[17];
    float* out = (float*)d_out;

    float* xn    = sym_addr(g_xn);
    float* qkv   = sym_addr(g_qkv);
    float* gridx = sym_addr(g_gridx);
    float* mbuf  = sym_addr(g_m);
    float* pm    = sym_addr(g_pm);
    float* qg    = sym_addr(g_qg);
    float* kvb   = sym_addr(g_kv);

    cudaFuncSetAttribute(win_attn_mma_kernel,
                         cudaFuncAttributeMaxDynamicSharedMemorySize, WIN_SMEM);
    cudaFuncSetAttribute(glob_attn_mma_kernel,
                         cudaFuncAttributeMaxDynamicSharedMemorySize, GLOB_SMEM);

    dim3 gnGrid(64, BATCH);

    zero_stats_kernel<<<1, 32>>>();

    // ---- stage 1: stats(x); qkv = conv1x1(GN(x)) with GN fused in GEMM ----
    gn_stats_kernel<<<gnGrid, 256>>>(x, C * P, 0);
    gemm_tf32_kernel<<<dim3(P / 128, 768 / 128, BATCH), 256>>>(
        qkv_w, x, qkv_b, qkv, 768, P, C, norm_w, norm_b, 0);

    // ---- stage 2: windowed attention + residual + fused stats; GN apply ----
    win_attn_mma_kernel<<<dim3(64, NH, BATCH), 128, WIN_SMEM>>>(qkv, x, gridx);
    gn_apply_kernel<<<gnGrid, 256>>>(gridx, gridnw, gridnb, gridx, P, C * P, EPS_GN, 1);

    // ---- stage 3: patch merge + LN; pm reduction GEMM ----
    patch_merge_ln_kernel<<<dim3(P2, BATCH), 256>>>(gridx, pm_ln_w, pm_ln_b, mbuf);
    gemm_tf32_kernel<<<dim3(P2 / 128, C / 128, BATCH), 256>>>(
        pm_red_w, mbuf, nullptr, pm, C, P2, 4 * C, nullptr, nullptr, -1);

    // ---- stage 4: stats(pm); q/kv projections (kv GEMM fuses GN(pm)) ----
    gn_stats_kernel<<<gnGrid, 256>>>(pm, C * P2, 2);
    gemm_tf32_kernel<<<dim3(P / 128, C / 128, BATCH), 256>>>(
        q_w, gridx, q_b, qg, C, P, C, nullptr, nullptr, -1);
    gemm_tf32_kernel<<<dim3(P2 / 128, 512 / 128, BATCH), 256>>>(
        kv_w, pm, kv_b, kvb, 512, P2, C, ds_nw, ds_nb, 2);

    // ---- stage 5: global attention + residual ----
    glob_attn_mma_kernel<<<dim3(P / 128, NH, BATCH), 128, GLOB_SMEM>>>(qg, kvb, gridx, xn);

    // ---- stage 6: proj ----
    gemm_tf32_kernel<<<dim3(P / 128, C / 128, BATCH), 256>>>(
        proj_w, xn, proj_b, out, C, P, C, nullptr, nullptr, -1);
}

// round 7
// speedup vs baseline: 4.0328x; 1.0844x over previous
#include <cuda_runtime.h>
#include <math.h>
#include <stdint.h>

// ---------------- problem constants ----------------
constexpr int BATCH = 4;
constexpr int C = 256;
constexpr int H = 64, W = 64;
constexpr int P = H * W;              // 4096
constexpr int NH = 8, HD = 32;
constexpr int P2 = (H / 2) * (W / 2); // 1024
constexpr float SCALE = 0.1767766952966369f; // 32^-0.5
constexpr float EPS_GN = 1e-6f;
constexpr float EPS_LN = 1e-5f;

// ---------------- scratch (device globals) ----------
// stats slots: 0 = x (stage1), 1 = gridx raw (stage2), 2 = pm (stage4)
__device__ float g_stats[3][2 * BATCH];
__device__ float g_xn[BATCH * C * P];     // global_x scratch
__device__ float g_qkv[BATCH * 3 * C * P];
__device__ float g_gridx[BATCH * C * P];  // x + win_attn out (RAW, pre-GN)
__device__ float g_m[BATCH * 4 * C * P2];
__device__ float g_pm[BATCH * C * P2];
__device__ float g_qg[BATCH * C * P];
__device__ float g_kv[BATCH * 2 * C * P2];

// ---------------- mma helpers ----------------
__device__ __forceinline__ uint32_t f2tf(float f) {
    uint32_t u;
    asm("cvt.rna.tf32.f32 %0, %1;" : "=r"(u) : "f"(f));
    return u;
}
__device__ __forceinline__ void mma_tf32(float* c, const uint32_t* a,
                                         uint32_t b0, uint32_t b1) {
    asm volatile(
        "mma.sync.aligned.m16n8k8.row.col.f32.tf32.tf32.f32 "
        "{%0,%1,%2,%3}, {%4,%5,%6,%7}, {%8,%9}, {%0,%1,%2,%3};"
        : "+f"(c[0]), "+f"(c[1]), "+f"(c[2]), "+f"(c[3])
        : "r"(a[0]), "r"(a[1]), "r"(a[2]), "r"(a[3]), "r"(b0), "r"(b1));
}

// ---------------- GroupNorm helpers ----------------
__global__ void zero_stats_kernel() {
    if (threadIdx.x < 3 * 2 * BATCH) ((float*)g_stats)[threadIdx.x] = 0.f;
}

__global__ void gn_stats_kernel(const float* __restrict__ x, int per_batch, int slot) {
    int b = blockIdx.y;
    const float* xb = x + (size_t)b * per_batch;
    float s = 0.f, ss = 0.f;
    for (int i = blockIdx.x * blockDim.x + threadIdx.x; i < per_batch;
         i += gridDim.x * blockDim.x) {
        float v = xb[i];
        s += v;
        ss = fmaf(v, v, ss);
    }
#pragma unroll
    for (int o = 16; o > 0; o >>= 1) {
        s += __shfl_xor_sync(~0u, s, o);
        ss += __shfl_xor_sync(~0u, ss, o);
    }
    __shared__ float red[2][8];
    int lane = threadIdx.x & 31, wp = threadIdx.x >> 5;
    if (lane == 0) { red[0][wp] = s; red[1][wp] = ss; }
    __syncthreads();
    if (threadIdx.x < 32) {
        float a = threadIdx.x < 8 ? red[0][threadIdx.x] : 0.f;
        float q = threadIdx.x < 8 ? red[1][threadIdx.x] : 0.f;
#pragma unroll
        for (int o = 4; o > 0; o >>= 1) {
            a += __shfl_xor_sync(~0u, a, o);
            q += __shfl_xor_sync(~0u, q, o);
        }
        if (threadIdx.x == 0) {
            atomicAdd(&g_stats[slot][2 * b], a);
            atomicAdd(&g_stats[slot][2 * b + 1], q);
        }
    }
}

// ---------------- TF32 GEMM (fused GN on B, optional fused stats on C) -----
constexpr int GEMM_LDS = 136;
__global__ __launch_bounds__(256, 2)
void gemm_tf32_kernel(const float* __restrict__ A,
                      const float* __restrict__ Bm,
                      const float* __restrict__ bias,
                      float* __restrict__ Cm,
                      int M, int N, int K,
                      const float* __restrict__ gnw,
                      const float* __restrict__ gnb,
                      int slot,
                      int stats_out) {
    const int b = blockIdx.z;
    Bm += (size_t)b * K * N;
    Cm += (size_t)b * M * N;
    __shared__ uint32_t As[16 * GEMM_LDS];
    __shared__ uint32_t Bs[16 * GEMM_LDS];
    const int tid = threadIdx.x;
    const int warp = tid >> 5, lane = tid & 31;
    const int wm = warp >> 2, wn = warp & 3;
    const int g = lane >> 2, tq = lane & 3;
    const int m0 = blockIdx.y * 128, n0 = blockIdx.x * 128;
    const int ar = tid >> 2;
    const int ac = (tid & 3) << 2;
    const int br = tid >> 5;
    const int bc = lane << 2;

    float mean = 0.f, inv = 0.f;
    if (gnw) {
        float cnt = (float)K * (float)N;
        mean = g_stats[slot][2 * b] / cnt;
        float var = g_stats[slot][2 * b + 1] / cnt - mean * mean;
        inv = rsqrtf(var + EPS_GN);
    }

    const float* Aplo = &A[(size_t)(m0 + ar) * K + ac];
    const float* Aphi = &A[(size_t)(m0 + ar + 64) * K + ac];
    const float* Bplo = &Bm[(size_t)br * N + n0 + bc];
    const float* Bphi = &Bm[(size_t)(br + 8) * N + n0 + bc];

    float4 a0v = *(const float4*)Aplo;
    float4 a1v = *(const float4*)Aphi;
    float4 b0v = *(const float4*)Bplo;
    float4 b1v = *(const float4*)Bphi;

    float acc[4][4][4] = {};
    const int ntile = K >> 4;
#pragma unroll 1
    for (int i = 0; i < ntile; ++i) {
        __syncthreads();
        As[(ac + 0) * GEMM_LDS + ar] = f2tf(a0v.x);
        As[(ac + 1) * GEMM_LDS + ar] = f2tf(a0v.y);
        As[(ac + 2) * GEMM_LDS + ar] = f2tf(a0v.z);
        As[(ac + 3) * GEMM_LDS + ar] = f2tf(a0v.w);
        As[(ac + 0) * GEMM_LDS + ar + 64] = f2tf(a1v.x);
        As[(ac + 1) * GEMM_LDS + ar + 64] = f2tf(a1v.y);
        As[(ac + 2) * GEMM_LDS + ar + 64] = f2tf(a1v.z);
        As[(ac + 3) * GEMM_LDS + ar + 64] = f2tf(a1v.w);
        if (gnw) {
            int k0r = i * 16 + br;
            float al0 = inv * gnw[k0r], be0 = gnb[k0r] - mean * al0;
            float al1 = inv * gnw[k0r + 8], be1 = gnb[k0r + 8] - mean * al1;
            uint4 bu0 = {f2tf(fmaf(b0v.x, al0, be0)), f2tf(fmaf(b0v.y, al0, be0)),
                         f2tf(fmaf(b0v.z, al0, be0)), f2tf(fmaf(b0v.w, al0, be0))};
            uint4 bu1 = {f2tf(fmaf(b1v.x, al1, be1)), f2tf(fmaf(b1v.y, al1, be1)),
                         f2tf(fmaf(b1v.z, al1, be1)), f2tf(fmaf(b1v.w, al1, be1))};
            *(uint4*)&Bs[br * GEMM_LDS + bc] = bu0;
            *(uint4*)&Bs[(br + 8) * GEMM_LDS + bc] = bu1;
        } else {
            uint4 bu0 = {f2tf(b0v.x), f2tf(b0v.y), f2tf(b0v.z), f2tf(b0v.w)};
            uint4 bu1 = {f2tf(b1v.x), f2tf(b1v.y), f2tf(b1v.z), f2tf(b1v.w)};
            *(uint4*)&Bs[br * GEMM_LDS + bc] = bu0;
            *(uint4*)&Bs[(br + 8) * GEMM_LDS + bc] = bu1;
        }
        __syncthreads();
        if (i + 1 < ntile) {
            const int k1 = (i + 1) << 4;
            a0v = *(const float4*)(Aplo + k1);
            a1v = *(const float4*)(Aphi + k1);
            b0v = *(const float4*)(Bplo + (size_t)k1 * N);
            b1v = *(const float4*)(Bphi + (size_t)k1 * N);
        }
#pragma unroll
        for (int ks = 0; ks < 2; ++ks) {
            const int kb = ks * 8;
            uint32_t af[4][4];
            uint32_t bf[4][2];
#pragma unroll
            for (int mt = 0; mt < 4; ++mt) {
                const int mb = wm * 64 + mt * 16;
                af[mt][0] = As[(kb + tq) * GEMM_LDS + mb + g];
                af[mt][1] = As[(kb + tq) * GEMM_LDS + mb + 8 + g];
                af[mt][2] = As[(kb + tq + 4) * GEMM_LDS + mb + g];
                af[mt][3] = As[(kb + tq + 4) * GEMM_LDS + mb + 8 + g];
            }
#pragma unroll
            for (int nt = 0; nt < 4; ++nt) {
                const int nb = wn * 32 + nt * 8;
                bf[nt][0] = Bs[(kb + tq) * GEMM_LDS + nb + g];
                bf[nt][1] = Bs[(kb + tq + 4) * GEMM_LDS + nb + g];
            }
#pragma unroll
            for (int mt = 0; mt < 4; ++mt)
#pragma unroll
                for (int nt = 0; nt < 4; ++nt)
                    mma_tf32(acc[mt][nt], af[mt], bf[nt][0], bf[nt][1]);
        }
    }
    float s = 0.f, ssq = 0.f;
#pragma unroll
    for (int mt = 0; mt < 4; ++mt) {
#pragma unroll
        for (int nt = 0; nt < 4; ++nt) {
            int row = m0 + wm * 64 + mt * 16 + g;
            int col = n0 + wn * 32 + nt * 8 + tq * 2;
            float bv0 = bias ? bias[row] : 0.f;
            float bv1 = bias ? bias[row + 8] : 0.f;
            float2 o0 = {acc[mt][nt][0] + bv0, acc[mt][nt][1] + bv0};
            float2 o1 = {acc[mt][nt][2] + bv1, acc[mt][nt][3] + bv1};
            *(float2*)&Cm[(size_t)row * N + col] = o0;
            *(float2*)&Cm[(size_t)(row + 8) * N + col] = o1;
            if (stats_out >= 0) {
                s += o0.x + o0.y + o1.x + o1.y;
                ssq = fmaf(o0.x, o0.x, ssq);
                ssq = fmaf(o0.y, o0.y, ssq);
                ssq = fmaf(o1.x, o1.x, ssq);
                ssq = fmaf(o1.y, o1.y, ssq);
            }
        }
    }
    if (stats_out >= 0) {
#pragma unroll
        for (int o = 16; o > 0; o >>= 1) {
            s += __shfl_xor_sync(~0u, s, o);
            ssq += __shfl_xor_sync(~0u, ssq, o);
        }
        __shared__ float red[2][8];
        if (lane == 0) { red[0][warp] = s; red[1][warp] = ssq; }
        __syncthreads();
        if (tid < 32) {
            float a = tid < 8 ? red[0][tid] : 0.f;
            float q = tid < 8 ? red[1][tid] : 0.f;
#pragma unroll
            for (int o = 4; o > 0; o >>= 1) {
                a += __shfl_xor_sync(~0u, a, o);
                q += __shfl_xor_sync(~0u, q, o);
            }
            if (tid == 0) {
                atomicAdd(&g_stats[stats_out][2 * b], a);
                atomicAdd(&g_stats[stats_out][2 * b + 1], q);
            }
        }
    }
}

// ---------------- windowed 8x8 attention via TF32 mma (vectorized I/O) ------
constexpr int WK_LD = 72;
constexpr int WIN_SMEM = (3 * 32 * WK_LD + 64 * WK_LD) * 4;
__global__ __launch_bounds__(128, 4)
void win_attn_mma_kernel(const float* __restrict__ qkv,
                         const float* __restrict__ x,
                         float* __restrict__ out) {
    extern __shared__ uint32_t smu[];
    uint32_t* sQ = smu;                  // [32][72] tf32, [d][token]
    uint32_t* sK = smu + 32 * WK_LD;     // [32][72]
    uint32_t* sV = sK + 32 * WK_LD;      // [32][72]
    uint32_t* sP = sV + 32 * WK_LD;      // [64][72] probs; later O staging
    float* sO = (float*)sP;              // epilogue alias

    const int win = blockIdx.x;
    const int gi = win >> 3, gj = win & 7;
    const int h = blockIdx.y;
    const int b = blockIdx.z;
    const int tid = threadIdx.x, warp = tid >> 5, lane = tid & 31;
    const int g = lane >> 2, tq = lane & 3;

    const int row0 = gi * 8;
    const int col0 = gj * 8;
    const size_t qkb = ((size_t)b * 768 + h * 32) * (size_t)P;

#pragma unroll
    for (int ch = 0; ch < 4; ++ch) {
        int idx = tid + ch * 128;
        int d = idx >> 4;
        int si = (idx >> 1) & 7;
        int sj4 = (idx & 1) << 2;
        int tok = si * 8 + sj4;
        size_t ga = qkb + (size_t)d * P + (row0 + si) * W + col0 + sj4;
        float4 qv = *(const float4*)&qkv[ga];
        float4 kv4 = *(const float4*)&qkv[ga + (size_t)256 * P];
        float4 vv = *(const float4*)&qkv[ga + (size_t)512 * P];
        uint4 qu = {f2tf(qv.x * SCALE), f2tf(qv.y * SCALE),
                    f2tf(qv.z * SCALE), f2tf(qv.w * SCALE)};
        uint4 ku = {f2tf(kv4.x), f2tf(kv4.y), f2tf(kv4.z), f2tf(kv4.w)};
        uint4 vu = {f2tf(vv.x), f2tf(vv.y), f2tf(vv.z), f2tf(vv.w)};
        *(uint4*)&sQ[d * WK_LD + tok] = qu;
        *(uint4*)&sK[d * WK_LD + tok] = ku;
        *(uint4*)&sV[d * WK_LD + tok] = vu;
    }
    __syncthreads();

    const int qb = warp * 16;
    uint32_t qf[4][4];
#pragma unroll
    for (int ks = 0; ks < 4; ++ks) {
        const int kb = ks * 8;
        qf[ks][0] = sQ[(kb + tq) * WK_LD + qb + g];
        qf[ks][1] = sQ[(kb + tq) * WK_LD + qb + 8 + g];
        qf[ks][2] = sQ[(kb + tq + 4) * WK_LD + qb + g];
        qf[ks][3] = sQ[(kb + tq + 4) * WK_LD + qb + 8 + g];
    }

    float S[8][4];
#pragma unroll
    for (int nt = 0; nt < 8; ++nt) {
        const int nb = nt * 8;
        S[nt][0] = S[nt][1] = S[nt][2] = S[nt][3] = 0.f;
#pragma unroll
        for (int ks = 0; ks < 4; ++ks) {
            const int kb = ks * 8;
            uint32_t b0 = sK[(kb + tq) * WK_LD + nb + g];
            uint32_t b1 = sK[(kb + tq + 4) * WK_LD + nb + g];
            mma_tf32(S[nt], qf[ks], b0, b1);
        }
    }

    float m0 = -1e30f, m1 = -1e30f;
#pragma unroll
    for (int nt = 0; nt < 8; ++nt) {
        m0 = fmaxf(m0, fmaxf(S[nt][0], S[nt][1]));
        m1 = fmaxf(m1, fmaxf(S[nt][2], S[nt][3]));
    }
    m0 = fmaxf(m0, __shfl_xor_sync(~0u, m0, 1));
    m0 = fmaxf(m0, __shfl_xor_sync(~0u, m0, 2));
    m1 = fmaxf(m1, __shfl_xor_sync(~0u, m1, 1));
    m1 = fmaxf(m1, __shfl_xor_sync(~0u, m1, 2));
    float l0 = 0.f, l1 = 0.f;
#pragma unroll
    for (int nt = 0; nt < 8; ++nt) {
        float p0 = __expf(S[nt][0] - m0);
        float p1 = __expf(S[nt][1] - m0);
        float p2 = __expf(S[nt][2] - m1);
        float p3 = __expf(S[nt][3] - m1);
        l0 += p0 + p1; l1 += p2 + p3;
        const int col = nt * 8 + tq * 2;
        sP[(qb + g) * WK_LD + col] = f2tf(p0);
        sP[(qb + g) * WK_LD + col + 1] = f2tf(p1);
        sP[(qb + 8 + g) * WK_LD + col] = f2tf(p2);
        sP[(qb + 8 + g) * WK_LD + col + 1] = f2tf(p3);
    }
    l0 += __shfl_xor_sync(~0u, l0, 1);
    l0 += __shfl_xor_sync(~0u, l0, 2);
    l1 += __shfl_xor_sync(~0u, l1, 1);
    l1 += __shfl_xor_sync(~0u, l1, 2);
    __syncwarp();

    float O[4][4] = {};
#pragma unroll
    for (int ks = 0; ks < 8; ++ks) {
        const int kb = ks * 8;
        uint32_t af[4];
        af[0] = sP[(qb + g) * WK_LD + kb + tq];
        af[1] = sP[(qb + 8 + g) * WK_LD + kb + tq];
        af[2] = sP[(qb + g) * WK_LD + kb + tq + 4];
        af[3] = sP[(qb + 8 + g) * WK_LD + kb + tq + 4];
#pragma unroll
        for (int ntd = 0; ntd < 4; ++ntd) {
            const int nb = ntd * 8;
            uint32_t b0 = sV[(nb + g) * WK_LD + kb + tq];
            uint32_t b1 = sV[(nb + g) * WK_LD + kb + tq + 4];
            mma_tf32(O[ntd], af, b0, b1);
        }
    }

    __syncthreads();
    float rl0 = 1.f / l0, rl1 = 1.f / l1;
    const int t0 = qb + g, t1 = qb + 8 + g;
#pragma unroll
    for (int ntd = 0; ntd < 4; ++ntd) {
        const int d0 = ntd * 8 + tq * 2;
        sO[d0 * WK_LD + t0] = O[ntd][0] * rl0;
        sO[(d0 + 1) * WK_LD + t0] = O[ntd][1] * rl0;
        sO[d0 * WK_LD + t1] = O[ntd][2] * rl1;
        sO[(d0 + 1) * WK_LD + t1] = O[ntd][3] * rl1;
    }
    __syncthreads();

    float s = 0.f, ss = 0.f;
#pragma unroll
    for (int ch = 0; ch < 4; ++ch) {
        int idx = tid + ch * 128;
        int d = idx >> 4;
        int si = (idx >> 1) & 7;
        int sj4 = (idx & 1) << 2;
        int tok = si * 8 + sj4;
        size_t ga = ((size_t)b * 256 + h * 32 + d) * (size_t)P
                    + (row0 + si) * W + col0 + sj4;
        float4 xv = *(const float4*)&x[ga];
        float4 ov = *(float4*)&sO[d * WK_LD + tok];
        float4 r;
        r.x = xv.x + ov.x; r.y = xv.y + ov.y;
        r.z = xv.z + ov.z; r.w = xv.w + ov.w;
        *(float4*)&out[ga] = r;
        s += r.x + r.y + r.z + r.w;
        ss = fmaf(r.x, r.x, ss);
        ss = fmaf(r.y, r.y, ss);
        ss = fmaf(r.z, r.z, ss);
        ss = fmaf(r.w, r.w, ss);
    }
#pragma unroll
    for (int o = 16; o > 0; o >>= 1) {
        s += __shfl_xor_sync(~0u, s, o);
        ss += __shfl_xor_sync(~0u, ss, o);
    }
    __shared__ float red[2][4];
    if (lane == 0) { red[0][warp] = s; red[1][warp] = ss; }
    __syncthreads();
    if (tid == 0) {
        float a = red[0][0] + red[0][1] + red[0][2] + red[0][3];
        float qq = red[1][0] + red[1][1] + red[1][2] + red[1][3];
        atomicAdd(&g_stats[1][2 * b], a);
        atomicAdd(&g_stats[1][2 * b + 1], qq);
    }
}

// ---------------- patch merge + LN (vectorized, fused GN on gridx) ---------
// grid (8 col-groups, 32 rows, BATCH); 256 threads (one per channel).
// Each block produces 4 consecutive p2 positions; float4 I/O throughout.
__global__ __launch_bounds__(256)
void patch_merge_ln_kernel(const float* __restrict__ gx,
                           const float* __restrict__ gnw,
                           const float* __restrict__ gnb,
                           const float* __restrict__ lnw,
                           const float* __restrict__ lnb,
                           float* __restrict__ m_out) {
    const int jg = blockIdx.x;   // 0..7
    const int i = blockIdx.y;    // 0..31 (output row)
    const int b = blockIdx.z;
    const int c = threadIdx.x;

    float cnt = (float)(C * P);
    float mean = g_stats[1][2 * b] / cnt;
    float var = g_stats[1][2 * b + 1] / cnt - mean * mean;
    float inv = rsqrtf(var + EPS_GN);
    float al = inv * gnw[c];
    float be = gnb[c] - mean * al;

    size_t ga = ((size_t)b * 256 + c) * (size_t)P + (2 * i) * W + 8 * jg;
    float4 r0a = *(const float4*)&gx[ga];
    float4 r0b = *(const float4*)&gx[ga + 4];
    float4 r1a = *(const float4*)&gx[ga + W];
    float4 r1b = *(const float4*)&gx[ga + W + 4];
#define GN4(v) v.x = fmaf(v.x, al, be); v.y = fmaf(v.y, al, be); \
               v.z = fmaf(v.z, al, be); v.w = fmaf(v.w, al, be);
    GN4(r0a) GN4(r0b) GN4(r1a) GN4(r1b)
#undef GN4

    // per-p2 feature values: v0=(even,even) v1=(odd,even) v2=(even,odd) v3=(odd,odd)
    float v0[4] = {r0a.x, r0a.z, r0b.x, r0b.z};
    float v1[4] = {r1a.x, r1a.z, r1b.x, r1b.z};
    float v2[4] = {r0a.y, r0a.w, r0b.y, r0b.w};
    float v3[4] = {r1a.y, r1a.w, r1b.y, r1b.w};

    float s[4], ss[4];
#pragma unroll
    for (int t = 0; t < 4; ++t) {
        s[t] = v0[t] + v1[t] + v2[t] + v3[t];
        ss[t] = v0[t] * v0[t] + v1[t] * v1[t] + v2[t] * v2[t] + v3[t] * v3[t];
    }
#pragma unroll
    for (int t = 0; t < 4; ++t) {
#pragma unroll
        for (int o = 16; o > 0; o >>= 1) {
            s[t] += __shfl_xor_sync(~0u, s[t], o);
            ss[t] += __shfl_xor_sync(~0u, ss[t], o);
        }
    }
    __shared__ float red[2][8][4];
    const int lane = c & 31, wp = c >> 5;
    if (lane == 0) {
#pragma unroll
        for (int t = 0; t < 4; ++t) { red[0][wp][t] = s[t]; red[1][wp][t] = ss[t]; }
    }
    __syncthreads();
    __shared__ float smean[4], sinv[4];
    if (c < 4) {
        float a = 0.f, q = 0.f;
#pragma unroll
        for (int w8 = 0; w8 < 8; ++w8) { a += red[0][w8][c]; q += red[1][w8][c]; }
        float mu = a * (1.f / 1024.f);
        smean[c] = mu;
        sinv[c] = rsqrtf(q * (1.f / 1024.f) - mu * mu + EPS_LN);
    }
    __syncthreads();

    const size_t ob = (size_t)b * 1024 * (size_t)P2 + i * 32 + jg * 4;
#pragma unroll
    for (int q = 0; q < 4; ++q) {
        const int k = q * 256 + c;
        const float w_ = lnw[k], bb = lnb[k];
        const float* vq = (q == 0) ? v0 : (q == 1) ? v1 : (q == 2) ? v2 : v3;
        float4 o;
        o.x = (vq[0] - smean[0]) * sinv[0] * w_ + bb;
        o.y = (vq[1] - smean[1]) * sinv[1] * w_ + bb;
        o.z = (vq[2] - smean[2]) * sinv[2] * w_ + bb;
        o.w = (vq[3] - smean[3]) * sinv[3] * w_ + bb;
        *(float4*)&m_out[ob + (size_t)k * P2] = o;
    }
}

// ---------------- global attention: flash-style TF32 mma (lean smem) -------
// Residual input gridx is RAW; GN(slot 1) fused into the epilogue.
constexpr int SQ_LD = 136;
constexpr int SK_LD = 72;
constexpr int GLOB_SMEM = (2 * 32 * SK_LD + 128 * SK_LD) * 4;  // 54 KB
__global__ __launch_bounds__(128, 3)
void glob_attn_mma_kernel(const float* __restrict__ qg,
                          const float* __restrict__ kv,
                          const float* __restrict__ gridx,
                          const float* __restrict__ gnw,
                          const float* __restrict__ gnb,
                          float* __restrict__ out) {
    extern __shared__ uint32_t smg[];
    uint32_t* sK = smg;
    uint32_t* sV = sK + 32 * SK_LD;
    uint32_t* sP = sV + 32 * SK_LD;
    float* sQ = (float*)sP;

    const int b = blockIdx.z, h = blockIdx.y;
    const int q0 = blockIdx.x * 128;
    const int tid = threadIdx.x, warp = tid >> 5, lane = tid & 31;
    const int g = lane >> 2, tq = lane & 3;

    const size_t qbase = ((size_t)b * 256 + h * 32) * (size_t)P + q0;
    for (int i = tid; i < 32 * 32; i += 128) {
        int d = i >> 5, q4 = (i & 31) << 2;
        float4 v = *(const float4*)&qg[qbase + (size_t)d * P + q4];
        v.x *= SCALE; v.y *= SCALE; v.z *= SCALE; v.w *= SCALE;
        *(float4*)&sQ[d * SQ_LD + q4] = v;
    }
    __syncthreads();

    uint32_t qf[2][4][4];
#pragma unroll
    for (int mt = 0; mt < 2; ++mt) {
        const int qb = warp * 32 + mt * 16;
#pragma unroll
        for (int ks = 0; ks < 4; ++ks) {
            const int kb = ks * 8;
            qf[mt][ks][0] = f2tf(sQ[(kb + tq) * SQ_LD + qb + g]);
            qf[mt][ks][1] = f2tf(sQ[(kb + tq) * SQ_LD + qb + 8 + g]);
            qf[mt][ks][2] = f2tf(sQ[(kb + tq + 4) * SQ_LD + qb + g]);
            qf[mt][ks][3] = f2tf(sQ[(kb + tq + 4) * SQ_LD + qb + 8 + g]);
        }
    }

    float O[2][4][4] = {};
    float mrow[2][2], lrow[2][2];
#pragma unroll
    for (int mt = 0; mt < 2; ++mt) {
        mrow[mt][0] = mrow[mt][1] = -1e30f;
        lrow[mt][0] = lrow[mt][1] = 0.f;
    }

    const size_t kbase = ((size_t)b * 512 + h * 32) * (size_t)P2;
    const size_t vbase = kbase + (size_t)256 * P2;

    for (int t = 0; t < P2; t += 64) {
        __syncthreads();
        for (int i = tid; i < 32 * 16; i += 128) {
            int d = i >> 4, c4 = (i & 15) << 2;
            float4 kk = *(const float4*)&kv[kbase + (size_t)d * P2 + t + c4];
            float4 vv = *(const float4*)&kv[vbase + (size_t)d * P2 + t + c4];
            uint4 ku = {f2tf(kk.x), f2tf(kk.y), f2tf(kk.z), f2tf(kk.w)};
            uint4 vu = {f2tf(vv.x), f2tf(vv.y), f2tf(vv.z), f2tf(vv.w)};
            *(uint4*)&sK[d * SK_LD + c4] = ku;
            *(uint4*)&sV[d * SK_LD + c4] = vu;
        }
        __syncthreads();

        float S[2][8][4];
#pragma unroll
        for (int nt = 0; nt < 8; ++nt) {
            const int nb = nt * 8;
            uint32_t b0[4], b1[4];
#pragma unroll
            for (int ks = 0; ks < 4; ++ks) {
                const int kb = ks * 8;
                b0[ks] = sK[(kb + tq) * SK_LD + nb + g];
                b1[ks] = sK[(kb + tq + 4) * SK_LD + nb + g];
            }
#pragma unroll
            for (int mt = 0; mt < 2; ++mt) {
                S[mt][nt][0] = S[mt][nt][1] = S[mt][nt][2] = S[mt][nt][3] = 0.f;
#pragma unroll
                for (int ks = 0; ks < 4; ++ks)
                    mma_tf32(S[mt][nt], qf[mt][ks], b0[ks], b1[ks]);
            }
        }

#pragma unroll
        for (int mt = 0; mt < 2; ++mt) {
            const int qb = warp * 32 + mt * 16;
            float tm0 = -1e30f, tm1 = -1e30f;
#pragma unroll
            for (int nt = 0; nt < 8; ++nt) {
                tm0 = fmaxf(tm0, fmaxf(S[mt][nt][0], S[mt][nt][1]));
                tm1 = fmaxf(tm1, fmaxf(S[mt][nt][2], S[mt][nt][3]));
            }
            tm0 = fmaxf(tm0, __shfl_xor_sync(~0u, tm0, 1));
            tm0 = fmaxf(tm0, __shfl_xor_sync(~0u, tm0, 2));
            tm1 = fmaxf(tm1, __shfl_xor_sync(~0u, tm1, 1));
            tm1 = fmaxf(tm1, __shfl_xor_sync(~0u, tm1, 2));
            float m0n = fmaxf(mrow[mt][0], tm0);
            float m1n = fmaxf(mrow[mt][1], tm1);
            float c0 = __expf(mrow[mt][0] - m0n);
            float c1 = __expf(mrow[mt][1] - m1n);
            mrow[mt][0] = m0n; mrow[mt][1] = m1n;
            float s0 = 0.f, s1 = 0.f;
#pragma unroll
            for (int nt = 0; nt < 8; ++nt) {
                float p0 = __expf(S[mt][nt][0] - m0n);
                float p1 = __expf(S[mt][nt][1] - m0n);
                float p2 = __expf(S[mt][nt][2] - m1n);
                float p3 = __expf(S[mt][nt][3] - m1n);
                s0 += p0 + p1; s1 += p2 + p3;
                const int col = nt * 8 + tq * 2;
                sP[(qb + g) * SK_LD + col] = f2tf(p0);
                sP[(qb + g) * SK_LD + col + 1] = f2tf(p1);
                sP[(qb + 8 + g) * SK_LD + col] = f2tf(p2);
                sP[(qb + 8 + g) * SK_LD + col + 1] = f2tf(p3);
            }
            s0 += __shfl_xor_sync(~0u, s0, 1);
            s0 += __shfl_xor_sync(~0u, s0, 2);
            s1 += __shfl_xor_sync(~0u, s1, 1);
            s1 += __shfl_xor_sync(~0u, s1, 2);
            lrow[mt][0] = lrow[mt][0] * c0 + s0;
            lrow[mt][1] = lrow[mt][1] * c1 + s1;
#pragma unroll
            for (int ntd = 0; ntd < 4; ++ntd) {
                O[mt][ntd][0] *= c0; O[mt][ntd][1] *= c0;
                O[mt][ntd][2] *= c1; O[mt][ntd][3] *= c1;
            }
        }
        __syncwarp();

#pragma unroll
        for (int ks = 0; ks < 8; ++ks) {
            const int kb = ks * 8;
            uint32_t af[2][4];
#pragma unroll
            for (int mt = 0; mt < 2; ++mt) {
                const int qb = warp * 32 + mt * 16;
                af[mt][0] = sP[(qb + g) * SK_LD + kb + tq];
                af[mt][1] = sP[(qb + 8 + g) * SK_LD + kb + tq];
                af[mt][2] = sP[(qb + g) * SK_LD + kb + tq + 4];
                af[mt][3] = sP[(qb + 8 + g) * SK_LD + kb + tq + 4];
            }
#pragma unroll
            for (int ntd = 0; ntd < 4; ++ntd) {
                const int nb = ntd * 8;
                uint32_t b0 = sV[(nb + g) * SK_LD + kb + tq];
                uint32_t b1 = sV[(nb + g) * SK_LD + kb + tq + 4];
#pragma unroll
                for (int mt = 0; mt < 2; ++mt)
                    mma_tf32(O[mt][ntd], af[mt], b0, b1);
            }
        }
    }

    __syncthreads();
#pragma unroll
    for (int mt = 0; mt < 2; ++mt) {
        const int qb = warp * 32 + mt * 16;
        float rl0 = 1.f / lrow[mt][0];
        float rl1 = 1.f / lrow[mt][1];
#pragma unroll
        for (int ntd = 0; ntd < 4; ++ntd) {
            const int d0 = ntd * 8 + tq * 2;
            sQ[(d0) * SQ_LD + qb + g] = O[mt][ntd][0] * rl0;
            sQ[(d0 + 1) * SQ_LD + qb + g] = O[mt][ntd][1] * rl0;
            sQ[(d0) * SQ_LD + qb + 8 + g] = O[mt][ntd][2] * rl1;
            sQ[(d0 + 1) * SQ_LD + qb + 8 + g] = O[mt][ntd][3] * rl1;
        }
    }
    __syncthreads();
    // epilogue: out = O + GN(gridx)  (GN slot 1 fused)
    {
        float cnt = (float)(C * P);
        float mean = g_stats[1][2 * b] / cnt;
        float var = g_stats[1][2 * b + 1] / cnt - mean * mean;
        float inv = rsqrtf(var + EPS_GN);
        for (int i = tid; i < 32 * 32; i += 128) {
            int d = i >> 5, q4 = (i & 31) << 2;
            int cch = h * 32 + d;
            float al = inv * gnw[cch];
            float be = gnb[cch] - mean * al;
            float4 o = *(float4*)&sQ[d * SQ_LD + q4];
            float4 r = *(const float4*)&gridx[qbase + (size_t)d * P + q4];
            o.x += fmaf(r.x, al, be);
            o.y += fmaf(r.y, al, be);
            o.z += fmaf(r.z, al, be);
            o.w += fmaf(r.w, al, be);
            *(float4*)&out[qbase + (size_t)d * P + q4] = o;
        }
    }
}

// ---------------- host launcher ----------------
static float* sym_addr(const void* s) {
    void* p = nullptr;
    cudaGetSymbolAddress(&p, s);
    return (float*)p;
}

extern "C" void kernel_launch(void* const* d_in, const int* in_sizes, int n_in,
                              void* d_out, int out_size) {
    const float* x        = (const float*)d_in[0];
    const float* norm_w   = (const float*)d_in[1];
    const float* norm_b   = (const float*)d_in[2];
    const float* qkv_w    = (const float*)d_in[3];
    const float* qkv_b    = (const float*)d_in[4];
    const float* proj_w   = (const float*)d_in[5];
    const float* proj_b   = (const float*)d_in[6];
    const float* gridnw   = (const float*)d_in[7];
    const float* gridnb   = (const float*)d_in[8];
    const float* pm_ln_w  = (const float*)d_in[9];
    const float* pm_ln_b  = (const float*)d_in[10];
    const float* pm_red_w = (const float*)d_in[11];
    const float* ds_nw    = (const float*)d_in[12];
    const float* ds_nb    = (const float*)d_in[13];
    const float* q_w      = (const float*)d_in[14];
    const float* q_b      = (const float*)d_in[15];
    const float* kv_w     = (const float*)d_in[16];
    const float* kv_b     = (const float*)d_in[17];
    float* out = (float*)d_out;

    float* xn    = sym_addr(g_xn);
    float* qkv   = sym_addr(g_qkv);
    float* gridx = sym_addr(g_gridx);
    float* mbuf  = sym_addr(g_m);
    float* pm    = sym_addr(g_pm);
    float* qg    = sym_addr(g_qg);
    float* kvb   = sym_addr(g_kv);

    cudaFuncSetAttribute(win_attn_mma_kernel,
                         cudaFuncAttributeMaxDynamicSharedMemorySize, WIN_SMEM);
    cudaFuncSetAttribute(glob_attn_mma_kernel,
                         cudaFuncAttributeMaxDynamicSharedMemorySize, GLOB_SMEM);

    dim3 gnGrid(64, BATCH);

    zero_stats_kernel<<<1, 32>>>();

    // ---- stage 1: stats(x); qkv = conv1x1(GN(x)) (GN fused in GEMM) ----
    gn_stats_kernel<<<gnGrid, 256>>>(x, C * P, 0);
    gemm_tf32_kernel<<<dim3(P / 128, 768 / 128, BATCH), 256>>>(
        qkv_w, x, qkv_b, qkv, 768, P, C, norm_w, norm_b, 0, -1);

    // ---- stage 2: windowed attention + residual + fused stats(slot1) ----
    win_attn_mma_kernel<<<dim3(64, NH, BATCH), 128, WIN_SMEM>>>(qkv, x, gridx);

    // ---- stage 3: patch merge (GN fused) + LN; pm GEMM (+stats slot2) ----
    patch_merge_ln_kernel<<<dim3(8, 32, BATCH), 256>>>(
        gridx, gridnw, gridnb, pm_ln_w, pm_ln_b, mbuf);
    gemm_tf32_kernel<<<dim3(P2 / 128, C / 128, BATCH), 256>>>(
        pm_red_w, mbuf, nullptr, pm, C, P2, 4 * C, nullptr, nullptr, -1, 2);

    // ---- stage 4: q projection (GN slot1 fused on gridx); kv (GN slot2) ----
    gemm_tf32_kernel<<<dim3(P / 128, C / 128, BATCH), 256>>>(
        q_w, gridx, q_b, qg, C, P, C, gridnw, gridnb, 1, -1);
    gemm_tf32_kernel<<<dim3(P2 / 128, 512 / 128, BATCH), 256>>>(
        kv_w, pm, kv_b, kvb, 512, P2, C, ds_nw, ds_nb, 2, -1);

    // ---- stage 5: global attention + GN(gridx) residual ----
    glob_attn_mma_kernel<<<dim3(P / 128, NH, BATCH), 128, GLOB_SMEM>>>(
        qg, kvb, gridx, gridnw, gridnb, xn);

    // ---- stage 6: proj ----
    gemm_tf32_kernel<<<dim3(P / 128, C / 128, BATCH), 256>>>(
        proj_w, xn, proj_b, out, C, P, C, nullptr, nullptr, -1, -1);
}